// round 1
// baseline (speedup 1.0000x reference)
#include <cuda_runtime.h>
#include <cuda_bf16.h>

#define BB 2
#define NN 4096
#define DD 512
#define HH 8
#define DH 64
#define MM 1024
#define NK 5120          // NN + MM
#define LSEQ 5119        // NK - 1 (PEG stream length)

// ---------------- scratch (device globals; no allocation allowed) ----------
__device__ float g_xn [BB * NN * DD];   // layernorm output
__device__ float g_q  [BB * NN * DD];   // q (scaled later at load)
__device__ float g_k  [BB * NK * DD];   // k ++ mem (pre-PEG)
__device__ float g_v  [BB * NK * DD];   // v ++ mem (pre-PEG)
__device__ float g_kp [BB * NK * DD];   // k after PEG
__device__ float g_vp [BB * NK * DD];   // v after PEG
__device__ float g_att[BB * NN * DD];   // attention out, (b, n, h*64+d)

// ---------------- LayerNorm: one block per row of 512 ----------------------
__global__ void ln_kernel(const float* __restrict__ x,
                          const float* __restrict__ g,
                          const float* __restrict__ bt) {
    int row = blockIdx.x;                       // 0 .. BB*NN-1
    int t = threadIdx.x;                        // 128 threads, float4 each
    const float4* xr = (const float4*)(x + (size_t)row * DD);
    float4 v = xr[t];
    float s  = v.x + v.y + v.z + v.w;
    float s2 = v.x*v.x + v.y*v.y + v.z*v.z + v.w*v.w;
    #pragma unroll
    for (int o = 16; o > 0; o >>= 1) {
        s  += __shfl_xor_sync(0xffffffffu, s,  o);
        s2 += __shfl_xor_sync(0xffffffffu, s2, o);
    }
    __shared__ float a1[4], a2[4];
    int w = t >> 5;
    if ((t & 31) == 0) { a1[w] = s; a2[w] = s2; }
    __syncthreads();
    s  = a1[0] + a1[1] + a1[2] + a1[3];
    s2 = a2[0] + a2[1] + a2[2] + a2[3];
    float mu  = s * (1.0f / 512.0f);
    float var = s2 * (1.0f / 512.0f) - mu * mu;
    float rs  = rsqrtf(var + 1e-5f);
    float4 gg = ((const float4*)g)[t];
    float4 bb = ((const float4*)bt)[t];
    float4 o4;
    o4.x = (v.x - mu) * rs * gg.x + bb.x;
    o4.y = (v.y - mu) * rs * gg.y + bb.y;
    o4.z = (v.z - mu) * rs * gg.z + bb.z;
    o4.w = (v.w - mu) * rs * gg.w + bb.w;
    ((float4*)(g_xn + (size_t)row * DD))[t] = o4;
}

// ---------------- tiled SGEMM (A[8192x512] @ W[512xcn]) --------------------
// mode 0: A = g_xn, W = w_qkv (cn=1536), epilogue scatters into g_q/g_k/g_v
// mode 1: A = g_att, W = w_out (cn=512),  epilogue adds bias, writes dout
__global__ void sgemm_kernel(const float* __restrict__ Bw,
                             const float* __restrict__ bias,
                             float* __restrict__ dout,
                             int cn, int mode) {
    const float* A = mode ? g_att : g_xn;
    __shared__ float sA[16][68];   // transposed A tile (pad vs bank conflicts)
    __shared__ float sB[16][64];
    int tid  = threadIdx.x;                    // 256 threads
    int row0 = blockIdx.y * 64, col0 = blockIdx.x * 64;
    int arow = tid >> 2, akq = (tid & 3) << 2;
    int brow = tid >> 4, bcq = (tid & 15) << 2;
    int tx = tid & 15, ty = tid >> 4;
    float acc[4][4] = {};
    const float* Aptr = A  + (size_t)(row0 + arow) * 512 + akq;
    const float* Bptr = Bw + (size_t)brow * cn + col0 + bcq;
    for (int kt = 0; kt < 512; kt += 16) {
        float4 av = *(const float4*)(Aptr + kt);
        sA[akq + 0][arow] = av.x;
        sA[akq + 1][arow] = av.y;
        sA[akq + 2][arow] = av.z;
        sA[akq + 3][arow] = av.w;
        float4 bv = *(const float4*)(Bptr + (size_t)kt * cn);
        *(float4*)&sB[brow][bcq] = bv;
        __syncthreads();
        #pragma unroll
        for (int k = 0; k < 16; k++) {
            float4 a  = *(float4*)&sA[k][ty << 2];
            float4 bq = *(float4*)&sB[k][tx << 2];
            acc[0][0] += a.x*bq.x; acc[0][1] += a.x*bq.y; acc[0][2] += a.x*bq.z; acc[0][3] += a.x*bq.w;
            acc[1][0] += a.y*bq.x; acc[1][1] += a.y*bq.y; acc[1][2] += a.y*bq.z; acc[1][3] += a.y*bq.w;
            acc[2][0] += a.z*bq.x; acc[2][1] += a.z*bq.y; acc[2][2] += a.z*bq.z; acc[2][3] += a.z*bq.w;
            acc[3][0] += a.w*bq.x; acc[3][1] += a.w*bq.y; acc[3][2] += a.w*bq.z; acc[3][3] += a.w*bq.w;
        }
        __syncthreads();
    }
    int rbase = row0 + (ty << 2);
    int cbase = col0 + (tx << 2);
    if (mode == 0) {
        #pragma unroll
        for (int i = 0; i < 4; i++) {
            int rr = rbase + i;
            int b = rr >> 12, n = rr & 4095;
            #pragma unroll
            for (int j = 0; j < 4; j++) {
                int cc = cbase + j;
                int sel = cc >> 9, c5 = cc & 511;
                float vv = acc[i][j];
                if (sel == 0)      g_q[((size_t)b * NN + n) * 512 + c5] = vv;
                else if (sel == 1) g_k[((size_t)b * NK + n) * 512 + c5] = vv;
                else               g_v[((size_t)b * NK + n) * 512 + c5] = vv;
            }
        }
    } else {
        #pragma unroll
        for (int i = 0; i < 4; i++) {
            float4 bq = *(const float4*)(bias + cbase);
            float4 o4;
            o4.x = acc[i][0] + bq.x; o4.y = acc[i][1] + bq.y;
            o4.z = acc[i][2] + bq.z; o4.w = acc[i][3] + bq.w;
            *(float4*)(dout + (size_t)(rbase + i) * 512 + cbase) = o4;
        }
    }
}

// ---------------- append mem rows to k and v tails --------------------------
__global__ void copy_mem_kernel(const float* __restrict__ mem) {
    int i = blockIdx.x * blockDim.x + threadIdx.x;
    if (i >= BB * MM * 512 / 4) return;
    float4 v = ((const float4*)mem)[i];
    int gi = i << 2;
    int b = gi / (MM * 512);
    int rem = gi - b * (MM * 512);
    size_t off = ((size_t)b * NK + NN) * 512 + rem;
    *(float4*)(g_k + off) = v;
    *(float4*)(g_v + off) = v;
}

// ---------------- PEG1D depthwise conv (chunks of 32, + shifted pass) ------
// which = 0: g_k -> g_kp ; which = 1: g_v -> g_vp. Row 0 (cls) copied.
__global__ void peg_kernel(const float* __restrict__ w,
                           const float* __restrict__ bias, int which) {
    const float* src = which ? g_v : g_k;
    float*       dst = which ? g_vp : g_kp;
    int gr = blockIdx.x;               // 0 .. BB*NK-1
    int b = gr / NK, r = gr - b * NK;
    int c = threadIdx.x << 2;          // 128 threads * 4 channels
    const float* base = src + (size_t)b * NK * 512;
    float4 xc = *(const float4*)(base + (size_t)r * 512 + c);
    float* drow = dst + ((size_t)b * NK + r) * 512 + c;
    if (r == 0) { *(float4*)drow = xc; return; }
    int t = r - 1;                     // 0 .. LSEQ-1
    float w0[4], w1[4], w2[4];
    #pragma unroll
    for (int j = 0; j < 4; j++) {
        w0[j] = __ldg(w + (c + j) * 3 + 0);
        w1[j] = __ldg(w + (c + j) * 3 + 1);
        w2[j] = __ldg(w + (c + j) * 3 + 2);
    }
    float4 bb = *(const float4*)(bias + c);
    const float4 z4 = make_float4(0.f, 0.f, 0.f, 0.f);
    // pass 1 (unshifted)
    int p = t & 31;
    float4 L1 = (p > 0)                 ? *(const float4*)(base + (size_t)r * 512 - 512 + c) : z4;
    float4 R1 = (p < 31 && t + 1 < LSEQ)? *(const float4*)(base + (size_t)r * 512 + 512 + c) : z4;
    // pass 2 (roll +16, conv, roll -16)
    int u   = (t + 16) % LSEQ;
    int p2p = u % 32;
    int jl  = (u + LSEQ - 17) % LSEQ;
    int jr  = (u + LSEQ - 15) % LSEQ;
    float4 L2 = (p2p > 0)                  ? *(const float4*)(base + (size_t)(1 + jl) * 512 + c) : z4;
    float4 R2 = (p2p < 31 && u + 1 < LSEQ) ? *(const float4*)(base + (size_t)(1 + jr) * 512 + c) : z4;
    float4 o4;
    o4.x = xc.x + (w0[0]*L1.x + w1[0]*xc.x + w2[0]*R1.x + bb.x)
                + (w0[0]*L2.x + w1[0]*xc.x + w2[0]*R2.x + bb.x);
    o4.y = xc.y + (w0[1]*L1.y + w1[1]*xc.y + w2[1]*R1.y + bb.y)
                + (w0[1]*L2.y + w1[1]*xc.y + w2[1]*R2.y + bb.y);
    o4.z = xc.z + (w0[2]*L1.z + w1[2]*xc.z + w2[2]*R1.z + bb.z)
                + (w0[2]*L2.z + w1[2]*xc.z + w2[2]*R2.z + bb.z);
    o4.w = xc.w + (w0[3]*L1.w + w1[3]*xc.w + w2[3]*R1.w + bb.w)
                + (w0[3]*L2.w + w1[3]*xc.w + w2[3]*R2.w + bb.w);
    *(float4*)drow = o4;
}

// ---------------- flash attention, fp32 -------------------------------------
// grid (NN/64, BB*HH), 256 threads. 4 lanes per query (16 dims each),
// 32-key tiles with two-pass softmax (tile max, then exp + accumulate).
__global__ __launch_bounds__(256, 2)
void attn_kernel() {
    __shared__ float Ks[32][64];
    __shared__ float Vs[32][64];
    int bh = blockIdx.y;
    int b = bh >> 3, h = bh & 7;
    int tid = threadIdx.x;
    int qi  = blockIdx.x * 64 + (tid >> 2);
    int sub = tid & 3;
    const float scale = 0.125f;              // 64^-0.5
    float4 qv[4];
    {
        const float* qptr = g_q + ((size_t)b * NN + qi) * 512 + h * 64 + sub * 16;
        #pragma unroll
        for (int i = 0; i < 4; i++) {
            float4 tq = *(const float4*)(qptr + 4 * i);
            qv[i].x = tq.x * scale; qv[i].y = tq.y * scale;
            qv[i].z = tq.z * scale; qv[i].w = tq.w * scale;
        }
    }
    float o[16];
    #pragma unroll
    for (int i = 0; i < 16; i++) o[i] = 0.f;
    float m = -1e30f, l = 0.f;
    int lrow = tid >> 3;
    int lcol = (tid & 7) << 3;
    const float* kb = g_kp + (size_t)b * NK * 512 + h * 64;
    const float* vb = g_vp + (size_t)b * NK * 512 + h * 64;
    for (int kt = 0; kt < NK; kt += 32) {
        {
            const float* kr = kb + (size_t)(kt + lrow) * 512 + lcol;
            const float* vr = vb + (size_t)(kt + lrow) * 512 + lcol;
            *(float4*)&Ks[lrow][lcol]     = *(const float4*)(kr);
            *(float4*)&Ks[lrow][lcol + 4] = *(const float4*)(kr + 4);
            *(float4*)&Vs[lrow][lcol]     = *(const float4*)(vr);
            *(float4*)&Vs[lrow][lcol + 4] = *(const float4*)(vr + 4);
        }
        __syncthreads();
        float s[32];
        float tmax = -1e30f;
        #pragma unroll
        for (int kk = 0; kk < 32; kk++) {
            const float* kp = &Ks[kk][sub << 4];
            float4 k0 = *(const float4*)(kp);
            float4 k1 = *(const float4*)(kp + 4);
            float4 k2 = *(const float4*)(kp + 8);
            float4 k3 = *(const float4*)(kp + 12);
            float d = qv[0].x*k0.x + qv[0].y*k0.y + qv[0].z*k0.z + qv[0].w*k0.w
                    + qv[1].x*k1.x + qv[1].y*k1.y + qv[1].z*k1.z + qv[1].w*k1.w
                    + qv[2].x*k2.x + qv[2].y*k2.y + qv[2].z*k2.z + qv[2].w*k2.w
                    + qv[3].x*k3.x + qv[3].y*k3.y + qv[3].z*k3.z + qv[3].w*k3.w;
            d += __shfl_xor_sync(0xffffffffu, d, 1);
            d += __shfl_xor_sync(0xffffffffu, d, 2);
            s[kk] = d;
            tmax = fmaxf(tmax, d);
        }
        float mnew = fmaxf(m, tmax);
        float corr = __expf(m - mnew);
        l *= corr;
        #pragma unroll
        for (int i = 0; i < 16; i++) o[i] *= corr;
        #pragma unroll
        for (int kk = 0; kk < 32; kk++) {
            float pexp = __expf(s[kk] - mnew);
            l += pexp;
            const float* vp = &Vs[kk][sub << 4];
            float4 v0 = *(const float4*)(vp);
            float4 v1 = *(const float4*)(vp + 4);
            float4 v2 = *(const float4*)(vp + 8);
            float4 v3 = *(const float4*)(vp + 12);
            o[0]  += pexp * v0.x; o[1]  += pexp * v0.y; o[2]  += pexp * v0.z; o[3]  += pexp * v0.w;
            o[4]  += pexp * v1.x; o[5]  += pexp * v1.y; o[6]  += pexp * v1.z; o[7]  += pexp * v1.w;
            o[8]  += pexp * v2.x; o[9]  += pexp * v2.y; o[10] += pexp * v2.z; o[11] += pexp * v2.w;
            o[12] += pexp * v3.x; o[13] += pexp * v3.y; o[14] += pexp * v3.z; o[15] += pexp * v3.w;
        }
        m = mnew;
        __syncthreads();
    }
    float inv = 1.0f / l;
    float* op = g_att + ((size_t)b * NN + qi) * 512 + h * 64 + sub * 16;
    #pragma unroll
    for (int i = 0; i < 4; i++) {
        float4 o4;
        o4.x = o[4*i+0] * inv; o4.y = o[4*i+1] * inv;
        o4.z = o[4*i+2] * inv; o4.w = o[4*i+3] * inv;
        *(float4*)(op + 4 * i) = o4;
    }
}

// ---------------- launch ----------------------------------------------------
extern "C" void kernel_launch(void* const* d_in, const int* in_sizes, int n_in,
                              void* d_out, int out_size) {
    const float* x     = (const float*)d_in[0];
    const float* mem   = (const float*)d_in[1];
    const float* ln_g  = (const float*)d_in[2];
    const float* ln_b  = (const float*)d_in[3];
    const float* w_qkv = (const float*)d_in[4];
    const float* w_out = (const float*)d_in[5];
    const float* b_out = (const float*)d_in[6];
    const float* pk_w  = (const float*)d_in[7];
    const float* pk_b  = (const float*)d_in[8];
    const float* pv_w  = (const float*)d_in[9];
    const float* pv_b  = (const float*)d_in[10];
    float* out = (float*)d_out;

    ln_kernel<<<BB * NN, 128>>>(x, ln_g, ln_b);
    sgemm_kernel<<<dim3(1536 / 64, (BB * NN) / 64), 256>>>(w_qkv, nullptr, nullptr, 1536, 0);
    copy_mem_kernel<<<(BB * MM * 512 / 4 + 255) / 256, 256>>>(mem);
    peg_kernel<<<BB * NK, 128>>>(pk_w, pk_b, 0);
    peg_kernel<<<BB * NK, 128>>>(pv_w, pv_b, 1);
    attn_kernel<<<dim3(NN / 64, BB * HH), 256>>>();
    sgemm_kernel<<<dim3(512 / 64, (BB * NN) / 64), 256>>>(w_out, b_out, out, 512, 1);
}

// round 2
// speedup vs baseline: 1.0088x; 1.0088x over previous
#include <cuda_runtime.h>
#include <cuda_bf16.h>

#define BB 2
#define NN 4096
#define DD 512
#define HH 8
#define DH 64
#define MM 1024
#define NK 5120          // NN + MM
#define LSEQ 5119        // NK - 1 (PEG stream length)

typedef unsigned long long ull;

// ---------------- f32x2 packed helpers (FFMA2 path) -------------------------
__device__ __forceinline__ ull pk2(float x, float y) {
    ull r; asm("mov.b64 %0, {%1, %2};" : "=l"(r) : "f"(x), "f"(y)); return r;
}
__device__ __forceinline__ void upk2(float &x, float &y, ull v) {
    asm("mov.b64 {%0, %1}, %2;" : "=f"(x), "=f"(y) : "l"(v));
}
__device__ __forceinline__ void fma2(ull &d, ull a, ull b) {
    asm("fma.rn.f32x2 %0, %1, %2, %0;" : "+l"(d) : "l"(a), "l"(b));
}
__device__ __forceinline__ void mul2(ull &d, ull a) {
    asm("mul.rn.f32x2 %0, %0, %1;" : "+l"(d) : "l"(a));
}
__device__ __forceinline__ ull add2(ull a, ull b) {
    ull r; asm("add.rn.f32x2 %0, %1, %2;" : "=l"(r) : "l"(a), "l"(b)); return r;
}

// ---------------- scratch (device globals; no allocation allowed) ----------
__device__ float g_xn [BB * NN * DD];   // layernorm output
__device__ float g_q  [BB * NN * DD];   // q
__device__ float g_k  [BB * NK * DD];   // k ++ mem (pre-PEG)
__device__ float g_v  [BB * NK * DD];   // v ++ mem (pre-PEG)
__device__ float g_kp [BB * NK * DD];   // k after PEG
__device__ float g_vp [BB * NK * DD];   // v after PEG
__device__ float g_att[BB * NN * DD];   // attention out, (b, n, h*64+d)

// ---------------- LayerNorm: one block per row of 512 ----------------------
__global__ void ln_kernel(const float* __restrict__ x,
                          const float* __restrict__ g,
                          const float* __restrict__ bt) {
    int row = blockIdx.x;
    int t = threadIdx.x;                        // 128 threads, float4 each
    const float4* xr = (const float4*)(x + (size_t)row * DD);
    float4 v = xr[t];
    float s  = v.x + v.y + v.z + v.w;
    float s2 = v.x*v.x + v.y*v.y + v.z*v.z + v.w*v.w;
    #pragma unroll
    for (int o = 16; o > 0; o >>= 1) {
        s  += __shfl_xor_sync(0xffffffffu, s,  o);
        s2 += __shfl_xor_sync(0xffffffffu, s2, o);
    }
    __shared__ float a1[4], a2[4];
    int w = t >> 5;
    if ((t & 31) == 0) { a1[w] = s; a2[w] = s2; }
    __syncthreads();
    s  = a1[0] + a1[1] + a1[2] + a1[3];
    s2 = a2[0] + a2[1] + a2[2] + a2[3];
    float mu  = s * (1.0f / 512.0f);
    float var = s2 * (1.0f / 512.0f) - mu * mu;
    float rs  = rsqrtf(var + 1e-5f);
    float4 gg = ((const float4*)g)[t];
    float4 bb = ((const float4*)bt)[t];
    float4 o4;
    o4.x = (v.x - mu) * rs * gg.x + bb.x;
    o4.y = (v.y - mu) * rs * gg.y + bb.y;
    o4.z = (v.z - mu) * rs * gg.z + bb.z;
    o4.w = (v.w - mu) * rs * gg.w + bb.w;
    ((float4*)(g_xn + (size_t)row * DD))[t] = o4;
}

// ---------------- tiled SGEMM (A[8192x512] @ W[512xcn]), f32x2 --------------
// 128x64 block tile, 256 threads, 8x4 microtile (rows packed as f32x2 pairs).
// mode 0: A = g_xn, W = w_qkv (cn=1536), epilogue scatters into g_q/g_k/g_v
// mode 1: A = g_att, W = w_out (cn=512),  epilogue adds bias, writes dout
__global__ __launch_bounds__(256)
void sgemm_kernel(const float* __restrict__ Bw,
                  const float* __restrict__ bias,
                  float* __restrict__ dout,
                  int cn, int mode) {
    const float* A = mode ? g_att : g_xn;
    __shared__ __align__(16) float sA[16][132];   // transposed A tile, padded
    __shared__ __align__(16) float sB[16][64];
    int tid  = threadIdx.x;                    // 256 threads
    int row0 = blockIdx.y * 128, col0 = blockIdx.x * 64;
    int arow = tid >> 2, akq = (tid & 3) << 2;
    int brow = tid >> 4, bcq = (tid & 15) << 2;
    int tx = tid & 15;
    int rowb = (tid >> 4) << 3;                // 0..120, 8 rows per thread
    ull acc[4][4];
    #pragma unroll
    for (int p = 0; p < 4; p++)
        #pragma unroll
        for (int j = 0; j < 4; j++) acc[p][j] = 0ULL;
    const float* Aptr0 = A  + (size_t)(row0 + arow) * 512 + akq;
    const float* Aptr1 = A  + (size_t)(row0 + arow + 64) * 512 + akq;
    const float* Bptr  = Bw + (size_t)brow * cn + col0 + bcq;
    for (int kt = 0; kt < 512; kt += 16) {
        float4 av0 = *(const float4*)(Aptr0 + kt);
        float4 av1 = *(const float4*)(Aptr1 + kt);
        sA[akq + 0][arow] = av0.x;
        sA[akq + 1][arow] = av0.y;
        sA[akq + 2][arow] = av0.z;
        sA[akq + 3][arow] = av0.w;
        sA[akq + 0][arow + 64] = av1.x;
        sA[akq + 1][arow + 64] = av1.y;
        sA[akq + 2][arow + 64] = av1.z;
        sA[akq + 3][arow + 64] = av1.w;
        float4 bv = *(const float4*)(Bptr + (size_t)kt * cn);
        *(float4*)&sB[brow][bcq] = bv;
        __syncthreads();
        #pragma unroll
        for (int k = 0; k < 16; k++) {
            const ulonglong2* ap = (const ulonglong2*)&sA[k][rowb];
            ulonglong2 a01 = ap[0];
            ulonglong2 a23 = ap[1];
            float4 bq = *(float4*)&sB[k][tx << 2];
            ull b0 = pk2(bq.x, bq.x), b1 = pk2(bq.y, bq.y);
            ull b2 = pk2(bq.z, bq.z), b3 = pk2(bq.w, bq.w);
            fma2(acc[0][0], a01.x, b0); fma2(acc[0][1], a01.x, b1);
            fma2(acc[0][2], a01.x, b2); fma2(acc[0][3], a01.x, b3);
            fma2(acc[1][0], a01.y, b0); fma2(acc[1][1], a01.y, b1);
            fma2(acc[1][2], a01.y, b2); fma2(acc[1][3], a01.y, b3);
            fma2(acc[2][0], a23.x, b0); fma2(acc[2][1], a23.x, b1);
            fma2(acc[2][2], a23.x, b2); fma2(acc[2][3], a23.x, b3);
            fma2(acc[3][0], a23.y, b0); fma2(acc[3][1], a23.y, b1);
            fma2(acc[3][2], a23.y, b2); fma2(acc[3][3], a23.y, b3);
        }
        __syncthreads();
    }
    // unpack accumulators: r[8 rows][4 cols]
    float r[8][4];
    #pragma unroll
    for (int p = 0; p < 4; p++)
        #pragma unroll
        for (int j = 0; j < 4; j++)
            upk2(r[2 * p][j], r[2 * p + 1][j], acc[p][j]);
    int rbase = row0 + rowb;
    int cbase = col0 + (tx << 2);
    if (mode == 0) {
        #pragma unroll
        for (int i = 0; i < 8; i++) {
            int rr = rbase + i;
            int b = rr >> 12, n = rr & 4095;
            #pragma unroll
            for (int j = 0; j < 4; j++) {
                int cc = cbase + j;
                int sel = cc >> 9, c5 = cc & 511;
                float vv = r[i][j];
                if (sel == 0)      g_q[((size_t)b * NN + n) * 512 + c5] = vv;
                else if (sel == 1) g_k[((size_t)b * NK + n) * 512 + c5] = vv;
                else               g_v[((size_t)b * NK + n) * 512 + c5] = vv;
            }
        }
    } else {
        float4 bq = *(const float4*)(bias + cbase);
        #pragma unroll
        for (int i = 0; i < 8; i++) {
            float4 o4;
            o4.x = r[i][0] + bq.x; o4.y = r[i][1] + bq.y;
            o4.z = r[i][2] + bq.z; o4.w = r[i][3] + bq.w;
            *(float4*)(dout + (size_t)(rbase + i) * 512 + cbase) = o4;
        }
    }
}

// ---------------- append mem rows to k and v tails --------------------------
__global__ void copy_mem_kernel(const float* __restrict__ mem) {
    int i = blockIdx.x * blockDim.x + threadIdx.x;
    if (i >= BB * MM * 512 / 4) return;
    float4 v = ((const float4*)mem)[i];
    int gi = i << 2;
    int b = gi / (MM * 512);
    int rem = gi - b * (MM * 512);
    size_t off = ((size_t)b * NK + NN) * 512 + rem;
    *(float4*)(g_k + off) = v;
    *(float4*)(g_v + off) = v;
}

// ---------------- PEG1D depthwise conv (chunks of 32, + shifted pass) ------
__global__ void peg_kernel(const float* __restrict__ w,
                           const float* __restrict__ bias, int which) {
    const float* src = which ? g_v : g_k;
    float*       dst = which ? g_vp : g_kp;
    int gr = blockIdx.x;               // 0 .. BB*NK-1
    int b = gr / NK, r = gr - b * NK;
    int c = threadIdx.x << 2;          // 128 threads * 4 channels
    const float* base = src + (size_t)b * NK * 512;
    float4 xc = *(const float4*)(base + (size_t)r * 512 + c);
    float* drow = dst + ((size_t)b * NK + r) * 512 + c;
    if (r == 0) { *(float4*)drow = xc; return; }
    int t = r - 1;                     // 0 .. LSEQ-1
    float w0[4], w1[4], w2[4];
    #pragma unroll
    for (int j = 0; j < 4; j++) {
        w0[j] = __ldg(w + (c + j) * 3 + 0);
        w1[j] = __ldg(w + (c + j) * 3 + 1);
        w2[j] = __ldg(w + (c + j) * 3 + 2);
    }
    float4 bb = *(const float4*)(bias + c);
    const float4 z4 = make_float4(0.f, 0.f, 0.f, 0.f);
    int p = t & 31;
    float4 L1 = (p > 0)                 ? *(const float4*)(base + (size_t)r * 512 - 512 + c) : z4;
    float4 R1 = (p < 31 && t + 1 < LSEQ)? *(const float4*)(base + (size_t)r * 512 + 512 + c) : z4;
    int u   = (t + 16) % LSEQ;
    int p2p = u % 32;
    int jl  = (u + LSEQ - 17) % LSEQ;
    int jr  = (u + LSEQ - 15) % LSEQ;
    float4 L2 = (p2p > 0)                  ? *(const float4*)(base + (size_t)(1 + jl) * 512 + c) : z4;
    float4 R2 = (p2p < 31 && u + 1 < LSEQ) ? *(const float4*)(base + (size_t)(1 + jr) * 512 + c) : z4;
    float4 o4;
    o4.x = xc.x + (w0[0]*L1.x + w1[0]*xc.x + w2[0]*R1.x + bb.x)
                + (w0[0]*L2.x + w1[0]*xc.x + w2[0]*R2.x + bb.x);
    o4.y = xc.y + (w0[1]*L1.y + w1[1]*xc.y + w2[1]*R1.y + bb.y)
                + (w0[1]*L2.y + w1[1]*xc.y + w2[1]*R2.y + bb.y);
    o4.z = xc.z + (w0[2]*L1.z + w1[2]*xc.z + w2[2]*R1.z + bb.z)
                + (w0[2]*L2.z + w1[2]*xc.z + w2[2]*R2.z + bb.z);
    o4.w = xc.w + (w0[3]*L1.w + w1[3]*xc.w + w2[3]*R1.w + bb.w)
                + (w0[3]*L2.w + w1[3]*xc.w + w2[3]*R2.w + bb.w);
    *(float4*)drow = o4;
}

// ---------------- flash attention, fp32 via f32x2 ---------------------------
// grid (NN/64, BB*HH), 256 threads. 4 lanes per query (16 dims each),
// 32-key tiles with two-pass softmax.
__global__ __launch_bounds__(256, 2)
void attn_kernel() {
    __shared__ __align__(16) float Ks[32][64];
    __shared__ __align__(16) float Vs[32][64];
    int bh = blockIdx.y;
    int b = bh >> 3, h = bh & 7;
    int tid = threadIdx.x;
    int qi  = blockIdx.x * 64 + (tid >> 2);
    int sub = tid & 3;
    const float scale = 0.125f;              // 64^-0.5
    ull qp[8];
    {
        const float4* qptr = (const float4*)(g_q + ((size_t)b * NN + qi) * 512 + h * 64 + sub * 16);
        #pragma unroll
        for (int i = 0; i < 4; i++) {
            float4 tq = qptr[i];
            qp[2 * i]     = pk2(tq.x * scale, tq.y * scale);
            qp[2 * i + 1] = pk2(tq.z * scale, tq.w * scale);
        }
    }
    ull o8[8];
    #pragma unroll
    for (int i = 0; i < 8; i++) o8[i] = 0ULL;
    float m = -1e30f, l = 0.f;
    int lrow = tid >> 3;
    int lcol = (tid & 7) << 3;
    const float* kb = g_kp + (size_t)b * NK * 512 + h * 64;
    const float* vb = g_vp + (size_t)b * NK * 512 + h * 64;
    for (int kt = 0; kt < NK; kt += 32) {
        {
            const float* kr = kb + (size_t)(kt + lrow) * 512 + lcol;
            const float* vr = vb + (size_t)(kt + lrow) * 512 + lcol;
            *(float4*)&Ks[lrow][lcol]     = *(const float4*)(kr);
            *(float4*)&Ks[lrow][lcol + 4] = *(const float4*)(kr + 4);
            *(float4*)&Vs[lrow][lcol]     = *(const float4*)(vr);
            *(float4*)&Vs[lrow][lcol + 4] = *(const float4*)(vr + 4);
        }
        __syncthreads();
        float s[32];
        float tmax = -1e30f;
        #pragma unroll
        for (int kk = 0; kk < 32; kk++) {
            const ulonglong2* kp = (const ulonglong2*)&Ks[kk][sub << 4];
            ulonglong2 k01 = kp[0];
            ulonglong2 k23 = kp[1];
            ulonglong2 k45 = kp[2];
            ulonglong2 k67 = kp[3];
            ull acc0 = 0ULL, acc1 = 0ULL;
            fma2(acc0, qp[0], k01.x); fma2(acc1, qp[1], k01.y);
            fma2(acc0, qp[2], k23.x); fma2(acc1, qp[3], k23.y);
            fma2(acc0, qp[4], k45.x); fma2(acc1, qp[5], k45.y);
            fma2(acc0, qp[6], k67.x); fma2(acc1, qp[7], k67.y);
            ull accs = add2(acc0, acc1);
            float lo, hi; upk2(lo, hi, accs);
            float d = lo + hi;
            d += __shfl_xor_sync(0xffffffffu, d, 1);
            d += __shfl_xor_sync(0xffffffffu, d, 2);
            s[kk] = d;
            tmax = fmaxf(tmax, d);
        }
        float mnew = fmaxf(m, tmax);
        float corr = __expf(m - mnew);
        l *= corr;
        ull pc = pk2(corr, corr);
        #pragma unroll
        for (int i = 0; i < 8; i++) mul2(o8[i], pc);
        #pragma unroll
        for (int kk = 0; kk < 32; kk++) {
            float pexp = __expf(s[kk] - mnew);
            l += pexp;
            ull pp = pk2(pexp, pexp);
            const ulonglong2* vp = (const ulonglong2*)&Vs[kk][sub << 4];
            ulonglong2 v01 = vp[0];
            ulonglong2 v23 = vp[1];
            ulonglong2 v45 = vp[2];
            ulonglong2 v67 = vp[3];
            fma2(o8[0], pp, v01.x); fma2(o8[1], pp, v01.y);
            fma2(o8[2], pp, v23.x); fma2(o8[3], pp, v23.y);
            fma2(o8[4], pp, v45.x); fma2(o8[5], pp, v45.y);
            fma2(o8[6], pp, v67.x); fma2(o8[7], pp, v67.y);
        }
        m = mnew;
        __syncthreads();
    }
    float inv = 1.0f / l;
    ull pi = pk2(inv, inv);
    #pragma unroll
    for (int i = 0; i < 8; i++) mul2(o8[i], pi);
    ulonglong2* op = (ulonglong2*)(g_att + ((size_t)b * NN + qi) * 512 + h * 64 + sub * 16);
    ulonglong2 s0; s0.x = o8[0]; s0.y = o8[1]; op[0] = s0;
    ulonglong2 s1; s1.x = o8[2]; s1.y = o8[3]; op[1] = s1;
    ulonglong2 s2; s2.x = o8[4]; s2.y = o8[5]; op[2] = s2;
    ulonglong2 s3; s3.x = o8[6]; s3.y = o8[7]; op[3] = s3;
}

// ---------------- launch ----------------------------------------------------
extern "C" void kernel_launch(void* const* d_in, const int* in_sizes, int n_in,
                              void* d_out, int out_size) {
    const float* x     = (const float*)d_in[0];
    const float* mem   = (const float*)d_in[1];
    const float* ln_g  = (const float*)d_in[2];
    const float* ln_b  = (const float*)d_in[3];
    const float* w_qkv = (const float*)d_in[4];
    const float* w_out = (const float*)d_in[5];
    const float* b_out = (const float*)d_in[6];
    const float* pk_w  = (const float*)d_in[7];
    const float* pk_b  = (const float*)d_in[8];
    const float* pv_w  = (const float*)d_in[9];
    const float* pv_b  = (const float*)d_in[10];
    float* out = (float*)d_out;

    ln_kernel<<<BB * NN, 128>>>(x, ln_g, ln_b);
    sgemm_kernel<<<dim3(1536 / 64, (BB * NN) / 128), 256>>>(w_qkv, nullptr, nullptr, 1536, 0);
    copy_mem_kernel<<<(BB * MM * 512 / 4 + 255) / 256, 256>>>(mem);
    peg_kernel<<<BB * NK, 128>>>(pk_w, pk_b, 0);
    peg_kernel<<<BB * NK, 128>>>(pv_w, pv_b, 1);
    attn_kernel<<<dim3(NN / 64, BB * HH), 256>>>();
    sgemm_kernel<<<dim3(512 / 64, (BB * NN) / 128), 256>>>(w_out, b_out, out, 512, 1);
}

// round 3
// speedup vs baseline: 5.6910x; 5.6415x over previous
#include <cuda_runtime.h>
#include <cuda_bf16.h>
#include <cstring>

#define BB 2
#define NN 4096
#define DD 512
#define HH 8
#define DH 64
#define MM 1024
#define NK 5120          // NN + MM
#define LSEQ 5119        // NK - 1 (PEG stream length)

typedef unsigned long long ull;

// ---------------- f32x2 packed helpers (for the scalar GEMM) ----------------
__device__ __forceinline__ ull pk2(float x, float y) {
    ull r; asm("mov.b64 %0, {%1, %2};" : "=l"(r) : "f"(x), "f"(y)); return r;
}
__device__ __forceinline__ void upk2(float &x, float &y, ull v) {
    asm("mov.b64 {%0, %1}, %2;" : "=f"(x), "=f"(y) : "l"(v));
}
__device__ __forceinline__ void fma2(ull &d, ull a, ull b) {
    asm("fma.rn.f32x2 %0, %1, %2, %0;" : "+l"(d) : "l"(a), "l"(b));
}

// ---------------- bf16 split + mma helpers ----------------------------------
__device__ __forceinline__ unsigned b2u(__nv_bfloat162 v) {
    unsigned u; memcpy(&u, &v, 4); return u;
}
__device__ __forceinline__ void splitpk(float x, float y, unsigned &hi, unsigned &lo) {
    __nv_bfloat162 h = __floats2bfloat162_rn(x, y);
    float hx = __bfloat162float(h.x), hy = __bfloat162float(h.y);
    __nv_bfloat162 l = __floats2bfloat162_rn(x - hx, y - hy);
    hi = b2u(h); lo = b2u(l);
}
__device__ __forceinline__ void mma16816(float c[4], const unsigned a[4],
                                         unsigned b0, unsigned b1) {
    asm("mma.sync.aligned.m16n8k16.row.col.f32.bf16.bf16.f32 "
        "{%0,%1,%2,%3},{%4,%5,%6,%7},{%8,%9},{%0,%1,%2,%3};"
        : "+f"(c[0]), "+f"(c[1]), "+f"(c[2]), "+f"(c[3])
        : "r"(a[0]), "r"(a[1]), "r"(a[2]), "r"(a[3]), "r"(b0), "r"(b1));
}

// ---------------- scratch (device globals; no allocation allowed) ----------
__device__ float g_xn [BB * NN * DD];
__device__ float g_q  [BB * NN * DD];
__device__ float g_k  [BB * NK * DD];
__device__ float g_v  [BB * NK * DD];
__device__ float g_kp [BB * NK * DD];
__device__ float g_vp [BB * NK * DD];
__device__ float g_att[BB * NN * DD];

// ---------------- LayerNorm --------------------------------------------------
__global__ void ln_kernel(const float* __restrict__ x,
                          const float* __restrict__ g,
                          const float* __restrict__ bt) {
    int row = blockIdx.x;
    int t = threadIdx.x;
    const float4* xr = (const float4*)(x + (size_t)row * DD);
    float4 v = xr[t];
    float s  = v.x + v.y + v.z + v.w;
    float s2 = v.x*v.x + v.y*v.y + v.z*v.z + v.w*v.w;
    #pragma unroll
    for (int o = 16; o > 0; o >>= 1) {
        s  += __shfl_xor_sync(0xffffffffu, s,  o);
        s2 += __shfl_xor_sync(0xffffffffu, s2, o);
    }
    __shared__ float a1[4], a2[4];
    int w = t >> 5;
    if ((t & 31) == 0) { a1[w] = s; a2[w] = s2; }
    __syncthreads();
    s  = a1[0] + a1[1] + a1[2] + a1[3];
    s2 = a2[0] + a2[1] + a2[2] + a2[3];
    float mu  = s * (1.0f / 512.0f);
    float var = s2 * (1.0f / 512.0f) - mu * mu;
    float rs  = rsqrtf(var + 1e-5f);
    float4 gg = ((const float4*)g)[t];
    float4 bb = ((const float4*)bt)[t];
    float4 o4;
    o4.x = (v.x - mu) * rs * gg.x + bb.x;
    o4.y = (v.y - mu) * rs * gg.y + bb.y;
    o4.z = (v.z - mu) * rs * gg.z + bb.z;
    o4.w = (v.w - mu) * rs * gg.w + bb.w;
    ((float4*)(g_xn + (size_t)row * DD))[t] = o4;
}

// ---------------- tiled SGEMM (f32x2), unchanged from R1 --------------------
__global__ __launch_bounds__(256)
void sgemm_kernel(const float* __restrict__ Bw,
                  const float* __restrict__ bias,
                  float* __restrict__ dout,
                  int cn, int mode) {
    const float* A = mode ? g_att : g_xn;
    __shared__ __align__(16) float sA[16][132];
    __shared__ __align__(16) float sB[16][64];
    int tid  = threadIdx.x;
    int row0 = blockIdx.y * 128, col0 = blockIdx.x * 64;
    int arow = tid >> 2, akq = (tid & 3) << 2;
    int brow = tid >> 4, bcq = (tid & 15) << 2;
    int tx = tid & 15;
    int rowb = (tid >> 4) << 3;
    ull acc[4][4];
    #pragma unroll
    for (int p = 0; p < 4; p++)
        #pragma unroll
        for (int j = 0; j < 4; j++) acc[p][j] = 0ULL;
    const float* Aptr0 = A  + (size_t)(row0 + arow) * 512 + akq;
    const float* Aptr1 = A  + (size_t)(row0 + arow + 64) * 512 + akq;
    const float* Bptr  = Bw + (size_t)brow * cn + col0 + bcq;
    for (int kt = 0; kt < 512; kt += 16) {
        float4 av0 = *(const float4*)(Aptr0 + kt);
        float4 av1 = *(const float4*)(Aptr1 + kt);
        sA[akq + 0][arow] = av0.x;
        sA[akq + 1][arow] = av0.y;
        sA[akq + 2][arow] = av0.z;
        sA[akq + 3][arow] = av0.w;
        sA[akq + 0][arow + 64] = av1.x;
        sA[akq + 1][arow + 64] = av1.y;
        sA[akq + 2][arow + 64] = av1.z;
        sA[akq + 3][arow + 64] = av1.w;
        float4 bv = *(const float4*)(Bptr + (size_t)kt * cn);
        *(float4*)&sB[brow][bcq] = bv;
        __syncthreads();
        #pragma unroll
        for (int k = 0; k < 16; k++) {
            const ulonglong2* ap = (const ulonglong2*)&sA[k][rowb];
            ulonglong2 a01 = ap[0];
            ulonglong2 a23 = ap[1];
            float4 bq = *(float4*)&sB[k][tx << 2];
            ull b0 = pk2(bq.x, bq.x), b1 = pk2(bq.y, bq.y);
            ull b2 = pk2(bq.z, bq.z), b3 = pk2(bq.w, bq.w);
            fma2(acc[0][0], a01.x, b0); fma2(acc[0][1], a01.x, b1);
            fma2(acc[0][2], a01.x, b2); fma2(acc[0][3], a01.x, b3);
            fma2(acc[1][0], a01.y, b0); fma2(acc[1][1], a01.y, b1);
            fma2(acc[1][2], a01.y, b2); fma2(acc[1][3], a01.y, b3);
            fma2(acc[2][0], a23.x, b0); fma2(acc[2][1], a23.x, b1);
            fma2(acc[2][2], a23.x, b2); fma2(acc[2][3], a23.x, b3);
            fma2(acc[3][0], a23.y, b0); fma2(acc[3][1], a23.y, b1);
            fma2(acc[3][2], a23.y, b2); fma2(acc[3][3], a23.y, b3);
        }
        __syncthreads();
    }
    float r[8][4];
    #pragma unroll
    for (int p = 0; p < 4; p++)
        #pragma unroll
        for (int j = 0; j < 4; j++)
            upk2(r[2 * p][j], r[2 * p + 1][j], acc[p][j]);
    int rbase = row0 + rowb;
    int cbase = col0 + (tx << 2);
    if (mode == 0) {
        #pragma unroll
        for (int i = 0; i < 8; i++) {
            int rr = rbase + i;
            int b = rr >> 12, n = rr & 4095;
            #pragma unroll
            for (int j = 0; j < 4; j++) {
                int cc = cbase + j;
                int sel = cc >> 9, c5 = cc & 511;
                float vv = r[i][j];
                if (sel == 0)      g_q[((size_t)b * NN + n) * 512 + c5] = vv;
                else if (sel == 1) g_k[((size_t)b * NK + n) * 512 + c5] = vv;
                else               g_v[((size_t)b * NK + n) * 512 + c5] = vv;
            }
        }
    } else {
        float4 bq = *(const float4*)(bias + cbase);
        #pragma unroll
        for (int i = 0; i < 8; i++) {
            float4 o4;
            o4.x = r[i][0] + bq.x; o4.y = r[i][1] + bq.y;
            o4.z = r[i][2] + bq.z; o4.w = r[i][3] + bq.w;
            *(float4*)(dout + (size_t)(rbase + i) * 512 + cbase) = o4;
        }
    }
}

// ---------------- append mem rows to k and v tails --------------------------
__global__ void copy_mem_kernel(const float* __restrict__ mem) {
    int i = blockIdx.x * blockDim.x + threadIdx.x;
    if (i >= BB * MM * 512 / 4) return;
    float4 v = ((const float4*)mem)[i];
    int gi = i << 2;
    int b = gi / (MM * 512);
    int rem = gi - b * (MM * 512);
    size_t off = ((size_t)b * NK + NN) * 512 + rem;
    *(float4*)(g_k + off) = v;
    *(float4*)(g_v + off) = v;
}

// ---------------- PEG1D depthwise conv --------------------------------------
__global__ void peg_kernel(const float* __restrict__ w,
                           const float* __restrict__ bias, int which) {
    const float* src = which ? g_v : g_k;
    float*       dst = which ? g_vp : g_kp;
    int gr = blockIdx.x;
    int b = gr / NK, r = gr - b * NK;
    int c = threadIdx.x << 2;
    const float* base = src + (size_t)b * NK * 512;
    float4 xc = *(const float4*)(base + (size_t)r * 512 + c);
    float* drow = dst + ((size_t)b * NK + r) * 512 + c;
    if (r == 0) { *(float4*)drow = xc; return; }
    int t = r - 1;
    float w0[4], w1[4], w2[4];
    #pragma unroll
    for (int j = 0; j < 4; j++) {
        w0[j] = __ldg(w + (c + j) * 3 + 0);
        w1[j] = __ldg(w + (c + j) * 3 + 1);
        w2[j] = __ldg(w + (c + j) * 3 + 2);
    }
    float4 bb = *(const float4*)(bias + c);
    const float4 z4 = make_float4(0.f, 0.f, 0.f, 0.f);
    int p = t & 31;
    float4 L1 = (p > 0)                 ? *(const float4*)(base + (size_t)r * 512 - 512 + c) : z4;
    float4 R1 = (p < 31 && t + 1 < LSEQ)? *(const float4*)(base + (size_t)r * 512 + 512 + c) : z4;
    int u   = (t + 16) % LSEQ;
    int p2p = u % 32;
    int jl  = (u + LSEQ - 17) % LSEQ;
    int jr  = (u + LSEQ - 15) % LSEQ;
    float4 L2 = (p2p > 0)                  ? *(const float4*)(base + (size_t)(1 + jl) * 512 + c) : z4;
    float4 R2 = (p2p < 31 && u + 1 < LSEQ) ? *(const float4*)(base + (size_t)(1 + jr) * 512 + c) : z4;
    float4 o4;
    o4.x = xc.x + (w0[0]*L1.x + w1[0]*xc.x + w2[0]*R1.x + bb.x)
                + (w0[0]*L2.x + w1[0]*xc.x + w2[0]*R2.x + bb.x);
    o4.y = xc.y + (w0[1]*L1.y + w1[1]*xc.y + w2[1]*R1.y + bb.y)
                + (w0[1]*L2.y + w1[1]*xc.y + w2[1]*R2.y + bb.y);
    o4.z = xc.z + (w0[2]*L1.z + w1[2]*xc.z + w2[2]*R1.z + bb.z)
                + (w0[2]*L2.z + w1[2]*xc.z + w2[2]*R2.z + bb.z);
    o4.w = xc.w + (w0[3]*L1.w + w1[3]*xc.w + w2[3]*R1.w + bb.w)
                + (w0[3]*L2.w + w1[3]*xc.w + w2[3]*R2.w + bb.w);
    *(float4*)drow = o4;
}

// ---------------- flash attention, mma.sync bf16x3 --------------------------
// grid (NN/128, BB*HH), 256 threads = 8 warps, each warp owns 16 query rows.
// 64-key tiles; K/V staged in smem as bf16 hi/lo (split), V transposed.
#define KSTR 72
#define VSTR 66
__global__ __launch_bounds__(256)
void attn_mma_kernel() {
    __shared__ __nv_bfloat16 Ks_hi[64 * KSTR];
    __shared__ __nv_bfloat16 Ks_lo[64 * KSTR];
    __shared__ __nv_bfloat16 Vt_hi[64 * VSTR];
    __shared__ __nv_bfloat16 Vt_lo[64 * VSTR];
    int tid = threadIdx.x;
    int w = tid >> 5, lane = tid & 31;
    int gq = lane >> 2, qq = lane & 3;
    int bh = blockIdx.y;
    int b = bh >> 3, h = bh & 7;
    int q0 = blockIdx.x * 128 + w * 16;

    // ---- load Q fragments (hi/lo split), scale folded in ----
    unsigned qh[4][4], ql[4][4];
    {
        const float* qbase = g_q + ((size_t)b * NN + q0) * 512 + h * 64;
        #pragma unroll
        for (int kk = 0; kk < 4; kk++)
            #pragma unroll
            for (int cc = 0; cc < 2; cc++)
                #pragma unroll
                for (int rr = 0; rr < 2; rr++) {
                    int row = gq + rr * 8;
                    int dim = kk * 16 + cc * 8 + qq * 2;
                    float2 qv = *(const float2*)(qbase + (size_t)row * 512 + dim);
                    splitpk(qv.x * 0.125f, qv.y * 0.125f,
                            qh[kk][rr + 2 * cc], ql[kk][rr + 2 * cc]);
                }
    }

    float O[8][4];
    #pragma unroll
    for (int j = 0; j < 8; j++)
        #pragma unroll
        for (int c = 0; c < 4; c++) O[j][c] = 0.f;
    float rm0 = -1e30f, rm1 = -1e30f, rl0 = 0.f, rl1 = 0.f;

    const float* kbase0 = g_kp + ((size_t)b * NK) * 512 + h * 64;
    const float* vbase0 = g_vp + ((size_t)b * NK) * 512 + h * 64;

    for (int kt = 0; kt < NK; kt += 64) {
        // ---- cooperative tile load + hi/lo split ----
        #pragma unroll
        for (int i = 0; i < 4; i++) {
            int idx = tid + 256 * i;
            int row = idx >> 4, c4 = idx & 15;
            float4 kv = *(const float4*)(kbase0 + (size_t)(kt + row) * 512 + c4 * 4);
            unsigned h01, l01, h23, l23;
            splitpk(kv.x, kv.y, h01, l01);
            splitpk(kv.z, kv.w, h23, l23);
            unsigned* dh = (unsigned*)&Ks_hi[row * KSTR + c4 * 4];
            unsigned* dl = (unsigned*)&Ks_lo[row * KSTR + c4 * 4];
            dh[0] = h01; dh[1] = h23;
            dl[0] = l01; dl[1] = l23;
            float4 vv = *(const float4*)(vbase0 + (size_t)(kt + row) * 512 + c4 * 4);
            #pragma unroll
            for (int e = 0; e < 4; e++) {
                float x = (&vv.x)[e];
                __nv_bfloat16 hb = __float2bfloat16(x);
                __nv_bfloat16 lb = __float2bfloat16(x - __bfloat162float(hb));
                int dim = c4 * 4 + e;
                Vt_hi[dim * VSTR + row] = hb;
                Vt_lo[dim * VSTR + row] = lb;
            }
        }
        __syncthreads();

        // ---- S = Q @ K^T (bf16x3) ----
        float S[8][4];
        #pragma unroll
        for (int j = 0; j < 8; j++) {
            float c[4] = {0.f, 0.f, 0.f, 0.f};
            int key = 8 * j + gq;
            #pragma unroll
            for (int kk = 0; kk < 4; kk++) {
                int doff = kk * 16 + qq * 2;
                unsigned bh0 = *(const unsigned*)&Ks_hi[key * KSTR + doff];
                unsigned bh1 = *(const unsigned*)&Ks_hi[key * KSTR + doff + 8];
                unsigned bl0 = *(const unsigned*)&Ks_lo[key * KSTR + doff];
                unsigned bl1 = *(const unsigned*)&Ks_lo[key * KSTR + doff + 8];
                mma16816(c, qh[kk], bh0, bh1);
                mma16816(c, ql[kk], bh0, bh1);
                mma16816(c, qh[kk], bl0, bl1);
            }
            S[j][0] = c[0]; S[j][1] = c[1]; S[j][2] = c[2]; S[j][3] = c[3];
        }

        // ---- online softmax ----
        float tm0 = -1e30f, tm1 = -1e30f;
        #pragma unroll
        for (int j = 0; j < 8; j++) {
            tm0 = fmaxf(tm0, fmaxf(S[j][0], S[j][1]));
            tm1 = fmaxf(tm1, fmaxf(S[j][2], S[j][3]));
        }
        tm0 = fmaxf(tm0, __shfl_xor_sync(0xffffffffu, tm0, 1));
        tm0 = fmaxf(tm0, __shfl_xor_sync(0xffffffffu, tm0, 2));
        tm1 = fmaxf(tm1, __shfl_xor_sync(0xffffffffu, tm1, 1));
        tm1 = fmaxf(tm1, __shfl_xor_sync(0xffffffffu, tm1, 2));
        float m0n = fmaxf(rm0, tm0), m1n = fmaxf(rm1, tm1);
        float cor0 = __expf(rm0 - m0n), cor1 = __expf(rm1 - m1n);
        rl0 *= cor0; rl1 *= cor1;
        #pragma unroll
        for (int j = 0; j < 8; j++) {
            O[j][0] *= cor0; O[j][1] *= cor0;
            O[j][2] *= cor1; O[j][3] *= cor1;
        }
        rm0 = m0n; rm1 = m1n;

        // ---- P = exp(S - m), pack hi/lo A-fragments ----
        unsigned Ph[4][4], Pl[4][4];
        #pragma unroll
        for (int j = 0; j < 8; j++) {
            float p0 = __expf(S[j][0] - m0n);
            float p1 = __expf(S[j][1] - m0n);
            float p2 = __expf(S[j][2] - m1n);
            float p3 = __expf(S[j][3] - m1n);
            rl0 += p0 + p1; rl1 += p2 + p3;
            int kk2 = j >> 1, half = j & 1;
            splitpk(p0, p1, Ph[kk2][2 * half],     Pl[kk2][2 * half]);
            splitpk(p2, p3, Ph[kk2][2 * half + 1], Pl[kk2][2 * half + 1]);
        }

        // ---- O += P @ V (bf16x3) ----
        #pragma unroll
        for (int jd = 0; jd < 8; jd++) {
            int dim = 8 * jd + gq;
            #pragma unroll
            for (int kk2 = 0; kk2 < 4; kk2++) {
                int koff = kk2 * 16 + qq * 2;
                unsigned vh0 = *(const unsigned*)&Vt_hi[dim * VSTR + koff];
                unsigned vh1 = *(const unsigned*)&Vt_hi[dim * VSTR + koff + 8];
                unsigned vl0 = *(const unsigned*)&Vt_lo[dim * VSTR + koff];
                unsigned vl1 = *(const unsigned*)&Vt_lo[dim * VSTR + koff + 8];
                mma16816(O[jd], Ph[kk2], vh0, vh1);
                mma16816(O[jd], Pl[kk2], vh0, vh1);
                mma16816(O[jd], Ph[kk2], vl0, vl1);
            }
        }
        __syncthreads();
    }

    // ---- finalize: normalize and store ----
    float l0 = rl0, l1 = rl1;
    l0 += __shfl_xor_sync(0xffffffffu, l0, 1);
    l0 += __shfl_xor_sync(0xffffffffu, l0, 2);
    l1 += __shfl_xor_sync(0xffffffffu, l1, 1);
    l1 += __shfl_xor_sync(0xffffffffu, l1, 2);
    float inv0 = 1.0f / l0, inv1 = 1.0f / l1;
    float* obase = g_att + ((size_t)b * NN + q0) * 512 + h * 64;
    #pragma unroll
    for (int jd = 0; jd < 8; jd++) {
        int dim = 8 * jd + qq * 2;
        float2 lo2; lo2.x = O[jd][0] * inv0; lo2.y = O[jd][1] * inv0;
        float2 hi2; hi2.x = O[jd][2] * inv1; hi2.y = O[jd][3] * inv1;
        *(float2*)(obase + (size_t)gq * 512 + dim)       = lo2;
        *(float2*)(obase + (size_t)(gq + 8) * 512 + dim) = hi2;
    }
}

// ---------------- launch ----------------------------------------------------
extern "C" void kernel_launch(void* const* d_in, const int* in_sizes, int n_in,
                              void* d_out, int out_size) {
    const float* x     = (const float*)d_in[0];
    const float* mem   = (const float*)d_in[1];
    const float* ln_g  = (const float*)d_in[2];
    const float* ln_b  = (const float*)d_in[3];
    const float* w_qkv = (const float*)d_in[4];
    const float* w_out = (const float*)d_in[5];
    const float* b_out = (const float*)d_in[6];
    const float* pk_w  = (const float*)d_in[7];
    const float* pk_b  = (const float*)d_in[8];
    const float* pv_w  = (const float*)d_in[9];
    const float* pv_b  = (const float*)d_in[10];
    float* out = (float*)d_out;

    ln_kernel<<<BB * NN, 128>>>(x, ln_g, ln_b);
    sgemm_kernel<<<dim3(1536 / 64, (BB * NN) / 128), 256>>>(w_qkv, nullptr, nullptr, 1536, 0);
    copy_mem_kernel<<<(BB * MM * 512 / 4 + 255) / 256, 256>>>(mem);
    peg_kernel<<<BB * NK, 128>>>(pk_w, pk_b, 0);
    peg_kernel<<<BB * NK, 128>>>(pv_w, pv_b, 1);
    attn_mma_kernel<<<dim3(NN / 128, BB * HH), 256>>>();
    sgemm_kernel<<<dim3(512 / 64, (BB * NN) / 128), 256>>>(w_out, b_out, out, 512, 1);
}

// round 4
// speedup vs baseline: 5.8595x; 1.0296x over previous
#include <cuda_runtime.h>
#include <cuda_bf16.h>
#include <cstring>

#define BB 2
#define NN 4096
#define DD 512
#define HH 8
#define DH 64
#define MM 1024
#define NK 5120          // NN + MM
#define LSEQ 5119        // NK - 1

// ---------------- bf16 split + mma helpers ----------------------------------
__device__ __forceinline__ unsigned b2u(__nv_bfloat162 v) {
    unsigned u; memcpy(&u, &v, 4); return u;
}
__device__ __forceinline__ void splitpk(float x, float y, unsigned &hi, unsigned &lo) {
    __nv_bfloat162 h = __floats2bfloat162_rn(x, y);
    float hx = __bfloat162float(h.x), hy = __bfloat162float(h.y);
    __nv_bfloat162 l = __floats2bfloat162_rn(x - hx, y - hy);
    hi = b2u(h); lo = b2u(l);
}
__device__ __forceinline__ void mma16816(float c[4], const unsigned a[4],
                                         unsigned b0, unsigned b1) {
    asm("mma.sync.aligned.m16n8k16.row.col.f32.bf16.bf16.f32 "
        "{%0,%1,%2,%3},{%4,%5,%6,%7},{%8,%9},{%0,%1,%2,%3};"
        : "+f"(c[0]), "+f"(c[1]), "+f"(c[2]), "+f"(c[3])
        : "r"(a[0]), "r"(a[1]), "r"(a[2]), "r"(a[3]), "r"(b0), "r"(b1));
}

// ---------------- scratch ----------------------------------------------------
__device__ __nv_bfloat16 g_xh[BB * NN * DD];   // LN out hi
__device__ __nv_bfloat16 g_xl[BB * NN * DD];   // LN out lo
__device__ float         g_q [BB * NN * DD];   // q fp32 (gemm1 out)
__device__ float         g_k [BB * NK * DD];   // k ++ mem (pre-PEG fp32)
__device__ float         g_v [BB * NK * DD];
__device__ __nv_bfloat16 g_kh[BB * NK * DD];   // post-PEG K hi/lo
__device__ __nv_bfloat16 g_kl[BB * NK * DD];
__device__ __nv_bfloat16 g_vh[BB * NK * DD];   // post-PEG V hi/lo
__device__ __nv_bfloat16 g_vl[BB * NK * DD];
__device__ __nv_bfloat16 g_ah[BB * NN * DD];   // attention out hi/lo
__device__ __nv_bfloat16 g_al[BB * NN * DD];
__device__ __nv_bfloat16 g_wqh[DD * 3 * DD];   // w_qkv split
__device__ __nv_bfloat16 g_wql[DD * 3 * DD];
__device__ __nv_bfloat16 g_woh[DD * DD];       // w_out split
__device__ __nv_bfloat16 g_wol[DD * DD];

// ---------------- fp32 -> bf16 hi/lo splitter (weights) ---------------------
__global__ void split_kernel(const float* __restrict__ src,
                             __nv_bfloat16* __restrict__ hi,
                             __nv_bfloat16* __restrict__ lo, int n4) {
    int i = blockIdx.x * 256 + threadIdx.x;
    if (i >= n4) return;
    float4 v = ((const float4*)src)[i];
    unsigned h0, l0, h1, l1;
    splitpk(v.x, v.y, h0, l0);
    splitpk(v.z, v.w, h1, l1);
    ((uint2*)hi)[i] = make_uint2(h0, h1);
    ((uint2*)lo)[i] = make_uint2(l0, l1);
}

// ---------------- LayerNorm (writes hi/lo bf16) ------------------------------
__global__ void ln_kernel(const float* __restrict__ x,
                          const float* __restrict__ g,
                          const float* __restrict__ bt) {
    int row = blockIdx.x;
    int t = threadIdx.x;
    const float4* xr = (const float4*)(x + (size_t)row * DD);
    float4 v = xr[t];
    float s  = v.x + v.y + v.z + v.w;
    float s2 = v.x*v.x + v.y*v.y + v.z*v.z + v.w*v.w;
    #pragma unroll
    for (int o = 16; o > 0; o >>= 1) {
        s  += __shfl_xor_sync(0xffffffffu, s,  o);
        s2 += __shfl_xor_sync(0xffffffffu, s2, o);
    }
    __shared__ float a1[4], a2[4];
    int w = t >> 5;
    if ((t & 31) == 0) { a1[w] = s; a2[w] = s2; }
    __syncthreads();
    s  = a1[0] + a1[1] + a1[2] + a1[3];
    s2 = a2[0] + a2[1] + a2[2] + a2[3];
    float mu  = s * (1.0f / 512.0f);
    float var = s2 * (1.0f / 512.0f) - mu * mu;
    float rs  = rsqrtf(var + 1e-5f);
    float4 gg = ((const float4*)g)[t];
    float4 bb = ((const float4*)bt)[t];
    float4 o4;
    o4.x = (v.x - mu) * rs * gg.x + bb.x;
    o4.y = (v.y - mu) * rs * gg.y + bb.y;
    o4.z = (v.z - mu) * rs * gg.z + bb.z;
    o4.w = (v.w - mu) * rs * gg.w + bb.w;
    unsigned h0, l0, h1, l1;
    splitpk(o4.x, o4.y, h0, l0);
    splitpk(o4.z, o4.w, h1, l1);
    ((uint2*)(g_xh + (size_t)row * DD))[t] = make_uint2(h0, h1);
    ((uint2*)(g_xl + (size_t)row * DD))[t] = make_uint2(l0, l1);
}

// ---------------- bf16x3 mma GEMM: C[8192 x cn] = A[8192x512] @ W[512 x cn] --
// block: 128 rows x 64 cols, 8 warps (4 m x 2 n), warp tile m32 x n32.
// mode 0: A=g_xh/g_xl, W=wq split, scatter -> g_q/g_k/g_v fp32
// mode 1: A=g_ah/g_al, W=wo split, bias add -> dout
__global__ __launch_bounds__(256)
void mma_gemm_kernel(const __nv_bfloat16* __restrict__ Wh,
                     const __nv_bfloat16* __restrict__ Wl,
                     const float* __restrict__ bias,
                     float* __restrict__ dout, int cn, int mode) {
    const __nv_bfloat16* Ah = mode ? g_ah : g_xh;
    const __nv_bfloat16* Al = mode ? g_al : g_xl;
    __shared__ __align__(16) __nv_bfloat16 sAh[128 * 40];
    __shared__ __align__(16) __nv_bfloat16 sAl[128 * 40];
    __shared__ __align__(16) __nv_bfloat16 sWh[64 * 40];
    __shared__ __align__(16) __nv_bfloat16 sWl[64 * 40];
    int tid = threadIdx.x, w = tid >> 5, lane = tid & 31;
    int gq = lane >> 2, qq = lane & 3;
    int row0 = blockIdx.y * 128, col0 = blockIdx.x * 64;
    int wm = w >> 1, wn = w & 1;
    float acc[2][4][4];
    #pragma unroll
    for (int mf = 0; mf < 2; mf++)
        #pragma unroll
        for (int nf = 0; nf < 4; nf++)
            #pragma unroll
            for (int c = 0; c < 4; c++) acc[mf][nf][c] = 0.f;

    for (int kt = 0; kt < 512; kt += 32) {
        #pragma unroll
        for (int i = 0; i < 2; i++) {
            int idx = tid + 256 * i;          // 512 slots
            int r = idx >> 2, e = idx & 3;    // row, 8-elt chunk
            *(uint4*)&sAh[r * 40 + 8 * e] =
                *(const uint4*)(Ah + (size_t)(row0 + r) * 512 + kt + 8 * e);
            *(uint4*)&sAl[r * 40 + 8 * e] =
                *(const uint4*)(Al + (size_t)(row0 + r) * 512 + kt + 8 * e);
        }
        {
            int r = tid >> 3, e = tid & 7;    // k-row, n chunk
            uint4 hv = *(const uint4*)(Wh + (size_t)(kt + r) * cn + col0 + 8 * e);
            uint4 lv = *(const uint4*)(Wl + (size_t)(kt + r) * cn + col0 + 8 * e);
            const __nv_bfloat16* hp = (const __nv_bfloat16*)&hv;
            const __nv_bfloat16* lp = (const __nv_bfloat16*)&lv;
            #pragma unroll
            for (int j = 0; j < 8; j++) {
                sWh[(8 * e + j) * 40 + r] = hp[j];
                sWl[(8 * e + j) * 40 + r] = lp[j];
            }
        }
        __syncthreads();
        #pragma unroll
        for (int ks = 0; ks < 2; ks++) {
            int k0 = ks * 16;
            unsigned ah[2][4], al[2][4];
            #pragma unroll
            for (int mf = 0; mf < 2; mf++) {
                int rbase = wm * 32 + mf * 16 + gq;
                #pragma unroll
                for (int cc = 0; cc < 2; cc++)
                    #pragma unroll
                    for (int rr = 0; rr < 2; rr++) {
                        int r = rbase + rr * 8;
                        int kk = k0 + cc * 8 + qq * 2;
                        ah[mf][rr + 2 * cc] = *(const unsigned*)&sAh[r * 40 + kk];
                        al[mf][rr + 2 * cc] = *(const unsigned*)&sAl[r * 40 + kk];
                    }
            }
            #pragma unroll
            for (int nf = 0; nf < 4; nf++) {
                int n = wn * 32 + nf * 8 + gq;
                unsigned bh0 = *(const unsigned*)&sWh[n * 40 + k0 + qq * 2];
                unsigned bh1 = *(const unsigned*)&sWh[n * 40 + k0 + 8 + qq * 2];
                unsigned bl0 = *(const unsigned*)&sWl[n * 40 + k0 + qq * 2];
                unsigned bl1 = *(const unsigned*)&sWl[n * 40 + k0 + 8 + qq * 2];
                #pragma unroll
                for (int mf = 0; mf < 2; mf++) {
                    mma16816(acc[mf][nf], ah[mf], bh0, bh1);
                    mma16816(acc[mf][nf], al[mf], bh0, bh1);
                    mma16816(acc[mf][nf], ah[mf], bl0, bl1);
                }
            }
        }
        __syncthreads();
    }
    // epilogue
    #pragma unroll
    for (int mf = 0; mf < 2; mf++) {
        int rlo = row0 + wm * 32 + mf * 16 + gq;
        #pragma unroll
        for (int nf = 0; nf < 4; nf++) {
            int cl = col0 + wn * 32 + nf * 8 + 2 * qq;
            float* c = acc[mf][nf];
            if (mode == 0) {
                #pragma unroll
                for (int half = 0; half < 2; half++) {
                    int rr = rlo + half * 8;
                    int b = rr >> 12, n = rr & 4095;
                    #pragma unroll
                    for (int j = 0; j < 2; j++) {
                        int cc = cl + j;
                        int sel = cc >> 9, c5 = cc & 511;
                        float vv = c[2 * half + j];
                        if (sel == 0)      g_q[((size_t)b * NN + n) * 512 + c5] = vv;
                        else if (sel == 1) g_k[((size_t)b * NK + n) * 512 + c5] = vv;
                        else               g_v[((size_t)b * NK + n) * 512 + c5] = vv;
                    }
                }
            } else {
                float2 bq = *(const float2*)(bias + cl);
                float2 o0; o0.x = c[0] + bq.x; o0.y = c[1] + bq.y;
                float2 o1; o1.x = c[2] + bq.x; o1.y = c[3] + bq.y;
                *(float2*)(dout + (size_t)rlo * 512 + cl)       = o0;
                *(float2*)(dout + (size_t)(rlo + 8) * 512 + cl) = o1;
            }
        }
    }
}

// ---------------- append mem rows to k and v tails --------------------------
__global__ void copy_mem_kernel(const float* __restrict__ mem) {
    int i = blockIdx.x * blockDim.x + threadIdx.x;
    if (i >= BB * MM * 512 / 4) return;
    float4 v = ((const float4*)mem)[i];
    int gi = i << 2;
    int b = gi / (MM * 512);
    int rem = gi - b * (MM * 512);
    size_t off = ((size_t)b * NK + NN) * 512 + rem;
    *(float4*)(g_k + off) = v;
    *(float4*)(g_v + off) = v;
}

// ---------------- PEG1D depthwise conv -> hi/lo bf16 ------------------------
__global__ void peg_kernel(const float* __restrict__ w,
                           const float* __restrict__ bias, int which) {
    const float* src = which ? g_v : g_k;
    __nv_bfloat16* dh = which ? g_vh : g_kh;
    __nv_bfloat16* dl = which ? g_vl : g_kl;
    int gr = blockIdx.x;
    int b = gr / NK, r = gr - b * NK;
    int c = threadIdx.x << 2;
    const float* base = src + (size_t)b * NK * 512;
    float4 xc = *(const float4*)(base + (size_t)r * 512 + c);
    size_t doff = ((size_t)b * NK + r) * 512 + c;
    float4 o4;
    if (r == 0) {
        o4 = xc;
    } else {
        int t = r - 1;
        float w0[4], w1[4], w2[4];
        #pragma unroll
        for (int j = 0; j < 4; j++) {
            w0[j] = __ldg(w + (c + j) * 3 + 0);
            w1[j] = __ldg(w + (c + j) * 3 + 1);
            w2[j] = __ldg(w + (c + j) * 3 + 2);
        }
        float4 bb = *(const float4*)(bias + c);
        const float4 z4 = make_float4(0.f, 0.f, 0.f, 0.f);
        int p = t & 31;
        float4 L1 = (p > 0)                 ? *(const float4*)(base + (size_t)r * 512 - 512 + c) : z4;
        float4 R1 = (p < 31 && t + 1 < LSEQ)? *(const float4*)(base + (size_t)r * 512 + 512 + c) : z4;
        int u   = (t + 16) % LSEQ;
        int p2p = u % 32;
        int jl  = (u + LSEQ - 17) % LSEQ;
        int jr  = (u + LSEQ - 15) % LSEQ;
        float4 L2 = (p2p > 0)                  ? *(const float4*)(base + (size_t)(1 + jl) * 512 + c) : z4;
        float4 R2 = (p2p < 31 && u + 1 < LSEQ) ? *(const float4*)(base + (size_t)(1 + jr) * 512 + c) : z4;
        o4.x = xc.x + (w0[0]*L1.x + w1[0]*xc.x + w2[0]*R1.x + bb.x)
                    + (w0[0]*L2.x + w1[0]*xc.x + w2[0]*R2.x + bb.x);
        o4.y = xc.y + (w0[1]*L1.y + w1[1]*xc.y + w2[1]*R1.y + bb.y)
                    + (w0[1]*L2.y + w1[1]*xc.y + w2[1]*R2.y + bb.y);
        o4.z = xc.z + (w0[2]*L1.z + w1[2]*xc.z + w2[2]*R1.z + bb.z)
                    + (w0[2]*L2.z + w1[2]*xc.z + w2[2]*R2.z + bb.z);
        o4.w = xc.w + (w0[3]*L1.w + w1[3]*xc.w + w2[3]*R1.w + bb.w)
                    + (w0[3]*L2.w + w1[3]*xc.w + w2[3]*R2.w + bb.w);
    }
    unsigned h0, l0, h1, l1;
    splitpk(o4.x, o4.y, h0, l0);
    splitpk(o4.z, o4.w, h1, l1);
    *(uint2*)(dh + doff) = make_uint2(h0, h1);
    *(uint2*)(dl + doff) = make_uint2(l0, l1);
}

// ---------------- flash attention, mma.sync bf16x3 --------------------------
#define KSTR 72
#define VSTR 66
__global__ __launch_bounds__(256)
void attn_mma_kernel() {
    __shared__ __align__(16) __nv_bfloat16 Ks_hi[64 * KSTR];
    __shared__ __align__(16) __nv_bfloat16 Ks_lo[64 * KSTR];
    __shared__ __align__(16) __nv_bfloat16 Vt_hi[64 * VSTR];
    __shared__ __align__(16) __nv_bfloat16 Vt_lo[64 * VSTR];
    int tid = threadIdx.x;
    int w = tid >> 5, lane = tid & 31;
    int gq = lane >> 2, qq = lane & 3;
    int bh = blockIdx.y;
    int b = bh >> 3, h = bh & 7;
    int q0 = blockIdx.x * 128 + w * 16;

    unsigned qh[4][4], ql[4][4];
    {
        const float* qbase = g_q + ((size_t)b * NN + q0) * 512 + h * 64;
        #pragma unroll
        for (int kk = 0; kk < 4; kk++)
            #pragma unroll
            for (int cc = 0; cc < 2; cc++)
                #pragma unroll
                for (int rr = 0; rr < 2; rr++) {
                    int row = gq + rr * 8;
                    int dim = kk * 16 + cc * 8 + qq * 2;
                    float2 qv = *(const float2*)(qbase + (size_t)row * 512 + dim);
                    splitpk(qv.x * 0.125f, qv.y * 0.125f,
                            qh[kk][rr + 2 * cc], ql[kk][rr + 2 * cc]);
                }
    }

    float O[8][4];
    #pragma unroll
    for (int j = 0; j < 8; j++)
        #pragma unroll
        for (int c = 0; c < 4; c++) O[j][c] = 0.f;
    float rm0 = -1e30f, rm1 = -1e30f, rl0 = 0.f, rl1 = 0.f;

    const __nv_bfloat16* khb = g_kh + ((size_t)b * NK) * 512 + h * 64;
    const __nv_bfloat16* klb = g_kl + ((size_t)b * NK) * 512 + h * 64;
    const __nv_bfloat16* vhb = g_vh + ((size_t)b * NK) * 512 + h * 64;
    const __nv_bfloat16* vlb = g_vl + ((size_t)b * NK) * 512 + h * 64;

    for (int kt = 0; kt < NK; kt += 64) {
        #pragma unroll
        for (int i = 0; i < 2; i++) {
            int idx = tid + 256 * i;           // 512 slots
            int row = idx >> 3, e = idx & 7;   // key row, 8-dim chunk
            *(uint4*)&Ks_hi[row * KSTR + 8 * e] =
                *(const uint4*)(khb + (size_t)(kt + row) * 512 + 8 * e);
            *(uint4*)&Ks_lo[row * KSTR + 8 * e] =
                *(const uint4*)(klb + (size_t)(kt + row) * 512 + 8 * e);
            uint4 vh = *(const uint4*)(vhb + (size_t)(kt + row) * 512 + 8 * e);
            uint4 vl = *(const uint4*)(vlb + (size_t)(kt + row) * 512 + 8 * e);
            const __nv_bfloat16* vhp = (const __nv_bfloat16*)&vh;
            const __nv_bfloat16* vlp = (const __nv_bfloat16*)&vl;
            #pragma unroll
            for (int j = 0; j < 8; j++) {
                Vt_hi[(8 * e + j) * VSTR + row] = vhp[j];
                Vt_lo[(8 * e + j) * VSTR + row] = vlp[j];
            }
        }
        __syncthreads();

        float S[8][4];
        #pragma unroll
        for (int j = 0; j < 8; j++) {
            float c[4] = {0.f, 0.f, 0.f, 0.f};
            int key = 8 * j + gq;
            #pragma unroll
            for (int kk = 0; kk < 4; kk++) {
                int doff = kk * 16 + qq * 2;
                unsigned bh0 = *(const unsigned*)&Ks_hi[key * KSTR + doff];
                unsigned bh1 = *(const unsigned*)&Ks_hi[key * KSTR + doff + 8];
                unsigned bl0 = *(const unsigned*)&Ks_lo[key * KSTR + doff];
                unsigned bl1 = *(const unsigned*)&Ks_lo[key * KSTR + doff + 8];
                mma16816(c, qh[kk], bh0, bh1);
                mma16816(c, ql[kk], bh0, bh1);
                mma16816(c, qh[kk], bl0, bl1);
            }
            S[j][0] = c[0]; S[j][1] = c[1]; S[j][2] = c[2]; S[j][3] = c[3];
        }

        float tm0 = -1e30f, tm1 = -1e30f;
        #pragma unroll
        for (int j = 0; j < 8; j++) {
            tm0 = fmaxf(tm0, fmaxf(S[j][0], S[j][1]));
            tm1 = fmaxf(tm1, fmaxf(S[j][2], S[j][3]));
        }
        tm0 = fmaxf(tm0, __shfl_xor_sync(0xffffffffu, tm0, 1));
        tm0 = fmaxf(tm0, __shfl_xor_sync(0xffffffffu, tm0, 2));
        tm1 = fmaxf(tm1, __shfl_xor_sync(0xffffffffu, tm1, 1));
        tm1 = fmaxf(tm1, __shfl_xor_sync(0xffffffffu, tm1, 2));
        float m0n = fmaxf(rm0, tm0), m1n = fmaxf(rm1, tm1);
        float cor0 = __expf(rm0 - m0n), cor1 = __expf(rm1 - m1n);
        rl0 *= cor0; rl1 *= cor1;
        #pragma unroll
        for (int j = 0; j < 8; j++) {
            O[j][0] *= cor0; O[j][1] *= cor0;
            O[j][2] *= cor1; O[j][3] *= cor1;
        }
        rm0 = m0n; rm1 = m1n;

        unsigned Ph[4][4], Pl[4][4];
        #pragma unroll
        for (int j = 0; j < 8; j++) {
            float p0 = __expf(S[j][0] - m0n);
            float p1 = __expf(S[j][1] - m0n);
            float p2 = __expf(S[j][2] - m1n);
            float p3 = __expf(S[j][3] - m1n);
            rl0 += p0 + p1; rl1 += p2 + p3;
            int kk2 = j >> 1, half = j & 1;
            splitpk(p0, p1, Ph[kk2][2 * half],     Pl[kk2][2 * half]);
            splitpk(p2, p3, Ph[kk2][2 * half + 1], Pl[kk2][2 * half + 1]);
        }

        #pragma unroll
        for (int jd = 0; jd < 8; jd++) {
            int dim = 8 * jd + gq;
            #pragma unroll
            for (int kk2 = 0; kk2 < 4; kk2++) {
                int koff = kk2 * 16 + qq * 2;
                unsigned vh0 = *(const unsigned*)&Vt_hi[dim * VSTR + koff];
                unsigned vh1 = *(const unsigned*)&Vt_hi[dim * VSTR + koff + 8];
                unsigned vl0 = *(const unsigned*)&Vt_lo[dim * VSTR + koff];
                unsigned vl1 = *(const unsigned*)&Vt_lo[dim * VSTR + koff + 8];
                mma16816(O[jd], Ph[kk2], vh0, vh1);
                mma16816(O[jd], Pl[kk2], vh0, vh1);
                mma16816(O[jd], Ph[kk2], vl0, vl1);
            }
        }
        __syncthreads();
    }

    float l0 = rl0, l1 = rl1;
    l0 += __shfl_xor_sync(0xffffffffu, l0, 1);
    l0 += __shfl_xor_sync(0xffffffffu, l0, 2);
    l1 += __shfl_xor_sync(0xffffffffu, l1, 1);
    l1 += __shfl_xor_sync(0xffffffffu, l1, 2);
    float inv0 = 1.0f / l0, inv1 = 1.0f / l1;
    size_t obase = ((size_t)b * NN + q0) * 512 + h * 64;
    #pragma unroll
    for (int jd = 0; jd < 8; jd++) {
        int dim = 8 * jd + qq * 2;
        unsigned h2, l2;
        splitpk(O[jd][0] * inv0, O[jd][1] * inv0, h2, l2);
        *(unsigned*)&g_ah[obase + (size_t)gq * 512 + dim] = h2;
        *(unsigned*)&g_al[obase + (size_t)gq * 512 + dim] = l2;
        splitpk(O[jd][2] * inv1, O[jd][3] * inv1, h2, l2);
        *(unsigned*)&g_ah[obase + (size_t)(gq + 8) * 512 + dim] = h2;
        *(unsigned*)&g_al[obase + (size_t)(gq + 8) * 512 + dim] = l2;
    }
}

// ---------------- launch ----------------------------------------------------
extern "C" void kernel_launch(void* const* d_in, const int* in_sizes, int n_in,
                              void* d_out, int out_size) {
    const float* x     = (const float*)d_in[0];
    const float* mem   = (const float*)d_in[1];
    const float* ln_g  = (const float*)d_in[2];
    const float* ln_b  = (const float*)d_in[3];
    const float* w_qkv = (const float*)d_in[4];
    const float* w_out = (const float*)d_in[5];
    const float* b_out = (const float*)d_in[6];
    const float* pk_w  = (const float*)d_in[7];
    const float* pk_b  = (const float*)d_in[8];
    const float* pv_w  = (const float*)d_in[9];
    const float* pv_b  = (const float*)d_in[10];
    float* out = (float*)d_out;

    __nv_bfloat16 *wqh, *wql, *woh, *wol;
    cudaGetSymbolAddress((void**)&wqh, g_wqh);
    cudaGetSymbolAddress((void**)&wql, g_wql);
    cudaGetSymbolAddress((void**)&woh, g_woh);
    cudaGetSymbolAddress((void**)&wol, g_wol);

    split_kernel<<<(DD * 3 * DD / 4 + 255) / 256, 256>>>(w_qkv, wqh, wql, DD * 3 * DD / 4);
    split_kernel<<<(DD * DD / 4 + 255) / 256, 256>>>(w_out, woh, wol, DD * DD / 4);
    ln_kernel<<<BB * NN, 128>>>(x, ln_g, ln_b);
    mma_gemm_kernel<<<dim3(1536 / 64, (BB * NN) / 128), 256>>>(wqh, wql, nullptr, nullptr, 1536, 0);
    copy_mem_kernel<<<(BB * MM * 512 / 4 + 255) / 256, 256>>>(mem);
    peg_kernel<<<BB * NK, 128>>>(pk_w, pk_b, 0);
    peg_kernel<<<BB * NK, 128>>>(pv_w, pv_b, 1);
    attn_mma_kernel<<<dim3(NN / 128, BB * HH), 256>>>();
    mma_gemm_kernel<<<dim3(512 / 64, (BB * NN) / 128), 256>>>(woh, wol, b_out, out, 512, 1);
}

// round 5
// speedup vs baseline: 7.6974x; 1.3137x over previous
#include <cuda_runtime.h>
#include <cuda_bf16.h>
#include <cstring>

#define BB 2
#define NN 4096
#define DD 512
#define HH 8
#define DH 64
#define MM 1024
#define NK 5120          // NN + MM
#define LSEQ 5119        // NK - 1

// ---------------- bf16 split + mma + ldmatrix helpers -----------------------
__device__ __forceinline__ unsigned b2u(__nv_bfloat162 v) {
    unsigned u; memcpy(&u, &v, 4); return u;
}
__device__ __forceinline__ void splitpk(float x, float y, unsigned &hi, unsigned &lo) {
    __nv_bfloat162 h = __floats2bfloat162_rn(x, y);
    float hx = __bfloat162float(h.x), hy = __bfloat162float(h.y);
    __nv_bfloat162 l = __floats2bfloat162_rn(x - hx, y - hy);
    hi = b2u(h); lo = b2u(l);
}
__device__ __forceinline__ void mma16816(float c[4], const unsigned a[4],
                                         unsigned b0, unsigned b1) {
    asm("mma.sync.aligned.m16n8k16.row.col.f32.bf16.bf16.f32 "
        "{%0,%1,%2,%3},{%4,%5,%6,%7},{%8,%9},{%0,%1,%2,%3};"
        : "+f"(c[0]), "+f"(c[1]), "+f"(c[2]), "+f"(c[3])
        : "r"(a[0]), "r"(a[1]), "r"(a[2]), "r"(a[3]), "r"(b0), "r"(b1));
}
__device__ __forceinline__ unsigned su(const void* p) {
    return (unsigned)__cvta_generic_to_shared(p);
}
__device__ __forceinline__ void ldsm4(unsigned* r, unsigned addr) {
    asm volatile("ldmatrix.sync.aligned.m8n8.x4.shared.b16 {%0,%1,%2,%3}, [%4];"
                 : "=r"(r[0]), "=r"(r[1]), "=r"(r[2]), "=r"(r[3]) : "r"(addr));
}
__device__ __forceinline__ void ldsm4t(unsigned* r, unsigned addr) {
    asm volatile("ldmatrix.sync.aligned.m8n8.x4.trans.shared.b16 {%0,%1,%2,%3}, [%4];"
                 : "=r"(r[0]), "=r"(r[1]), "=r"(r[2]), "=r"(r[3]) : "r"(addr));
}

// ---------------- scratch ----------------------------------------------------
__device__ __nv_bfloat16 g_xh[BB * NN * DD];
__device__ __nv_bfloat16 g_xl[BB * NN * DD];
__device__ float         g_q [BB * NN * DD];
__device__ float         g_k [BB * NK * DD];
__device__ float         g_v [BB * NK * DD];
__device__ __nv_bfloat16 g_kh[BB * NK * DD];
__device__ __nv_bfloat16 g_kl[BB * NK * DD];
__device__ __nv_bfloat16 g_vh[BB * NK * DD];
__device__ __nv_bfloat16 g_vl[BB * NK * DD];
__device__ __nv_bfloat16 g_ah[BB * NN * DD];
__device__ __nv_bfloat16 g_al[BB * NN * DD];
__device__ __nv_bfloat16 g_wqh[DD * 3 * DD];
__device__ __nv_bfloat16 g_wql[DD * 3 * DD];
__device__ __nv_bfloat16 g_woh[DD * DD];
__device__ __nv_bfloat16 g_wol[DD * DD];

// ---------------- fp32 -> bf16 hi/lo splitter (weights) ---------------------
__global__ void split_kernel(const float* __restrict__ src,
                             __nv_bfloat16* __restrict__ hi,
                             __nv_bfloat16* __restrict__ lo, int n4) {
    int i = blockIdx.x * 256 + threadIdx.x;
    if (i >= n4) return;
    float4 v = ((const float4*)src)[i];
    unsigned h0, l0, h1, l1;
    splitpk(v.x, v.y, h0, l0);
    splitpk(v.z, v.w, h1, l1);
    ((uint2*)hi)[i] = make_uint2(h0, h1);
    ((uint2*)lo)[i] = make_uint2(l0, l1);
}

// ---------------- LayerNorm (writes hi/lo bf16) ------------------------------
__global__ void ln_kernel(const float* __restrict__ x,
                          const float* __restrict__ g,
                          const float* __restrict__ bt) {
    int row = blockIdx.x;
    int t = threadIdx.x;
    const float4* xr = (const float4*)(x + (size_t)row * DD);
    float4 v = xr[t];
    float s  = v.x + v.y + v.z + v.w;
    float s2 = v.x*v.x + v.y*v.y + v.z*v.z + v.w*v.w;
    #pragma unroll
    for (int o = 16; o > 0; o >>= 1) {
        s  += __shfl_xor_sync(0xffffffffu, s,  o);
        s2 += __shfl_xor_sync(0xffffffffu, s2, o);
    }
    __shared__ float a1[4], a2[4];
    int w = t >> 5;
    if ((t & 31) == 0) { a1[w] = s; a2[w] = s2; }
    __syncthreads();
    s  = a1[0] + a1[1] + a1[2] + a1[3];
    s2 = a2[0] + a2[1] + a2[2] + a2[3];
    float mu  = s * (1.0f / 512.0f);
    float var = s2 * (1.0f / 512.0f) - mu * mu;
    float rs  = rsqrtf(var + 1e-5f);
    float4 gg = ((const float4*)g)[t];
    float4 bb = ((const float4*)bt)[t];
    float4 o4;
    o4.x = (v.x - mu) * rs * gg.x + bb.x;
    o4.y = (v.y - mu) * rs * gg.y + bb.y;
    o4.z = (v.z - mu) * rs * gg.z + bb.z;
    o4.w = (v.w - mu) * rs * gg.w + bb.w;
    unsigned h0, l0, h1, l1;
    splitpk(o4.x, o4.y, h0, l0);
    splitpk(o4.z, o4.w, h1, l1);
    ((uint2*)(g_xh + (size_t)row * DD))[t] = make_uint2(h0, h1);
    ((uint2*)(g_xl + (size_t)row * DD))[t] = make_uint2(l0, l1);
}

// ---------------- bf16x3 mma GEMM with ldmatrix -----------------------------
// block 128 x 64, 8 warps (4m x 2n), warp tile m32 x n32, k-step 32.
#define WSTR 72
__global__ __launch_bounds__(256)
void mma_gemm_kernel(const __nv_bfloat16* __restrict__ Wh,
                     const __nv_bfloat16* __restrict__ Wl,
                     const float* __restrict__ bias,
                     float* __restrict__ dout, int cn, int mode) {
    const __nv_bfloat16* Ah = mode ? g_ah : g_xh;
    const __nv_bfloat16* Al = mode ? g_al : g_xl;
    __shared__ __align__(16) __nv_bfloat16 sAh[128 * 40];
    __shared__ __align__(16) __nv_bfloat16 sAl[128 * 40];
    __shared__ __align__(16) __nv_bfloat16 sWh[32 * WSTR];
    __shared__ __align__(16) __nv_bfloat16 sWl[32 * WSTR];
    int tid = threadIdx.x, w = tid >> 5, lane = tid & 31;
    int gq = lane >> 2, qq = lane & 3;
    int lt = lane >> 3, lr = lane & 7;          // ldmatrix tile / row
    int row0 = blockIdx.y * 128, col0 = blockIdx.x * 64;
    int wm = w >> 1, wn = w & 1;
    float acc[2][4][4];
    #pragma unroll
    for (int mf = 0; mf < 2; mf++)
        #pragma unroll
        for (int nf = 0; nf < 4; nf++)
            #pragma unroll
            for (int c = 0; c < 4; c++) acc[mf][nf][c] = 0.f;

    for (int kt = 0; kt < 512; kt += 32) {
        #pragma unroll
        for (int i = 0; i < 2; i++) {
            int idx = tid + 256 * i;          // 512 slots
            int r = idx >> 2, e = idx & 3;
            *(uint4*)&sAh[r * 40 + 8 * e] =
                *(const uint4*)(Ah + (size_t)(row0 + r) * 512 + kt + 8 * e);
            *(uint4*)&sAl[r * 40 + 8 * e] =
                *(const uint4*)(Al + (size_t)(row0 + r) * 512 + kt + 8 * e);
        }
        {
            int r = tid >> 3, e = tid & 7;    // k-row, n chunk (row-major copy)
            *(uint4*)&sWh[r * WSTR + 8 * e] =
                *(const uint4*)(Wh + (size_t)(kt + r) * cn + col0 + 8 * e);
            *(uint4*)&sWl[r * WSTR + 8 * e] =
                *(const uint4*)(Wl + (size_t)(kt + r) * cn + col0 + 8 * e);
        }
        __syncthreads();
        #pragma unroll
        for (int ks = 0; ks < 2; ks++) {
            int k0 = ks * 16;
            unsigned ah[2][4], al[2][4];
            #pragma unroll
            for (int mf = 0; mf < 2; mf++) {
                int ar = wm * 32 + mf * 16 + (lt & 1) * 8 + lr;
                int ak = k0 + (lt >> 1) * 8;
                ldsm4(ah[mf], su(&sAh[ar * 40 + ak]));
                ldsm4(al[mf], su(&sAl[ar * 40 + ak]));
            }
            unsigned bh[2][4], bl[2][4];      // [nh][frag]: frags nf=2nh, 2nh+1
            #pragma unroll
            for (int nh = 0; nh < 2; nh++) {
                int br = k0 + (lt & 1) * 8 + lr;
                int bc = wn * 32 + nh * 16 + (lt >> 1) * 8;
                ldsm4t(bh[nh], su(&sWh[br * WSTR + bc]));
                ldsm4t(bl[nh], su(&sWl[br * WSTR + bc]));
            }
            #pragma unroll
            for (int nf = 0; nf < 4; nf++) {
                unsigned bh0 = bh[nf >> 1][(nf & 1) * 2];
                unsigned bh1 = bh[nf >> 1][(nf & 1) * 2 + 1];
                unsigned bl0 = bl[nf >> 1][(nf & 1) * 2];
                unsigned bl1 = bl[nf >> 1][(nf & 1) * 2 + 1];
                #pragma unroll
                for (int mf = 0; mf < 2; mf++) {
                    mma16816(acc[mf][nf], ah[mf], bh0, bh1);
                    mma16816(acc[mf][nf], al[mf], bh0, bh1);
                    mma16816(acc[mf][nf], ah[mf], bl0, bl1);
                }
            }
        }
        __syncthreads();
    }
    #pragma unroll
    for (int mf = 0; mf < 2; mf++) {
        int rlo = row0 + wm * 32 + mf * 16 + gq;
        #pragma unroll
        for (int nf = 0; nf < 4; nf++) {
            int cl = col0 + wn * 32 + nf * 8 + 2 * qq;
            float* c = acc[mf][nf];
            if (mode == 0) {
                #pragma unroll
                for (int half = 0; half < 2; half++) {
                    int rr = rlo + half * 8;
                    int b = rr >> 12, n = rr & 4095;
                    #pragma unroll
                    for (int j = 0; j < 2; j++) {
                        int cc = cl + j;
                        int sel = cc >> 9, c5 = cc & 511;
                        float vv = c[2 * half + j];
                        if (sel == 0)      g_q[((size_t)b * NN + n) * 512 + c5] = vv;
                        else if (sel == 1) g_k[((size_t)b * NK + n) * 512 + c5] = vv;
                        else               g_v[((size_t)b * NK + n) * 512 + c5] = vv;
                    }
                }
            } else {
                float2 bq = *(const float2*)(bias + cl);
                float2 o0; o0.x = c[0] + bq.x; o0.y = c[1] + bq.y;
                float2 o1; o1.x = c[2] + bq.x; o1.y = c[3] + bq.y;
                *(float2*)(dout + (size_t)rlo * 512 + cl)       = o0;
                *(float2*)(dout + (size_t)(rlo + 8) * 512 + cl) = o1;
            }
        }
    }
}

// ---------------- append mem rows to k and v tails --------------------------
__global__ void copy_mem_kernel(const float* __restrict__ mem) {
    int i = blockIdx.x * blockDim.x + threadIdx.x;
    if (i >= BB * MM * 512 / 4) return;
    float4 v = ((const float4*)mem)[i];
    int gi = i << 2;
    int b = gi / (MM * 512);
    int rem = gi - b * (MM * 512);
    size_t off = ((size_t)b * NK + NN) * 512 + rem;
    *(float4*)(g_k + off) = v;
    *(float4*)(g_v + off) = v;
}

// ---------------- PEG1D depthwise conv -> hi/lo bf16 ------------------------
__global__ void peg_kernel(const float* __restrict__ w,
                           const float* __restrict__ bias, int which) {
    const float* src = which ? g_v : g_k;
    __nv_bfloat16* dh = which ? g_vh : g_kh;
    __nv_bfloat16* dl = which ? g_vl : g_kl;
    int gr = blockIdx.x;
    int b = gr / NK, r = gr - b * NK;
    int c = threadIdx.x << 2;
    const float* base = src + (size_t)b * NK * 512;
    float4 xc = *(const float4*)(base + (size_t)r * 512 + c);
    size_t doff = ((size_t)b * NK + r) * 512 + c;
    float4 o4;
    if (r == 0) {
        o4 = xc;
    } else {
        int t = r - 1;
        float w0[4], w1[4], w2[4];
        #pragma unroll
        for (int j = 0; j < 4; j++) {
            w0[j] = __ldg(w + (c + j) * 3 + 0);
            w1[j] = __ldg(w + (c + j) * 3 + 1);
            w2[j] = __ldg(w + (c + j) * 3 + 2);
        }
        float4 bb = *(const float4*)(bias + c);
        const float4 z4 = make_float4(0.f, 0.f, 0.f, 0.f);
        int p = t & 31;
        float4 L1 = (p > 0)                 ? *(const float4*)(base + (size_t)r * 512 - 512 + c) : z4;
        float4 R1 = (p < 31 && t + 1 < LSEQ)? *(const float4*)(base + (size_t)r * 512 + 512 + c) : z4;
        int u   = (t + 16) % LSEQ;
        int p2p = u % 32;
        int jl  = (u + LSEQ - 17) % LSEQ;
        int jr  = (u + LSEQ - 15) % LSEQ;
        float4 L2 = (p2p > 0)                  ? *(const float4*)(base + (size_t)(1 + jl) * 512 + c) : z4;
        float4 R2 = (p2p < 31 && u + 1 < LSEQ) ? *(const float4*)(base + (size_t)(1 + jr) * 512 + c) : z4;
        o4.x = xc.x + (w0[0]*L1.x + w1[0]*xc.x + w2[0]*R1.x + bb.x)
                    + (w0[0]*L2.x + w1[0]*xc.x + w2[0]*R2.x + bb.x);
        o4.y = xc.y + (w0[1]*L1.y + w1[1]*xc.y + w2[1]*R1.y + bb.y)
                    + (w0[1]*L2.y + w1[1]*xc.y + w2[1]*R2.y + bb.y);
        o4.z = xc.z + (w0[2]*L1.z + w1[2]*xc.z + w2[2]*R1.z + bb.z)
                    + (w0[2]*L2.z + w1[2]*xc.z + w2[2]*R2.z + bb.z);
        o4.w = xc.w + (w0[3]*L1.w + w1[3]*xc.w + w2[3]*R1.w + bb.w)
                    + (w0[3]*L2.w + w1[3]*xc.w + w2[3]*R2.w + bb.w);
    }
    unsigned h0, l0, h1, l1;
    splitpk(o4.x, o4.y, h0, l0);
    splitpk(o4.z, o4.w, h1, l1);
    *(uint2*)(dh + doff) = make_uint2(h0, h1);
    *(uint2*)(dl + doff) = make_uint2(l0, l1);
}

// ---------------- flash attention, mma.sync bf16x3 + ldmatrix ---------------
#define KSTR 72
__global__ __launch_bounds__(256)
void attn_mma_kernel() {
    __shared__ __align__(16) __nv_bfloat16 Ks_hi[64 * KSTR];
    __shared__ __align__(16) __nv_bfloat16 Ks_lo[64 * KSTR];
    __shared__ __align__(16) __nv_bfloat16 Vs_hi[64 * KSTR];
    __shared__ __align__(16) __nv_bfloat16 Vs_lo[64 * KSTR];
    int tid = threadIdx.x;
    int w = tid >> 5, lane = tid & 31;
    int gq = lane >> 2, qq = lane & 3;
    int lt = lane >> 3, lr = lane & 7;
    int bh_ = blockIdx.y;
    int b = bh_ >> 3, h = bh_ & 7;
    int q0 = blockIdx.x * 128 + w * 16;

    unsigned qh[4][4], ql[4][4];
    {
        const float* qbase = g_q + ((size_t)b * NN + q0) * 512 + h * 64;
        #pragma unroll
        for (int kk = 0; kk < 4; kk++)
            #pragma unroll
            for (int cc = 0; cc < 2; cc++)
                #pragma unroll
                for (int rr = 0; rr < 2; rr++) {
                    int row = gq + rr * 8;
                    int dim = kk * 16 + cc * 8 + qq * 2;
                    float2 qv = *(const float2*)(qbase + (size_t)row * 512 + dim);
                    splitpk(qv.x * 0.125f, qv.y * 0.125f,
                            qh[kk][rr + 2 * cc], ql[kk][rr + 2 * cc]);
                }
    }

    float O[8][4];
    #pragma unroll
    for (int j = 0; j < 8; j++)
        #pragma unroll
        for (int c = 0; c < 4; c++) O[j][c] = 0.f;
    float rm0 = -1e30f, rm1 = -1e30f, rl0 = 0.f, rl1 = 0.f;

    const __nv_bfloat16* khb = g_kh + ((size_t)b * NK) * 512 + h * 64;
    const __nv_bfloat16* klb = g_kl + ((size_t)b * NK) * 512 + h * 64;
    const __nv_bfloat16* vhb = g_vh + ((size_t)b * NK) * 512 + h * 64;
    const __nv_bfloat16* vlb = g_vl + ((size_t)b * NK) * 512 + h * 64;

    for (int kt = 0; kt < NK; kt += 64) {
        #pragma unroll
        for (int i = 0; i < 2; i++) {
            int idx = tid + 256 * i;           // 512 slots
            int row = idx >> 3, e = idx & 7;   // key row, 8-dim chunk
            size_t goff = (size_t)(kt + row) * 512 + 8 * e;
            int soff = row * KSTR + 8 * e;
            *(uint4*)&Ks_hi[soff] = *(const uint4*)(khb + goff);
            *(uint4*)&Ks_lo[soff] = *(const uint4*)(klb + goff);
            *(uint4*)&Vs_hi[soff] = *(const uint4*)(vhb + goff);
            *(uint4*)&Vs_lo[soff] = *(const uint4*)(vlb + goff);
        }
        __syncthreads();

        float S[8][4];
        #pragma unroll
        for (int j = 0; j < 8; j++) {
            unsigned bhf[8], blf[8];
            int krow = (8 * j + lr) * KSTR;
            ldsm4(bhf,     su(&Ks_hi[krow + 8 * lt]));
            ldsm4(bhf + 4, su(&Ks_hi[krow + 32 + 8 * lt]));
            ldsm4(blf,     su(&Ks_lo[krow + 8 * lt]));
            ldsm4(blf + 4, su(&Ks_lo[krow + 32 + 8 * lt]));
            float c[4] = {0.f, 0.f, 0.f, 0.f};
            #pragma unroll
            for (int kk = 0; kk < 4; kk++) {
                mma16816(c, qh[kk], bhf[2 * kk], bhf[2 * kk + 1]);
                mma16816(c, ql[kk], bhf[2 * kk], bhf[2 * kk + 1]);
                mma16816(c, qh[kk], blf[2 * kk], blf[2 * kk + 1]);
            }
            S[j][0] = c[0]; S[j][1] = c[1]; S[j][2] = c[2]; S[j][3] = c[3];
        }

        float tm0 = -1e30f, tm1 = -1e30f;
        #pragma unroll
        for (int j = 0; j < 8; j++) {
            tm0 = fmaxf(tm0, fmaxf(S[j][0], S[j][1]));
            tm1 = fmaxf(tm1, fmaxf(S[j][2], S[j][3]));
        }
        tm0 = fmaxf(tm0, __shfl_xor_sync(0xffffffffu, tm0, 1));
        tm0 = fmaxf(tm0, __shfl_xor_sync(0xffffffffu, tm0, 2));
        tm1 = fmaxf(tm1, __shfl_xor_sync(0xffffffffu, tm1, 1));
        tm1 = fmaxf(tm1, __shfl_xor_sync(0xffffffffu, tm1, 2));
        float m0n = fmaxf(rm0, tm0), m1n = fmaxf(rm1, tm1);
        float cor0 = __expf(rm0 - m0n), cor1 = __expf(rm1 - m1n);
        rl0 *= cor0; rl1 *= cor1;
        #pragma unroll
        for (int j = 0; j < 8; j++) {
            O[j][0] *= cor0; O[j][1] *= cor0;
            O[j][2] *= cor1; O[j][3] *= cor1;
        }
        rm0 = m0n; rm1 = m1n;

        unsigned Ph[4][4], Pl[4][4];
        #pragma unroll
        for (int j = 0; j < 8; j++) {
            float p0 = __expf(S[j][0] - m0n);
            float p1 = __expf(S[j][1] - m0n);
            float p2 = __expf(S[j][2] - m1n);
            float p3 = __expf(S[j][3] - m1n);
            rl0 += p0 + p1; rl1 += p2 + p3;
            int kk2 = j >> 1, half = j & 1;
            splitpk(p0, p1, Ph[kk2][2 * half],     Pl[kk2][2 * half]);
            splitpk(p2, p3, Ph[kk2][2 * half + 1], Pl[kk2][2 * half + 1]);
        }

        #pragma unroll
        for (int jd = 0; jd < 8; jd++) {
            unsigned vhf[8], vlf[8];
            ldsm4t(vhf,     su(&Vs_hi[(8 * lt + lr) * KSTR + 8 * jd]));
            ldsm4t(vhf + 4, su(&Vs_hi[(32 + 8 * lt + lr) * KSTR + 8 * jd]));
            ldsm4t(vlf,     su(&Vs_lo[(8 * lt + lr) * KSTR + 8 * jd]));
            ldsm4t(vlf + 4, su(&Vs_lo[(32 + 8 * lt + lr) * KSTR + 8 * jd]));
            #pragma unroll
            for (int kk2 = 0; kk2 < 4; kk2++) {
                mma16816(O[jd], Ph[kk2], vhf[2 * kk2], vhf[2 * kk2 + 1]);
                mma16816(O[jd], Pl[kk2], vhf[2 * kk2], vhf[2 * kk2 + 1]);
                mma16816(O[jd], Ph[kk2], vlf[2 * kk2], vlf[2 * kk2 + 1]);
            }
        }
        __syncthreads();
    }

    float l0 = rl0, l1 = rl1;
    l0 += __shfl_xor_sync(0xffffffffu, l0, 1);
    l0 += __shfl_xor_sync(0xffffffffu, l0, 2);
    l1 += __shfl_xor_sync(0xffffffffu, l1, 1);
    l1 += __shfl_xor_sync(0xffffffffu, l1, 2);
    float inv0 = 1.0f / l0, inv1 = 1.0f / l1;
    size_t obase = ((size_t)b * NN + q0) * 512 + h * 64;
    #pragma unroll
    for (int jd = 0; jd < 8; jd++) {
        int dim = 8 * jd + qq * 2;
        unsigned h2, l2;
        splitpk(O[jd][0] * inv0, O[jd][1] * inv0, h2, l2);
        *(unsigned*)&g_ah[obase + (size_t)gq * 512 + dim] = h2;
        *(unsigned*)&g_al[obase + (size_t)gq * 512 + dim] = l2;
        splitpk(O[jd][2] * inv1, O[jd][3] * inv1, h2, l2);
        *(unsigned*)&g_ah[obase + (size_t)(gq + 8) * 512 + dim] = h2;
        *(unsigned*)&g_al[obase + (size_t)(gq + 8) * 512 + dim] = l2;
    }
}

// ---------------- launch ----------------------------------------------------
extern "C" void kernel_launch(void* const* d_in, const int* in_sizes, int n_in,
                              void* d_out, int out_size) {
    const float* x     = (const float*)d_in[0];
    const float* mem   = (const float*)d_in[1];
    const float* ln_g  = (const float*)d_in[2];
    const float* ln_b  = (const float*)d_in[3];
    const float* w_qkv = (const float*)d_in[4];
    const float* w_out = (const float*)d_in[5];
    const float* b_out = (const float*)d_in[6];
    const float* pk_w  = (const float*)d_in[7];
    const float* pk_b  = (const float*)d_in[8];
    const float* pv_w  = (const float*)d_in[9];
    const float* pv_b  = (const float*)d_in[10];
    float* out = (float*)d_out;

    __nv_bfloat16 *wqh, *wql, *woh, *wol;
    cudaGetSymbolAddress((void**)&wqh, g_wqh);
    cudaGetSymbolAddress((void**)&wql, g_wql);
    cudaGetSymbolAddress((void**)&woh, g_woh);
    cudaGetSymbolAddress((void**)&wol, g_wol);

    split_kernel<<<(DD * 3 * DD / 4 + 255) / 256, 256>>>(w_qkv, wqh, wql, DD * 3 * DD / 4);
    split_kernel<<<(DD * DD / 4 + 255) / 256, 256>>>(w_out, woh, wol, DD * DD / 4);
    ln_kernel<<<BB * NN, 128>>>(x, ln_g, ln_b);
    mma_gemm_kernel<<<dim3(1536 / 64, (BB * NN) / 128), 256>>>(wqh, wql, nullptr, nullptr, 1536, 0);
    copy_mem_kernel<<<(BB * MM * 512 / 4 + 255) / 256, 256>>>(mem);
    peg_kernel<<<BB * NK, 128>>>(pk_w, pk_b, 0);
    peg_kernel<<<BB * NK, 128>>>(pv_w, pv_b, 1);
    attn_mma_kernel<<<dim3(NN / 128, BB * HH), 256>>>();
    mma_gemm_kernel<<<dim3(512 / 64, (BB * NN) / 128), 256>>>(woh, wol, b_out, out, 512, 1);
}

// round 6
// speedup vs baseline: 10.4664x; 1.3597x over previous
#include <cuda_runtime.h>
#include <cuda_fp16.h>
#include <cstring>

#define BB 2
#define NN 4096
#define DD 512
#define HH 8
#define DH 64
#define MM 1024
#define NK 5120          // NN + MM
#define LSEQ 5119        // NK - 1

// ---------------- fp16 split + mma + ldmatrix helpers -----------------------
__device__ __forceinline__ void splitpk(float x, float y, unsigned &hi, unsigned &lo) {
    __half2 h = __floats2half2_rn(x, y);
    float hx = __low2float(h), hy = __high2float(h);
    __half2 l = __floats2half2_rn(x - hx, y - hy);
    memcpy(&hi, &h, 4); memcpy(&lo, &l, 4);
}
__device__ __forceinline__ unsigned rnd2(float x, float y) {
    __half2 h = __floats2half2_rn(x, y);
    unsigned u; memcpy(&u, &h, 4); return u;
}
__device__ __forceinline__ void mma16816(float c[4], const unsigned a[4],
                                         unsigned b0, unsigned b1) {
    asm("mma.sync.aligned.m16n8k16.row.col.f32.f16.f16.f32 "
        "{%0,%1,%2,%3},{%4,%5,%6,%7},{%8,%9},{%0,%1,%2,%3};"
        : "+f"(c[0]), "+f"(c[1]), "+f"(c[2]), "+f"(c[3])
        : "r"(a[0]), "r"(a[1]), "r"(a[2]), "r"(a[3]), "r"(b0), "r"(b1));
}
__device__ __forceinline__ unsigned su(const void* p) {
    return (unsigned)__cvta_generic_to_shared(p);
}
__device__ __forceinline__ void ldsm4(unsigned* r, unsigned addr) {
    asm volatile("ldmatrix.sync.aligned.m8n8.x4.shared.b16 {%0,%1,%2,%3}, [%4];"
                 : "=r"(r[0]), "=r"(r[1]), "=r"(r[2]), "=r"(r[3]) : "r"(addr));
}
__device__ __forceinline__ void ldsm4t(unsigned* r, unsigned addr) {
    asm volatile("ldmatrix.sync.aligned.m8n8.x4.trans.shared.b16 {%0,%1,%2,%3}, [%4];"
                 : "=r"(r[0]), "=r"(r[1]), "=r"(r[2]), "=r"(r[3]) : "r"(addr));
}

// ---------------- scratch ----------------------------------------------------
__device__ __half g_xh[BB * NN * DD];    // LN out hi
__device__ __half g_xl[BB * NN * DD];    // LN out lo
__device__ float  g_q [BB * NN * DD];
__device__ float  g_k [BB * NK * DD];
__device__ float  g_v [BB * NK * DD];
__device__ __half g_kf[BB * NK * DD];    // post-PEG K (fp16 rounded)
__device__ __half g_vf[BB * NK * DD];    // post-PEG V (fp16 rounded)
__device__ __half g_ah[BB * NN * DD];    // attention out hi
__device__ __half g_al[BB * NN * DD];    // attention out lo
__device__ __half g_wqh[DD * 3 * DD];
__device__ __half g_wql[DD * 3 * DD];
__device__ __half g_woh[DD * DD];
__device__ __half g_wol[DD * DD];

// ---------------- fp32 -> fp16 hi/lo splitter (weights) ---------------------
__global__ void split_kernel(const float* __restrict__ src,
                             __half* __restrict__ hi,
                             __half* __restrict__ lo, int n4) {
    int i = blockIdx.x * 256 + threadIdx.x;
    if (i >= n4) return;
    float4 v = ((const float4*)src)[i];
    unsigned h0, l0, h1, l1;
    splitpk(v.x, v.y, h0, l0);
    splitpk(v.z, v.w, h1, l1);
    ((uint2*)hi)[i] = make_uint2(h0, h1);
    ((uint2*)lo)[i] = make_uint2(l0, l1);
}

// ---------------- LayerNorm (writes hi/lo fp16) ------------------------------
__global__ void ln_kernel(const float* __restrict__ x,
                          const float* __restrict__ g,
                          const float* __restrict__ bt) {
    int row = blockIdx.x;
    int t = threadIdx.x;
    const float4* xr = (const float4*)(x + (size_t)row * DD);
    float4 v = xr[t];
    float s  = v.x + v.y + v.z + v.w;
    float s2 = v.x*v.x + v.y*v.y + v.z*v.z + v.w*v.w;
    #pragma unroll
    for (int o = 16; o > 0; o >>= 1) {
        s  += __shfl_xor_sync(0xffffffffu, s,  o);
        s2 += __shfl_xor_sync(0xffffffffu, s2, o);
    }
    __shared__ float a1[4], a2[4];
    int w = t >> 5;
    if ((t & 31) == 0) { a1[w] = s; a2[w] = s2; }
    __syncthreads();
    s  = a1[0] + a1[1] + a1[2] + a1[3];
    s2 = a2[0] + a2[1] + a2[2] + a2[3];
    float mu  = s * (1.0f / 512.0f);
    float var = s2 * (1.0f / 512.0f) - mu * mu;
    float rs  = rsqrtf(var + 1e-5f);
    float4 gg = ((const float4*)g)[t];
    float4 bb = ((const float4*)bt)[t];
    float4 o4;
    o4.x = (v.x - mu) * rs * gg.x + bb.x;
    o4.y = (v.y - mu) * rs * gg.y + bb.y;
    o4.z = (v.z - mu) * rs * gg.z + bb.z;
    o4.w = (v.w - mu) * rs * gg.w + bb.w;
    unsigned h0, l0, h1, l1;
    splitpk(o4.x, o4.y, h0, l0);
    splitpk(o4.z, o4.w, h1, l1);
    ((uint2*)(g_xh + (size_t)row * DD))[t] = make_uint2(h0, h1);
    ((uint2*)(g_xl + (size_t)row * DD))[t] = make_uint2(l0, l1);
}

// ---------------- fp16x3 mma GEMM with ldmatrix -----------------------------
#define WSTR 72
__global__ __launch_bounds__(256)
void mma_gemm_kernel(const __half* __restrict__ Wh,
                     const __half* __restrict__ Wl,
                     const float* __restrict__ bias,
                     float* __restrict__ dout, int cn, int mode) {
    const __half* Ah = mode ? g_ah : g_xh;
    const __half* Al = mode ? g_al : g_xl;
    __shared__ __align__(16) __half sAh[128 * 40];
    __shared__ __align__(16) __half sAl[128 * 40];
    __shared__ __align__(16) __half sWh[32 * WSTR];
    __shared__ __align__(16) __half sWl[32 * WSTR];
    int tid = threadIdx.x, w = tid >> 5, lane = tid & 31;
    int gq = lane >> 2, qq = lane & 3;
    int lt = lane >> 3, lr = lane & 7;
    int row0 = blockIdx.y * 128, col0 = blockIdx.x * 64;
    int wm = w >> 1, wn = w & 1;
    float acc[2][4][4];
    #pragma unroll
    for (int mf = 0; mf < 2; mf++)
        #pragma unroll
        for (int nf = 0; nf < 4; nf++)
            #pragma unroll
            for (int c = 0; c < 4; c++) acc[mf][nf][c] = 0.f;

    for (int kt = 0; kt < 512; kt += 32) {
        #pragma unroll
        for (int i = 0; i < 2; i++) {
            int idx = tid + 256 * i;
            int r = idx >> 2, e = idx & 3;
            *(uint4*)&sAh[r * 40 + 8 * e] =
                *(const uint4*)(Ah + (size_t)(row0 + r) * 512 + kt + 8 * e);
            *(uint4*)&sAl[r * 40 + 8 * e] =
                *(const uint4*)(Al + (size_t)(row0 + r) * 512 + kt + 8 * e);
        }
        {
            int r = tid >> 3, e = tid & 7;
            *(uint4*)&sWh[r * WSTR + 8 * e] =
                *(const uint4*)(Wh + (size_t)(kt + r) * cn + col0 + 8 * e);
            *(uint4*)&sWl[r * WSTR + 8 * e] =
                *(const uint4*)(Wl + (size_t)(kt + r) * cn + col0 + 8 * e);
        }
        __syncthreads();
        #pragma unroll
        for (int ks = 0; ks < 2; ks++) {
            int k0 = ks * 16;
            unsigned ah[2][4], al[2][4];
            #pragma unroll
            for (int mf = 0; mf < 2; mf++) {
                int ar = wm * 32 + mf * 16 + (lt & 1) * 8 + lr;
                int ak = k0 + (lt >> 1) * 8;
                ldsm4(ah[mf], su(&sAh[ar * 40 + ak]));
                ldsm4(al[mf], su(&sAl[ar * 40 + ak]));
            }
            unsigned bh[2][4], bl[2][4];
            #pragma unroll
            for (int nh = 0; nh < 2; nh++) {
                int br = k0 + (lt & 1) * 8 + lr;
                int bc = wn * 32 + nh * 16 + (lt >> 1) * 8;
                ldsm4t(bh[nh], su(&sWh[br * WSTR + bc]));
                ldsm4t(bl[nh], su(&sWl[br * WSTR + bc]));
            }
            #pragma unroll
            for (int nf = 0; nf < 4; nf++) {
                unsigned bh0 = bh[nf >> 1][(nf & 1) * 2];
                unsigned bh1 = bh[nf >> 1][(nf & 1) * 2 + 1];
                unsigned bl0 = bl[nf >> 1][(nf & 1) * 2];
                unsigned bl1 = bl[nf >> 1][(nf & 1) * 2 + 1];
                #pragma unroll
                for (int mf = 0; mf < 2; mf++) {
                    mma16816(acc[mf][nf], ah[mf], bh0, bh1);
                    mma16816(acc[mf][nf], al[mf], bh0, bh1);
                    mma16816(acc[mf][nf], ah[mf], bl0, bl1);
                }
            }
        }
        __syncthreads();
    }
    #pragma unroll
    for (int mf = 0; mf < 2; mf++) {
        int rlo = row0 + wm * 32 + mf * 16 + gq;
        #pragma unroll
        for (int nf = 0; nf < 4; nf++) {
            int cl = col0 + wn * 32 + nf * 8 + 2 * qq;
            float* c = acc[mf][nf];
            if (mode == 0) {
                #pragma unroll
                for (int half_ = 0; half_ < 2; half_++) {
                    int rr = rlo + half_ * 8;
                    int b = rr >> 12, n = rr & 4095;
                    #pragma unroll
                    for (int j = 0; j < 2; j++) {
                        int cc = cl + j;
                        int sel = cc >> 9, c5 = cc & 511;
                        float vv = c[2 * half_ + j];
                        if (sel == 0)      g_q[((size_t)b * NN + n) * 512 + c5] = vv;
                        else if (sel == 1) g_k[((size_t)b * NK + n) * 512 + c5] = vv;
                        else               g_v[((size_t)b * NK + n) * 512 + c5] = vv;
                    }
                }
            } else {
                float2 bq = *(const float2*)(bias + cl);
                float2 o0; o0.x = c[0] + bq.x; o0.y = c[1] + bq.y;
                float2 o1; o1.x = c[2] + bq.x; o1.y = c[3] + bq.y;
                *(float2*)(dout + (size_t)rlo * 512 + cl)       = o0;
                *(float2*)(dout + (size_t)(rlo + 8) * 512 + cl) = o1;
            }
        }
    }
}

// ---------------- append mem rows to k and v tails --------------------------
__global__ void copy_mem_kernel(const float* __restrict__ mem) {
    int i = blockIdx.x * blockDim.x + threadIdx.x;
    if (i >= BB * MM * 512 / 4) return;
    float4 v = ((const float4*)mem)[i];
    int gi = i << 2;
    int b = gi / (MM * 512);
    int rem = gi - b * (MM * 512);
    size_t off = ((size_t)b * NK + NN) * 512 + rem;
    *(float4*)(g_k + off) = v;
    *(float4*)(g_v + off) = v;
}

// ---------------- PEG1D depthwise conv -> rounded fp16 ----------------------
__global__ void peg_kernel(const float* __restrict__ w,
                           const float* __restrict__ bias, int which) {
    const float* src = which ? g_v : g_k;
    __half* df = which ? g_vf : g_kf;
    int gr = blockIdx.x;
    int b = gr / NK, r = gr - b * NK;
    int c = threadIdx.x << 2;
    const float* base = src + (size_t)b * NK * 512;
    float4 xc = *(const float4*)(base + (size_t)r * 512 + c);
    size_t doff = ((size_t)b * NK + r) * 512 + c;
    float4 o4;
    if (r == 0) {
        o4 = xc;
    } else {
        int t = r - 1;
        float w0[4], w1[4], w2[4];
        #pragma unroll
        for (int j = 0; j < 4; j++) {
            w0[j] = __ldg(w + (c + j) * 3 + 0);
            w1[j] = __ldg(w + (c + j) * 3 + 1);
            w2[j] = __ldg(w + (c + j) * 3 + 2);
        }
        float4 bb = *(const float4*)(bias + c);
        const float4 z4 = make_float4(0.f, 0.f, 0.f, 0.f);
        int p = t & 31;
        float4 L1 = (p > 0)                 ? *(const float4*)(base + (size_t)r * 512 - 512 + c) : z4;
        float4 R1 = (p < 31 && t + 1 < LSEQ)? *(const float4*)(base + (size_t)r * 512 + 512 + c) : z4;
        int u   = (t + 16) % LSEQ;
        int p2p = u % 32;
        int jl  = (u + LSEQ - 17) % LSEQ;
        int jr  = (u + LSEQ - 15) % LSEQ;
        float4 L2 = (p2p > 0)                  ? *(const float4*)(base + (size_t)(1 + jl) * 512 + c) : z4;
        float4 R2 = (p2p < 31 && u + 1 < LSEQ) ? *(const float4*)(base + (size_t)(1 + jr) * 512 + c) : z4;
        o4.x = xc.x + (w0[0]*L1.x + w1[0]*xc.x + w2[0]*R1.x + bb.x)
                    + (w0[0]*L2.x + w1[0]*xc.x + w2[0]*R2.x + bb.x);
        o4.y = xc.y + (w0[1]*L1.y + w1[1]*xc.y + w2[1]*R1.y + bb.y)
                    + (w0[1]*L2.y + w1[1]*xc.y + w2[1]*R2.y + bb.y);
        o4.z = xc.z + (w0[2]*L1.z + w1[2]*xc.z + w2[2]*R1.z + bb.z)
                    + (w0[2]*L2.z + w1[2]*xc.z + w2[2]*R2.z + bb.z);
        o4.w = xc.w + (w0[3]*L1.w + w1[3]*xc.w + w2[3]*R1.w + bb.w)
                    + (w0[3]*L2.w + w1[3]*xc.w + w2[3]*R2.w + bb.w);
    }
    *(uint2*)(df + doff) = make_uint2(rnd2(o4.x, o4.y), rnd2(o4.z, o4.w));
}

// ---------------- flash attention, fp16x2 mma + ldmatrix --------------------
#define KSTR 72
__global__ __launch_bounds__(256)
void attn_mma_kernel() {
    __shared__ __align__(16) __half Ks[64 * KSTR];
    __shared__ __align__(16) __half Vs[64 * KSTR];
    int tid = threadIdx.x;
    int w = tid >> 5, lane = tid & 31;
    int gq = lane >> 2, qq = lane & 3;
    int lt = lane >> 3, lr = lane & 7;
    int bh_ = blockIdx.y;
    int b = bh_ >> 3, h = bh_ & 7;
    int q0 = blockIdx.x * 128 + w * 16;

    unsigned qh[4][4], ql[4][4];
    {
        const float* qbase = g_q + ((size_t)b * NN + q0) * 512 + h * 64;
        #pragma unroll
        for (int kk = 0; kk < 4; kk++)
            #pragma unroll
            for (int cc = 0; cc < 2; cc++)
                #pragma unroll
                for (int rr = 0; rr < 2; rr++) {
                    int row = gq + rr * 8;
                    int dim = kk * 16 + cc * 8 + qq * 2;
                    float2 qv = *(const float2*)(qbase + (size_t)row * 512 + dim);
                    splitpk(qv.x * 0.125f, qv.y * 0.125f,
                            qh[kk][rr + 2 * cc], ql[kk][rr + 2 * cc]);
                }
    }

    float O[8][4];
    #pragma unroll
    for (int j = 0; j < 8; j++)
        #pragma unroll
        for (int c = 0; c < 4; c++) O[j][c] = 0.f;
    float rm0 = -1e30f, rm1 = -1e30f, rl0 = 0.f, rl1 = 0.f;

    const __half* kfb = g_kf + ((size_t)b * NK) * 512 + h * 64;
    const __half* vfb = g_vf + ((size_t)b * NK) * 512 + h * 64;

    for (int kt = 0; kt < NK; kt += 64) {
        #pragma unroll
        for (int i = 0; i < 2; i++) {
            int idx = tid + 256 * i;
            int row = idx >> 3, e = idx & 7;
            size_t goff = (size_t)(kt + row) * 512 + 8 * e;
            int soff = row * KSTR + 8 * e;
            *(uint4*)&Ks[soff] = *(const uint4*)(kfb + goff);
            *(uint4*)&Vs[soff] = *(const uint4*)(vfb + goff);
        }
        __syncthreads();

        float S[8][4];
        #pragma unroll
        for (int j = 0; j < 8; j++) {
            unsigned bf[8];
            int krow = (8 * j + lr) * KSTR;
            ldsm4(bf,     su(&Ks[krow + 8 * lt]));
            ldsm4(bf + 4, su(&Ks[krow + 32 + 8 * lt]));
            float c[4] = {0.f, 0.f, 0.f, 0.f};
            #pragma unroll
            for (int kk = 0; kk < 4; kk++) {
                mma16816(c, qh[kk], bf[2 * kk], bf[2 * kk + 1]);
                mma16816(c, ql[kk], bf[2 * kk], bf[2 * kk + 1]);
            }
            S[j][0] = c[0]; S[j][1] = c[1]; S[j][2] = c[2]; S[j][3] = c[3];
        }

        float tm0 = -1e30f, tm1 = -1e30f;
        #pragma unroll
        for (int j = 0; j < 8; j++) {
            tm0 = fmaxf(tm0, fmaxf(S[j][0], S[j][1]));
            tm1 = fmaxf(tm1, fmaxf(S[j][2], S[j][3]));
        }
        tm0 = fmaxf(tm0, __shfl_xor_sync(0xffffffffu, tm0, 1));
        tm0 = fmaxf(tm0, __shfl_xor_sync(0xffffffffu, tm0, 2));
        tm1 = fmaxf(tm1, __shfl_xor_sync(0xffffffffu, tm1, 1));
        tm1 = fmaxf(tm1, __shfl_xor_sync(0xffffffffu, tm1, 2));
        float m0n = fmaxf(rm0, tm0), m1n = fmaxf(rm1, tm1);
        float cor0 = __expf(rm0 - m0n), cor1 = __expf(rm1 - m1n);
        rl0 *= cor0; rl1 *= cor1;
        #pragma unroll
        for (int j = 0; j < 8; j++) {
            O[j][0] *= cor0; O[j][1] *= cor0;
            O[j][2] *= cor1; O[j][3] *= cor1;
        }
        rm0 = m0n; rm1 = m1n;

        unsigned Ph[4][4], Pl[4][4];
        #pragma unroll
        for (int j = 0; j < 8; j++) {
            float p0 = __expf(S[j][0] - m0n);
            float p1 = __expf(S[j][1] - m0n);
            float p2 = __expf(S[j][2] - m1n);
            float p3 = __expf(S[j][3] - m1n);
            rl0 += p0 + p1; rl1 += p2 + p3;
            int kk2 = j >> 1, half_ = j & 1;
            splitpk(p0, p1, Ph[kk2][2 * half_],     Pl[kk2][2 * half_]);
            splitpk(p2, p3, Ph[kk2][2 * half_ + 1], Pl[kk2][2 * half_ + 1]);
        }

        #pragma unroll
        for (int jd = 0; jd < 8; jd++) {
            unsigned vf[8];
            ldsm4t(vf,     su(&Vs[(8 * lt + lr) * KSTR + 8 * jd]));
            ldsm4t(vf + 4, su(&Vs[(32 + 8 * lt + lr) * KSTR + 8 * jd]));
            #pragma unroll
            for (int kk2 = 0; kk2 < 4; kk2++) {
                mma16816(O[jd], Ph[kk2], vf[2 * kk2], vf[2 * kk2 + 1]);
                mma16816(O[jd], Pl[kk2], vf[2 * kk2], vf[2 * kk2 + 1]);
            }
        }
        __syncthreads();
    }

    float l0 = rl0, l1 = rl1;
    l0 += __shfl_xor_sync(0xffffffffu, l0, 1);
    l0 += __shfl_xor_sync(0xffffffffu, l0, 2);
    l1 += __shfl_xor_sync(0xffffffffu, l1, 1);
    l1 += __shfl_xor_sync(0xffffffffu, l1, 2);
    float inv0 = 1.0f / l0, inv1 = 1.0f / l1;
    size_t obase = ((size_t)b * NN + q0) * 512 + h * 64;
    #pragma unroll
    for (int jd = 0; jd < 8; jd++) {
        int dim = 8 * jd + qq * 2;
        unsigned h2, l2;
        splitpk(O[jd][0] * inv0, O[jd][1] * inv0, h2, l2);
        *(unsigned*)&g_ah[obase + (size_t)gq * 512 + dim] = h2;
        *(unsigned*)&g_al[obase + (size_t)gq * 512 + dim] = l2;
        splitpk(O[jd][2] * inv1, O[jd][3] * inv1, h2, l2);
        *(unsigned*)&g_ah[obase + (size_t)(gq + 8) * 512 + dim] = h2;
        *(unsigned*)&g_al[obase + (size_t)(gq + 8) * 512 + dim] = l2;
    }
}

// ---------------- launch ----------------------------------------------------
extern "C" void kernel_launch(void* const* d_in, const int* in_sizes, int n_in,
                              void* d_out, int out_size) {
    const float* x     = (const float*)d_in[0];
    const float* mem   = (const float*)d_in[1];
    const float* ln_g  = (const float*)d_in[2];
    const float* ln_b  = (const float*)d_in[3];
    const float* w_qkv = (const float*)d_in[4];
    const float* w_out = (const float*)d_in[5];
    const float* b_out = (const float*)d_in[6];
    const float* pk_w  = (const float*)d_in[7];
    const float* pk_b  = (const float*)d_in[8];
    const float* pv_w  = (const float*)d_in[9];
    const float* pv_b  = (const float*)d_in[10];
    float* out = (float*)d_out;

    __half *wqh, *wql, *woh, *wol;
    cudaGetSymbolAddress((void**)&wqh, g_wqh);
    cudaGetSymbolAddress((void**)&wql, g_wql);
    cudaGetSymbolAddress((void**)&woh, g_woh);
    cudaGetSymbolAddress((void**)&wol, g_wol);

    split_kernel<<<(DD * 3 * DD / 4 + 255) / 256, 256>>>(w_qkv, wqh, wql, DD * 3 * DD / 4);
    split_kernel<<<(DD * DD / 4 + 255) / 256, 256>>>(w_out, woh, wol, DD * DD / 4);
    ln_kernel<<<BB * NN, 128>>>(x, ln_g, ln_b);
    mma_gemm_kernel<<<dim3(1536 / 64, (BB * NN) / 128), 256>>>(wqh, wql, nullptr, nullptr, 1536, 0);
    copy_mem_kernel<<<(BB * MM * 512 / 4 + 255) / 256, 256>>>(mem);
    peg_kernel<<<BB * NK, 128>>>(pk_w, pk_b, 0);
    peg_kernel<<<BB * NK, 128>>>(pv_w, pv_b, 1);
    attn_mma_kernel<<<dim3(NN / 128, BB * HH), 256>>>();
    mma_gemm_kernel<<<dim3(512 / 64, (BB * NN) / 128), 256>>>(woh, wol, b_out, out, 512, 1);
}

// round 7
// speedup vs baseline: 11.5592x; 1.1044x over previous
#include <cuda_runtime.h>
#include <cuda_fp16.h>
#include <cstring>

#define BB 2
#define NN 4096
#define DD 512
#define HH 8
#define DH 64
#define MM 1024
#define NK 5120          // NN + MM
#define LSEQ 5119        // NK - 1

// ---------------- fp16 split + mma + ldmatrix + cp.async helpers ------------
__device__ __forceinline__ void splitpk(float x, float y, unsigned &hi, unsigned &lo) {
    __half2 h = __floats2half2_rn(x, y);
    float hx = __low2float(h), hy = __high2float(h);
    __half2 l = __floats2half2_rn(x - hx, y - hy);
    memcpy(&hi, &h, 4); memcpy(&lo, &l, 4);
}
__device__ __forceinline__ unsigned rnd2(float x, float y) {
    __half2 h = __floats2half2_rn(x, y);
    unsigned u; memcpy(&u, &h, 4); return u;
}
__device__ __forceinline__ void mma16816(float c[4], const unsigned a[4],
                                         unsigned b0, unsigned b1) {
    asm("mma.sync.aligned.m16n8k16.row.col.f32.f16.f16.f32 "
        "{%0,%1,%2,%3},{%4,%5,%6,%7},{%8,%9},{%0,%1,%2,%3};"
        : "+f"(c[0]), "+f"(c[1]), "+f"(c[2]), "+f"(c[3])
        : "r"(a[0]), "r"(a[1]), "r"(a[2]), "r"(a[3]), "r"(b0), "r"(b1));
}
__device__ __forceinline__ unsigned su(const void* p) {
    return (unsigned)__cvta_generic_to_shared(p);
}
__device__ __forceinline__ void ldsm4(unsigned* r, unsigned addr) {
    asm volatile("ldmatrix.sync.aligned.m8n8.x4.shared.b16 {%0,%1,%2,%3}, [%4];"
                 : "=r"(r[0]), "=r"(r[1]), "=r"(r[2]), "=r"(r[3]) : "r"(addr));
}
__device__ __forceinline__ void ldsm4t(unsigned* r, unsigned addr) {
    asm volatile("ldmatrix.sync.aligned.m8n8.x4.trans.shared.b16 {%0,%1,%2,%3}, [%4];"
                 : "=r"(r[0]), "=r"(r[1]), "=r"(r[2]), "=r"(r[3]) : "r"(addr));
}
__device__ __forceinline__ void cpa16(void* s, const void* g) {
    asm volatile("cp.async.cg.shared.global [%0], [%1], 16;" :: "r"(su(s)), "l"(g));
}
__device__ __forceinline__ void cp_commit() { asm volatile("cp.async.commit_group;"); }
__device__ __forceinline__ void cp_wait1()  { asm volatile("cp.async.wait_group 1;"); }
__device__ __forceinline__ void cp_wait0()  { asm volatile("cp.async.wait_group 0;"); }

// ---------------- scratch ----------------------------------------------------
__device__ __half g_xh[BB * NN * DD];
__device__ __half g_xl[BB * NN * DD];
__device__ float  g_q [BB * NN * DD];
__device__ float  g_k [BB * NK * DD];
__device__ float  g_v [BB * NK * DD];
__device__ __half g_kf[BB * NK * DD];
__device__ __half g_vf[BB * NK * DD];
__device__ __half g_ah[BB * NN * DD];
__device__ __half g_al[BB * NN * DD];
__device__ __half g_wqh[DD * 3 * DD];
__device__ __half g_wql[DD * 3 * DD];
__device__ __half g_woh[DD * DD];
__device__ __half g_wol[DD * DD];

// ---------------- fp32 -> fp16 hi/lo splitter (weights) ---------------------
__global__ void split_kernel(const float* __restrict__ src,
                             __half* __restrict__ hi,
                             __half* __restrict__ lo, int n4) {
    int i = blockIdx.x * 256 + threadIdx.x;
    if (i >= n4) return;
    float4 v = ((const float4*)src)[i];
    unsigned h0, l0, h1, l1;
    splitpk(v.x, v.y, h0, l0);
    splitpk(v.z, v.w, h1, l1);
    ((uint2*)hi)[i] = make_uint2(h0, h1);
    ((uint2*)lo)[i] = make_uint2(l0, l1);
}

// ---------------- LayerNorm (writes hi/lo fp16) ------------------------------
__global__ void ln_kernel(const float* __restrict__ x,
                          const float* __restrict__ g,
                          const float* __restrict__ bt) {
    int row = blockIdx.x;
    int t = threadIdx.x;
    const float4* xr = (const float4*)(x + (size_t)row * DD);
    float4 v = xr[t];
    float s  = v.x + v.y + v.z + v.w;
    float s2 = v.x*v.x + v.y*v.y + v.z*v.z + v.w*v.w;
    #pragma unroll
    for (int o = 16; o > 0; o >>= 1) {
        s  += __shfl_xor_sync(0xffffffffu, s,  o);
        s2 += __shfl_xor_sync(0xffffffffu, s2, o);
    }
    __shared__ float a1[4], a2[4];
    int w = t >> 5;
    if ((t & 31) == 0) { a1[w] = s; a2[w] = s2; }
    __syncthreads();
    s  = a1[0] + a1[1] + a1[2] + a1[3];
    s2 = a2[0] + a2[1] + a2[2] + a2[3];
    float mu  = s * (1.0f / 512.0f);
    float var = s2 * (1.0f / 512.0f) - mu * mu;
    float rs  = rsqrtf(var + 1e-5f);
    float4 gg = ((const float4*)g)[t];
    float4 bb = ((const float4*)bt)[t];
    float4 o4;
    o4.x = (v.x - mu) * rs * gg.x + bb.x;
    o4.y = (v.y - mu) * rs * gg.y + bb.y;
    o4.z = (v.z - mu) * rs * gg.z + bb.z;
    o4.w = (v.w - mu) * rs * gg.w + bb.w;
    unsigned h0, l0, h1, l1;
    splitpk(o4.x, o4.y, h0, l0);
    splitpk(o4.z, o4.w, h1, l1);
    ((uint2*)(g_xh + (size_t)row * DD))[t] = make_uint2(h0, h1);
    ((uint2*)(g_xl + (size_t)row * DD))[t] = make_uint2(l0, l1);
}

// ---------------- fp16x3 mma GEMM, 2-stage cp.async pipeline ----------------
// block 128x64, 8 warps (4m x 2n), k-step 16 per stage.
#define ASTR 24
#define WSTR 72
__global__ __launch_bounds__(256)
void mma_gemm_kernel(const __half* __restrict__ Wh,
                     const __half* __restrict__ Wl,
                     const float* __restrict__ bias,
                     float* __restrict__ dout, int cn, int mode) {
    const __half* Ah = mode ? g_ah : g_xh;
    const __half* Al = mode ? g_al : g_xl;
    __shared__ __align__(16) __half sAh[2][128 * ASTR];
    __shared__ __align__(16) __half sAl[2][128 * ASTR];
    __shared__ __align__(16) __half sWh[2][16 * WSTR];
    __shared__ __align__(16) __half sWl[2][16 * WSTR];
    int tid = threadIdx.x, w = tid >> 5, lane = tid & 31;
    int gq = lane >> 2, qq = lane & 3;
    int lt = lane >> 3, lr = lane & 7;
    int row0 = blockIdx.y * 128, col0 = blockIdx.x * 64;
    int wm = w >> 1, wn = w & 1;
    float acc[2][4][4];
    #pragma unroll
    for (int mf = 0; mf < 2; mf++)
        #pragma unroll
        for (int nf = 0; nf < 4; nf++)
            #pragma unroll
            for (int c = 0; c < 4; c++) acc[mf][nf][c] = 0.f;

    // tile loader: k-tile index t (16 k-rows), stage s
    auto load_tile = [&](int t, int s) {
        int kt = t * 16;
        {
            int r = tid >> 1, e = tid & 1;      // 128 rows x 2 chunks (hi)
            const __half* gp = Ah + (size_t)(row0 + r) * 512 + kt + 8 * e;
            cpa16(&sAh[s][r * ASTR + 8 * e], gp);
            const __half* gl = Al + (size_t)(row0 + r) * 512 + kt + 8 * e;
            cpa16(&sAl[s][r * ASTR + 8 * e], gl);
        }
        if (tid < 128) {
            int r = tid >> 3, e = tid & 7;      // 16 k-rows x 8 chunks
            cpa16(&sWh[s][r * WSTR + 8 * e],
                  Wh + (size_t)(kt + r) * cn + col0 + 8 * e);
            cpa16(&sWl[s][r * WSTR + 8 * e],
                  Wl + (size_t)(kt + r) * cn + col0 + 8 * e);
        }
        cp_commit();
    };

    load_tile(0, 0);
    for (int t = 0; t < 32; t++) {
        int s = t & 1;
        if (t + 1 < 32) load_tile(t + 1, (t + 1) & 1);
        if (t + 1 < 32) cp_wait1(); else cp_wait0();
        __syncthreads();
        unsigned ah[2][4], al[2][4];
        #pragma unroll
        for (int mf = 0; mf < 2; mf++) {
            int ar = wm * 32 + mf * 16 + (lt & 1) * 8 + lr;
            int ak = (lt >> 1) * 8;
            ldsm4(ah[mf], su(&sAh[s][ar * ASTR + ak]));
            ldsm4(al[mf], su(&sAl[s][ar * ASTR + ak]));
        }
        unsigned bh[2][4], bl[2][4];
        #pragma unroll
        for (int nh = 0; nh < 2; nh++) {
            int br = (lt & 1) * 8 + lr;
            int bc = wn * 32 + nh * 16 + (lt >> 1) * 8;
            ldsm4t(bh[nh], su(&sWh[s][br * WSTR + bc]));
            ldsm4t(bl[nh], su(&sWl[s][br * WSTR + bc]));
        }
        #pragma unroll
        for (int nf = 0; nf < 4; nf++) {
            unsigned bh0 = bh[nf >> 1][(nf & 1) * 2];
            unsigned bh1 = bh[nf >> 1][(nf & 1) * 2 + 1];
            unsigned bl0 = bl[nf >> 1][(nf & 1) * 2];
            unsigned bl1 = bl[nf >> 1][(nf & 1) * 2 + 1];
            #pragma unroll
            for (int mf = 0; mf < 2; mf++) {
                mma16816(acc[mf][nf], ah[mf], bh0, bh1);
                mma16816(acc[mf][nf], al[mf], bh0, bh1);
                mma16816(acc[mf][nf], ah[mf], bl0, bl1);
            }
        }
        __syncthreads();
    }
    #pragma unroll
    for (int mf = 0; mf < 2; mf++) {
        int rlo = row0 + wm * 32 + mf * 16 + gq;
        #pragma unroll
        for (int nf = 0; nf < 4; nf++) {
            int cl = col0 + wn * 32 + nf * 8 + 2 * qq;
            float* c = acc[mf][nf];
            if (mode == 0) {
                #pragma unroll
                for (int half_ = 0; half_ < 2; half_++) {
                    int rr = rlo + half_ * 8;
                    int b = rr >> 12, n = rr & 4095;
                    #pragma unroll
                    for (int j = 0; j < 2; j++) {
                        int cc = cl + j;
                        int sel = cc >> 9, c5 = cc & 511;
                        float vv = c[2 * half_ + j];
                        if (sel == 0)      g_q[((size_t)b * NN + n) * 512 + c5] = vv;
                        else if (sel == 1) g_k[((size_t)b * NK + n) * 512 + c5] = vv;
                        else               g_v[((size_t)b * NK + n) * 512 + c5] = vv;
                    }
                }
            } else {
                float2 bq = *(const float2*)(bias + cl);
                float2 o0; o0.x = c[0] + bq.x; o0.y = c[1] + bq.y;
                float2 o1; o1.x = c[2] + bq.x; o1.y = c[3] + bq.y;
                *(float2*)(dout + (size_t)rlo * 512 + cl)       = o0;
                *(float2*)(dout + (size_t)(rlo + 8) * 512 + cl) = o1;
            }
        }
    }
}

// ---------------- append mem rows to k and v tails --------------------------
__global__ void copy_mem_kernel(const float* __restrict__ mem) {
    int i = blockIdx.x * blockDim.x + threadIdx.x;
    if (i >= BB * MM * 512 / 4) return;
    float4 v = ((const float4*)mem)[i];
    int gi = i << 2;
    int b = gi / (MM * 512);
    int rem = gi - b * (MM * 512);
    size_t off = ((size_t)b * NK + NN) * 512 + rem;
    *(float4*)(g_k + off) = v;
    *(float4*)(g_v + off) = v;
}

// ---------------- PEG1D depthwise conv -> rounded fp16 ----------------------
__global__ void peg_kernel(const float* __restrict__ w,
                           const float* __restrict__ bias, int which) {
    const float* src = which ? g_v : g_k;
    __half* df = which ? g_vf : g_kf;
    int gr = blockIdx.x;
    int b = gr / NK, r = gr - b * NK;
    int c = threadIdx.x << 2;
    const float* base = src + (size_t)b * NK * 512;
    float4 xc = *(const float4*)(base + (size_t)r * 512 + c);
    size_t doff = ((size_t)b * NK + r) * 512 + c;
    float4 o4;
    if (r == 0) {
        o4 = xc;
    } else {
        int t = r - 1;
        float w0[4], w1[4], w2[4];
        #pragma unroll
        for (int j = 0; j < 4; j++) {
            w0[j] = __ldg(w + (c + j) * 3 + 0);
            w1[j] = __ldg(w + (c + j) * 3 + 1);
            w2[j] = __ldg(w + (c + j) * 3 + 2);
        }
        float4 bb = *(const float4*)(bias + c);
        const float4 z4 = make_float4(0.f, 0.f, 0.f, 0.f);
        int p = t & 31;
        float4 L1 = (p > 0)                 ? *(const float4*)(base + (size_t)r * 512 - 512 + c) : z4;
        float4 R1 = (p < 31 && t + 1 < LSEQ)? *(const float4*)(base + (size_t)r * 512 + 512 + c) : z4;
        int u   = (t + 16) % LSEQ;
        int p2p = u % 32;
        int jl  = (u + LSEQ - 17) % LSEQ;
        int jr  = (u + LSEQ - 15) % LSEQ;
        float4 L2 = (p2p > 0)                  ? *(const float4*)(base + (size_t)(1 + jl) * 512 + c) : z4;
        float4 R2 = (p2p < 31 && u + 1 < LSEQ) ? *(const float4*)(base + (size_t)(1 + jr) * 512 + c) : z4;
        o4.x = xc.x + (w0[0]*L1.x + w1[0]*xc.x + w2[0]*R1.x + bb.x)
                    + (w0[0]*L2.x + w1[0]*xc.x + w2[0]*R2.x + bb.x);
        o4.y = xc.y + (w0[1]*L1.y + w1[1]*xc.y + w2[1]*R1.y + bb.y)
                    + (w0[1]*L2.y + w1[1]*xc.y + w2[1]*R2.y + bb.y);
        o4.z = xc.z + (w0[2]*L1.z + w1[2]*xc.z + w2[2]*R1.z + bb.z)
                    + (w0[2]*L2.z + w1[2]*xc.z + w2[2]*R2.z + bb.z);
        o4.w = xc.w + (w0[3]*L1.w + w1[3]*xc.w + w2[3]*R1.w + bb.w)
                    + (w0[3]*L2.w + w1[3]*xc.w + w2[3]*R2.w + bb.w);
    }
    *(uint2*)(df + doff) = make_uint2(rnd2(o4.x, o4.y), rnd2(o4.z, o4.w));
}

// ---------------- flash attention, fp16x2 mma + cp.async pipeline -----------
#define KSTR 72
__global__ __launch_bounds__(256)
void attn_mma_kernel() {
    __shared__ __align__(16) __half Ks[2][64 * KSTR];
    __shared__ __align__(16) __half Vs[2][64 * KSTR];
    int tid = threadIdx.x;
    int w = tid >> 5, lane = tid & 31;
    int gq = lane >> 2, qq = lane & 3;
    int lt = lane >> 3, lr = lane & 7;
    int bh_ = blockIdx.y;
    int b = bh_ >> 3, h = bh_ & 7;
    int q0 = blockIdx.x * 128 + w * 16;

    const __half* kfb = g_kf + ((size_t)b * NK) * 512 + h * 64;
    const __half* vfb = g_vf + ((size_t)b * NK) * 512 + h * 64;

    auto load_tile = [&](int kt, int s) {
        #pragma unroll
        for (int i = 0; i < 2; i++) {
            int idx = tid + 256 * i;
            int row = idx >> 3, e = idx & 7;
            size_t goff = (size_t)(kt + row) * 512 + 8 * e;
            int soff = row * KSTR + 8 * e;
            cpa16(&Ks[s][soff], kfb + goff);
            cpa16(&Vs[s][soff], vfb + goff);
        }
        cp_commit();
    };

    unsigned qh[4][4], ql[4][4];
    {
        const float* qbase = g_q + ((size_t)b * NN + q0) * 512 + h * 64;
        #pragma unroll
        for (int kk = 0; kk < 4; kk++)
            #pragma unroll
            for (int cc = 0; cc < 2; cc++)
                #pragma unroll
                for (int rr = 0; rr < 2; rr++) {
                    int row = gq + rr * 8;
                    int dim = kk * 16 + cc * 8 + qq * 2;
                    float2 qv = *(const float2*)(qbase + (size_t)row * 512 + dim);
                    splitpk(qv.x * 0.125f, qv.y * 0.125f,
                            qh[kk][rr + 2 * cc], ql[kk][rr + 2 * cc]);
                }
    }

    float O[8][4];
    #pragma unroll
    for (int j = 0; j < 8; j++)
        #pragma unroll
        for (int c = 0; c < 4; c++) O[j][c] = 0.f;
    float rm0 = -1e30f, rm1 = -1e30f, rl0 = 0.f, rl1 = 0.f;

    load_tile(0, 0);
    const int NT = NK / 64;                 // 80 tiles
    for (int t = 0; t < NT; t++) {
        int s = t & 1;
        if (t + 1 < NT) load_tile((t + 1) * 64, (t + 1) & 1);
        if (t + 1 < NT) cp_wait1(); else cp_wait0();
        __syncthreads();

        float S[8][4];
        #pragma unroll
        for (int j = 0; j < 8; j++) {
            unsigned bf[8];
            int krow = (8 * j + lr) * KSTR;
            ldsm4(bf,     su(&Ks[s][krow + 8 * lt]));
            ldsm4(bf + 4, su(&Ks[s][krow + 32 + 8 * lt]));
            float c[4] = {0.f, 0.f, 0.f, 0.f};
            #pragma unroll
            for (int kk = 0; kk < 4; kk++) {
                mma16816(c, qh[kk], bf[2 * kk], bf[2 * kk + 1]);
                mma16816(c, ql[kk], bf[2 * kk], bf[2 * kk + 1]);
            }
            S[j][0] = c[0]; S[j][1] = c[1]; S[j][2] = c[2]; S[j][3] = c[3];
        }

        float tm0 = -1e30f, tm1 = -1e30f;
        #pragma unroll
        for (int j = 0; j < 8; j++) {
            tm0 = fmaxf(tm0, fmaxf(S[j][0], S[j][1]));
            tm1 = fmaxf(tm1, fmaxf(S[j][2], S[j][3]));
        }
        tm0 = fmaxf(tm0, __shfl_xor_sync(0xffffffffu, tm0, 1));
        tm0 = fmaxf(tm0, __shfl_xor_sync(0xffffffffu, tm0, 2));
        tm1 = fmaxf(tm1, __shfl_xor_sync(0xffffffffu, tm1, 1));
        tm1 = fmaxf(tm1, __shfl_xor_sync(0xffffffffu, tm1, 2));
        float m0n = fmaxf(rm0, tm0), m1n = fmaxf(rm1, tm1);
        float cor0 = __expf(rm0 - m0n), cor1 = __expf(rm1 - m1n);
        rl0 *= cor0; rl1 *= cor1;
        #pragma unroll
        for (int j = 0; j < 8; j++) {
            O[j][0] *= cor0; O[j][1] *= cor0;
            O[j][2] *= cor1; O[j][3] *= cor1;
        }
        rm0 = m0n; rm1 = m1n;

        unsigned Ph[4][4], Pl[4][4];
        #pragma unroll
        for (int j = 0; j < 8; j++) {
            float p0 = __expf(S[j][0] - m0n);
            float p1 = __expf(S[j][1] - m0n);
            float p2 = __expf(S[j][2] - m1n);
            float p3 = __expf(S[j][3] - m1n);
            rl0 += p0 + p1; rl1 += p2 + p3;
            int kk2 = j >> 1, half_ = j & 1;
            splitpk(p0, p1, Ph[kk2][2 * half_],     Pl[kk2][2 * half_]);
            splitpk(p2, p3, Ph[kk2][2 * half_ + 1], Pl[kk2][2 * half_ + 1]);
        }

        #pragma unroll
        for (int jd = 0; jd < 8; jd++) {
            unsigned vf[8];
            ldsm4t(vf,     su(&Vs[s][(8 * lt + lr) * KSTR + 8 * jd]));
            ldsm4t(vf + 4, su(&Vs[s][(32 + 8 * lt + lr) * KSTR + 8 * jd]));
            #pragma unroll
            for (int kk2 = 0; kk2 < 4; kk2++) {
                mma16816(O[jd], Ph[kk2], vf[2 * kk2], vf[2 * kk2 + 1]);
                mma16816(O[jd], Pl[kk2], vf[2 * kk2], vf[2 * kk2 + 1]);
            }
        }
        __syncthreads();
    }

    float l0 = rl0, l1 = rl1;
    l0 += __shfl_xor_sync(0xffffffffu, l0, 1);
    l0 += __shfl_xor_sync(0xffffffffu, l0, 2);
    l1 += __shfl_xor_sync(0xffffffffu, l1, 1);
    l1 += __shfl_xor_sync(0xffffffffu, l1, 2);
    float inv0 = 1.0f / l0, inv1 = 1.0f / l1;
    size_t obase = ((size_t)b * NN + q0) * 512 + h * 64;
    #pragma unroll
    for (int jd = 0; jd < 8; jd++) {
        int dim = 8 * jd + qq * 2;
        unsigned h2, l2;
        splitpk(O[jd][0] * inv0, O[jd][1] * inv0, h2, l2);
        *(unsigned*)&g_ah[obase + (size_t)gq * 512 + dim] = h2;
        *(unsigned*)&g_al[obase + (size_t)gq * 512 + dim] = l2;
        splitpk(O[jd][2] * inv1, O[jd][3] * inv1, h2, l2);
        *(unsigned*)&g_ah[obase + (size_t)(gq + 8) * 512 + dim] = h2;
        *(unsigned*)&g_al[obase + (size_t)(gq + 8) * 512 + dim] = l2;
    }
}

// ---------------- launch ----------------------------------------------------
extern "C" void kernel_launch(void* const* d_in, const int* in_sizes, int n_in,
                              void* d_out, int out_size) {
    const float* x     = (const float*)d_in[0];
    const float* mem   = (const float*)d_in[1];
    const float* ln_g  = (const float*)d_in[2];
    const float* ln_b  = (const float*)d_in[3];
    const float* w_qkv = (const float*)d_in[4];
    const float* w_out = (const float*)d_in[5];
    const float* b_out = (const float*)d_in[6];
    const float* pk_w  = (const float*)d_in[7];
    const float* pk_b  = (const float*)d_in[8];
    const float* pv_w  = (const float*)d_in[9];
    const float* pv_b  = (const float*)d_in[10];
    float* out = (float*)d_out;

    __half *wqh, *wql, *woh, *wol;
    cudaGetSymbolAddress((void**)&wqh, g_wqh);
    cudaGetSymbolAddress((void**)&wql, g_wql);
    cudaGetSymbolAddress((void**)&woh, g_woh);
    cudaGetSymbolAddress((void**)&wol, g_wol);

    split_kernel<<<(DD * 3 * DD / 4 + 255) / 256, 256>>>(w_qkv, wqh, wql, DD * 3 * DD / 4);
    split_kernel<<<(DD * DD / 4 + 255) / 256, 256>>>(w_out, woh, wol, DD * DD / 4);
    ln_kernel<<<BB * NN, 128>>>(x, ln_g, ln_b);
    mma_gemm_kernel<<<dim3(1536 / 64, (BB * NN) / 128), 256>>>(wqh, wql, nullptr, nullptr, 1536, 0);
    copy_mem_kernel<<<(BB * MM * 512 / 4 + 255) / 256, 256>>>(mem);
    peg_kernel<<<BB * NK, 128>>>(pk_w, pk_b, 0);
    peg_kernel<<<BB * NK, 128>>>(pv_w, pv_b, 1);
    attn_mma_kernel<<<dim3(NN / 128, BB * HH), 256>>>();
    mma_gemm_kernel<<<dim3(512 / 64, (BB * NN) / 128), 256>>>(woh, wol, b_out, out, 512, 1);
}

// round 8
// speedup vs baseline: 18.2014x; 1.5746x over previous
#include <cuda_runtime.h>
#include <cuda_fp16.h>
#include <cstring>

#define BB 2
#define NN 4096
#define DD 512
#define HH 8
#define DH 64
#define MM 1024
#define NK 5120          // NN + MM
#define LSEQ 5119        // NK - 1

// ---------------- fp16 split + mma + ldmatrix + cp.async helpers ------------
__device__ __forceinline__ void splitpk(float x, float y, unsigned &hi, unsigned &lo) {
    __half2 h = __floats2half2_rn(x, y);
    float hx = __low2float(h), hy = __high2float(h);
    __half2 l = __floats2half2_rn(x - hx, y - hy);
    memcpy(&hi, &h, 4); memcpy(&lo, &l, 4);
}
__device__ __forceinline__ unsigned rnd2(float x, float y) {
    __half2 h = __floats2half2_rn(x, y);
    unsigned u; memcpy(&u, &h, 4); return u;
}
__device__ __forceinline__ void mma16816(float c[4], const unsigned a[4],
                                         unsigned b0, unsigned b1) {
    asm("mma.sync.aligned.m16n8k16.row.col.f32.f16.f16.f32 "
        "{%0,%1,%2,%3},{%4,%5,%6,%7},{%8,%9},{%0,%1,%2,%3};"
        : "+f"(c[0]), "+f"(c[1]), "+f"(c[2]), "+f"(c[3])
        : "r"(a[0]), "r"(a[1]), "r"(a[2]), "r"(a[3]), "r"(b0), "r"(b1));
}
__device__ __forceinline__ unsigned su(const void* p) {
    return (unsigned)__cvta_generic_to_shared(p);
}
__device__ __forceinline__ void ldsm4(unsigned* r, unsigned addr) {
    asm volatile("ldmatrix.sync.aligned.m8n8.x4.shared.b16 {%0,%1,%2,%3}, [%4];"
                 : "=r"(r[0]), "=r"(r[1]), "=r"(r[2]), "=r"(r[3]) : "r"(addr));
}
__device__ __forceinline__ void ldsm4t(unsigned* r, unsigned addr) {
    asm volatile("ldmatrix.sync.aligned.m8n8.x4.trans.shared.b16 {%0,%1,%2,%3}, [%4];"
                 : "=r"(r[0]), "=r"(r[1]), "=r"(r[2]), "=r"(r[3]) : "r"(addr));
}
__device__ __forceinline__ void cpa16(void* s, const void* g) {
    asm volatile("cp.async.cg.shared.global [%0], [%1], 16;" :: "r"(su(s)), "l"(g));
}
__device__ __forceinline__ void cp_commit() { asm volatile("cp.async.commit_group;"); }
__device__ __forceinline__ void cp_wait0()  { asm volatile("cp.async.wait_group 0;"); }

// ---------------- scratch ----------------------------------------------------
__device__ __half g_xh[BB * NN * DD];
__device__ __half g_xl[BB * NN * DD];
__device__ float  g_q [BB * NN * DD];
__device__ float  g_k [BB * NK * DD];
__device__ float  g_v [BB * NK * DD];
__device__ __half g_kf[BB * NK * DD];
__device__ __half g_vf[BB * NK * DD];
__device__ __half g_ah[BB * NN * DD];
__device__ __half g_al[BB * NN * DD];
__device__ __half g_wqh[DD * 3 * DD];
__device__ __half g_wql[DD * 3 * DD];
__device__ __half g_woh[DD * DD];
__device__ __half g_wol[DD * DD];

// ---------------- fp32 -> fp16 hi/lo splitter (weights) ---------------------
__global__ void split_kernel(const float* __restrict__ src,
                             __half* __restrict__ hi,
                             __half* __restrict__ lo, int n4) {
    int i = blockIdx.x * 256 + threadIdx.x;
    if (i >= n4) return;
    float4 v = ((const float4*)src)[i];
    unsigned h0, l0, h1, l1;
    splitpk(v.x, v.y, h0, l0);
    splitpk(v.z, v.w, h1, l1);
    ((uint2*)hi)[i] = make_uint2(h0, h1);
    ((uint2*)lo)[i] = make_uint2(l0, l1);
}

// ---------------- LayerNorm (writes hi/lo fp16) ------------------------------
__global__ void ln_kernel(const float* __restrict__ x,
                          const float* __restrict__ g,
                          const float* __restrict__ bt) {
    int row = blockIdx.x;
    int t = threadIdx.x;
    const float4* xr = (const float4*)(x + (size_t)row * DD);
    float4 v = xr[t];
    float s  = v.x + v.y + v.z + v.w;
    float s2 = v.x*v.x + v.y*v.y + v.z*v.z + v.w*v.w;
    #pragma unroll
    for (int o = 16; o > 0; o >>= 1) {
        s  += __shfl_xor_sync(0xffffffffu, s,  o);
        s2 += __shfl_xor_sync(0xffffffffu, s2, o);
    }
    __shared__ float a1[4], a2[4];
    int w = t >> 5;
    if ((t & 31) == 0) { a1[w] = s; a2[w] = s2; }
    __syncthreads();
    s  = a1[0] + a1[1] + a1[2] + a1[3];
    s2 = a2[0] + a2[1] + a2[2] + a2[3];
    float mu  = s * (1.0f / 512.0f);
    float var = s2 * (1.0f / 512.0f) - mu * mu;
    float rs  = rsqrtf(var + 1e-5f);
    float4 gg = ((const float4*)g)[t];
    float4 bb = ((const float4*)bt)[t];
    float4 o4;
    o4.x = (v.x - mu) * rs * gg.x + bb.x;
    o4.y = (v.y - mu) * rs * gg.y + bb.y;
    o4.z = (v.z - mu) * rs * gg.z + bb.z;
    o4.w = (v.w - mu) * rs * gg.w + bb.w;
    unsigned h0, l0, h1, l1;
    splitpk(o4.x, o4.y, h0, l0);
    splitpk(o4.z, o4.w, h1, l1);
    ((uint2*)(g_xh + (size_t)row * DD))[t] = make_uint2(h0, h1);
    ((uint2*)(g_xl + (size_t)row * DD))[t] = make_uint2(l0, l1);
}

// ---------------- fp16x3 mma GEMM, 2-stage cp.async, 1 sync/iter ------------
#define ASTR 24
#define WSTR 72
__global__ __launch_bounds__(256)
void mma_gemm_kernel(const __half* __restrict__ Wh,
                     const __half* __restrict__ Wl,
                     const float* __restrict__ bias,
                     float* __restrict__ dout, int cn, int mode) {
    const __half* Ah = mode ? g_ah : g_xh;
    const __half* Al = mode ? g_al : g_xl;
    __shared__ __align__(16) __half sAh[2][128 * ASTR];
    __shared__ __align__(16) __half sAl[2][128 * ASTR];
    __shared__ __align__(16) __half sWh[2][16 * WSTR];
    __shared__ __align__(16) __half sWl[2][16 * WSTR];
    int tid = threadIdx.x, w = tid >> 5, lane = tid & 31;
    int gq = lane >> 2, qq = lane & 3;
    int lt = lane >> 3, lr = lane & 7;
    int row0 = blockIdx.y * 128, col0 = blockIdx.x * 64;
    int wm = w >> 1, wn = w & 1;
    float acc[2][4][4];
    #pragma unroll
    for (int mf = 0; mf < 2; mf++)
        #pragma unroll
        for (int nf = 0; nf < 4; nf++)
            #pragma unroll
            for (int c = 0; c < 4; c++) acc[mf][nf][c] = 0.f;

    auto load_tile = [&](int t, int s) {
        int kt = t * 16;
        {
            int r = tid >> 1, e = tid & 1;
            cpa16(&sAh[s][r * ASTR + 8 * e], Ah + (size_t)(row0 + r) * 512 + kt + 8 * e);
            cpa16(&sAl[s][r * ASTR + 8 * e], Al + (size_t)(row0 + r) * 512 + kt + 8 * e);
        }
        if (tid < 128) {
            int r = tid >> 3, e = tid & 7;
            cpa16(&sWh[s][r * WSTR + 8 * e], Wh + (size_t)(kt + r) * cn + col0 + 8 * e);
            cpa16(&sWl[s][r * WSTR + 8 * e], Wl + (size_t)(kt + r) * cn + col0 + 8 * e);
        }
        cp_commit();
    };

    load_tile(0, 0);
    for (int t = 0; t < 32; t++) {
        int s = t & 1;
        cp_wait0();
        __syncthreads();
        if (t + 1 < 32) load_tile(t + 1, s ^ 1);
        unsigned ah[2][4], al[2][4];
        #pragma unroll
        for (int mf = 0; mf < 2; mf++) {
            int ar = wm * 32 + mf * 16 + (lt & 1) * 8 + lr;
            int ak = (lt >> 1) * 8;
            ldsm4(ah[mf], su(&sAh[s][ar * ASTR + ak]));
            ldsm4(al[mf], su(&sAl[s][ar * ASTR + ak]));
        }
        unsigned bh[2][4], bl[2][4];
        #pragma unroll
        for (int nh = 0; nh < 2; nh++) {
            int br = (lt & 1) * 8 + lr;
            int bc = wn * 32 + nh * 16 + (lt >> 1) * 8;
            ldsm4t(bh[nh], su(&sWh[s][br * WSTR + bc]));
            ldsm4t(bl[nh], su(&sWl[s][br * WSTR + bc]));
        }
        #pragma unroll
        for (int nf = 0; nf < 4; nf++) {
            unsigned bh0 = bh[nf >> 1][(nf & 1) * 2];
            unsigned bh1 = bh[nf >> 1][(nf & 1) * 2 + 1];
            unsigned bl0 = bl[nf >> 1][(nf & 1) * 2];
            unsigned bl1 = bl[nf >> 1][(nf & 1) * 2 + 1];
            #pragma unroll
            for (int mf = 0; mf < 2; mf++) {
                mma16816(acc[mf][nf], ah[mf], bh0, bh1);
                mma16816(acc[mf][nf], al[mf], bh0, bh1);
                mma16816(acc[mf][nf], ah[mf], bl0, bl1);
            }
        }
    }
    #pragma unroll
    for (int mf = 0; mf < 2; mf++) {
        int rlo = row0 + wm * 32 + mf * 16 + gq;
        #pragma unroll
        for (int nf = 0; nf < 4; nf++) {
            int cl = col0 + wn * 32 + nf * 8 + 2 * qq;
            float* c = acc[mf][nf];
            if (mode == 0) {
                #pragma unroll
                for (int half_ = 0; half_ < 2; half_++) {
                    int rr = rlo + half_ * 8;
                    int b = rr >> 12, n = rr & 4095;
                    #pragma unroll
                    for (int j = 0; j < 2; j++) {
                        int cc = cl + j;
                        int sel = cc >> 9, c5 = cc & 511;
                        float vv = c[2 * half_ + j];
                        if (sel == 0)      g_q[((size_t)b * NN + n) * 512 + c5] = vv;
                        else if (sel == 1) g_k[((size_t)b * NK + n) * 512 + c5] = vv;
                        else               g_v[((size_t)b * NK + n) * 512 + c5] = vv;
                    }
                }
            } else {
                float2 bq = *(const float2*)(bias + cl);
                float2 o0; o0.x = c[0] + bq.x; o0.y = c[1] + bq.y;
                float2 o1; o1.x = c[2] + bq.x; o1.y = c[3] + bq.y;
                *(float2*)(dout + (size_t)rlo * 512 + cl)       = o0;
                *(float2*)(dout + (size_t)(rlo + 8) * 512 + cl) = o1;
            }
        }
    }
}

// ---------------- append mem rows to k and v tails --------------------------
__global__ void copy_mem_kernel(const float* __restrict__ mem) {
    int i = blockIdx.x * blockDim.x + threadIdx.x;
    if (i >= BB * MM * 512 / 4) return;
    float4 v = ((const float4*)mem)[i];
    int gi = i << 2;
    int b = gi / (MM * 512);
    int rem = gi - b * (MM * 512);
    size_t off = ((size_t)b * NK + NN) * 512 + rem;
    *(float4*)(g_k + off) = v;
    *(float4*)(g_v + off) = v;
}

// ---------------- PEG1D depthwise conv -> rounded fp16 ----------------------
__global__ void peg_kernel(const float* __restrict__ w,
                           const float* __restrict__ bias, int which) {
    const float* src = which ? g_v : g_k;
    __half* df = which ? g_vf : g_kf;
    int gr = blockIdx.x;
    int b = gr / NK, r = gr - b * NK;
    int c = threadIdx.x << 2;
    const float* base = src + (size_t)b * NK * 512;
    float4 xc = *(const float4*)(base + (size_t)r * 512 + c);
    size_t doff = ((size_t)b * NK + r) * 512 + c;
    float4 o4;
    if (r == 0) {
        o4 = xc;
    } else {
        int t = r - 1;
        float w0[4], w1[4], w2[4];
        #pragma unroll
        for (int j = 0; j < 4; j++) {
            w0[j] = __ldg(w + (c + j) * 3 + 0);
            w1[j] = __ldg(w + (c + j) * 3 + 1);
            w2[j] = __ldg(w + (c + j) * 3 + 2);
        }
        float4 bb = *(const float4*)(bias + c);
        const float4 z4 = make_float4(0.f, 0.f, 0.f, 0.f);
        int p = t & 31;
        float4 L1 = (p > 0)                 ? *(const float4*)(base + (size_t)r * 512 - 512 + c) : z4;
        float4 R1 = (p < 31 && t + 1 < LSEQ)? *(const float4*)(base + (size_t)r * 512 + 512 + c) : z4;
        int u   = (t + 16) % LSEQ;
        int p2p = u % 32;
        int jl  = (u + LSEQ - 17) % LSEQ;
        int jr  = (u + LSEQ - 15) % LSEQ;
        float4 L2 = (p2p > 0)                  ? *(const float4*)(base + (size_t)(1 + jl) * 512 + c) : z4;
        float4 R2 = (p2p < 31 && u + 1 < LSEQ) ? *(const float4*)(base + (size_t)(1 + jr) * 512 + c) : z4;
        o4.x = xc.x + (w0[0]*L1.x + w1[0]*xc.x + w2[0]*R1.x + bb.x)
                    + (w0[0]*L2.x + w1[0]*xc.x + w2[0]*R2.x + bb.x);
        o4.y = xc.y + (w0[1]*L1.y + w1[1]*xc.y + w2[1]*R1.y + bb.y)
                    + (w0[1]*L2.y + w1[1]*xc.y + w2[1]*R2.y + bb.y);
        o4.z = xc.z + (w0[2]*L1.z + w1[2]*xc.z + w2[2]*R1.z + bb.z)
                    + (w0[2]*L2.z + w1[2]*xc.z + w2[2]*R2.z + bb.z);
        o4.w = xc.w + (w0[3]*L1.w + w1[3]*xc.w + w2[3]*R1.w + bb.w)
                    + (w0[3]*L2.w + w1[3]*xc.w + w2[3]*R2.w + bb.w);
    }
    *(uint2*)(df + doff) = make_uint2(rnd2(o4.x, o4.y), rnd2(o4.z, o4.w));
}

// ---------------- flash attention, fp16 1-term mma + cp.async ---------------
#define KSTR 72
__global__ __launch_bounds__(256)
void attn_mma_kernel() {
    __shared__ __align__(16) __half Ks[2][64 * KSTR];
    __shared__ __align__(16) __half Vs[2][64 * KSTR];
    int tid = threadIdx.x;
    int w = tid >> 5, lane = tid & 31;
    int gq = lane >> 2, qq = lane & 3;
    int lt = lane >> 3, lr = lane & 7;
    int bh_ = blockIdx.y;
    int b = bh_ >> 3, h = bh_ & 7;
    int q0 = blockIdx.x * 128 + w * 16;

    const __half* kfb = g_kf + ((size_t)b * NK) * 512 + h * 64;
    const __half* vfb = g_vf + ((size_t)b * NK) * 512 + h * 64;

    auto load_tile = [&](int kt, int s) {
        #pragma unroll
        for (int i = 0; i < 2; i++) {
            int idx = tid + 256 * i;
            int row = idx >> 3, e = idx & 7;
            size_t goff = (size_t)(kt + row) * 512 + 8 * e;
            int soff = row * KSTR + 8 * e;
            cpa16(&Ks[s][soff], kfb + goff);
            cpa16(&Vs[s][soff], vfb + goff);
        }
        cp_commit();
    };

    unsigned qh[4][4];
    {
        const float* qbase = g_q + ((size_t)b * NN + q0) * 512 + h * 64;
        #pragma unroll
        for (int kk = 0; kk < 4; kk++)
            #pragma unroll
            for (int cc = 0; cc < 2; cc++)
                #pragma unroll
                for (int rr = 0; rr < 2; rr++) {
                    int row = gq + rr * 8;
                    int dim = kk * 16 + cc * 8 + qq * 2;
                    float2 qv = *(const float2*)(qbase + (size_t)row * 512 + dim);
                    qh[kk][rr + 2 * cc] = rnd2(qv.x * 0.125f, qv.y * 0.125f);
                }
    }

    float O[8][4];
    #pragma unroll
    for (int j = 0; j < 8; j++)
        #pragma unroll
        for (int c = 0; c < 4; c++) O[j][c] = 0.f;
    float rm0 = -1e30f, rm1 = -1e30f, rl0 = 0.f, rl1 = 0.f;

    load_tile(0, 0);
    const int NT = NK / 64;
    for (int t = 0; t < NT; t++) {
        int s = t & 1;
        cp_wait0();
        __syncthreads();
        if (t + 1 < NT) load_tile((t + 1) * 64, s ^ 1);

        float S[8][4];
        #pragma unroll
        for (int j = 0; j < 8; j++) {
            unsigned bf[8];
            int krow = (8 * j + lr) * KSTR;
            ldsm4(bf,     su(&Ks[s][krow + 8 * lt]));
            ldsm4(bf + 4, su(&Ks[s][krow + 32 + 8 * lt]));
            float c[4] = {0.f, 0.f, 0.f, 0.f};
            #pragma unroll
            for (int kk = 0; kk < 4; kk++)
                mma16816(c, qh[kk], bf[2 * kk], bf[2 * kk + 1]);
            S[j][0] = c[0]; S[j][1] = c[1]; S[j][2] = c[2]; S[j][3] = c[3];
        }

        float tm0 = -1e30f, tm1 = -1e30f;
        #pragma unroll
        for (int j = 0; j < 8; j++) {
            tm0 = fmaxf(tm0, fmaxf(S[j][0], S[j][1]));
            tm1 = fmaxf(tm1, fmaxf(S[j][2], S[j][3]));
        }
        tm0 = fmaxf(tm0, __shfl_xor_sync(0xffffffffu, tm0, 1));
        tm0 = fmaxf(tm0, __shfl_xor_sync(0xffffffffu, tm0, 2));
        tm1 = fmaxf(tm1, __shfl_xor_sync(0xffffffffu, tm1, 1));
        tm1 = fmaxf(tm1, __shfl_xor_sync(0xffffffffu, tm1, 2));
        float m0n = fmaxf(rm0, tm0), m1n = fmaxf(rm1, tm1);
        float cor0 = __expf(rm0 - m0n), cor1 = __expf(rm1 - m1n);
        rl0 *= cor0; rl1 *= cor1;
        #pragma unroll
        for (int j = 0; j < 8; j++) {
            O[j][0] *= cor0; O[j][1] *= cor0;
            O[j][2] *= cor1; O[j][3] *= cor1;
        }
        rm0 = m0n; rm1 = m1n;

        unsigned Ph[4][4];
        #pragma unroll
        for (int j = 0; j < 8; j++) {
            float p0 = __expf(S[j][0] - m0n);
            float p1 = __expf(S[j][1] - m0n);
            float p2 = __expf(S[j][2] - m1n);
            float p3 = __expf(S[j][3] - m1n);
            rl0 += p0 + p1; rl1 += p2 + p3;
            int kk2 = j >> 1, half_ = j & 1;
            Ph[kk2][2 * half_]     = rnd2(p0, p1);
            Ph[kk2][2 * half_ + 1] = rnd2(p2, p3);
        }

        #pragma unroll
        for (int jd = 0; jd < 8; jd++) {
            unsigned vf[8];
            ldsm4t(vf,     su(&Vs[s][(8 * lt + lr) * KSTR + 8 * jd]));
            ldsm4t(vf + 4, su(&Vs[s][(32 + 8 * lt + lr) * KSTR + 8 * jd]));
            #pragma unroll
            for (int kk2 = 0; kk2 < 4; kk2++)
                mma16816(O[jd], Ph[kk2], vf[2 * kk2], vf[2 * kk2 + 1]);
        }
    }

    float l0 = rl0, l1 = rl1;
    l0 += __shfl_xor_sync(0xffffffffu, l0, 1);
    l0 += __shfl_xor_sync(0xffffffffu, l0, 2);
    l1 += __shfl_xor_sync(0xffffffffu, l1, 1);
    l1 += __shfl_xor_sync(0xffffffffu, l1, 2);
    float inv0 = 1.0f / l0, inv1 = 1.0f / l1;
    size_t obase = ((size_t)b * NN + q0) * 512 + h * 64;
    #pragma unroll
    for (int jd = 0; jd < 8; jd++) {
        int dim = 8 * jd + qq * 2;
        unsigned h2, l2;
        splitpk(O[jd][0] * inv0, O[jd][1] * inv0, h2, l2);
        *(unsigned*)&g_ah[obase + (size_t)gq * 512 + dim] = h2;
        *(unsigned*)&g_al[obase + (size_t)gq * 512 + dim] = l2;
        splitpk(O[jd][2] * inv1, O[jd][3] * inv1, h2, l2);
        *(unsigned*)&g_ah[obase + (size_t)(gq + 8) * 512 + dim] = h2;
        *(unsigned*)&g_al[obase + (size_t)(gq + 8) * 512 + dim] = l2;
    }
}

// ---------------- launch ----------------------------------------------------
extern "C" void kernel_launch(void* const* d_in, const int* in_sizes, int n_in,
                              void* d_out, int out_size) {
    const float* x     = (const float*)d_in[0];
    const float* mem   = (const float*)d_in[1];
    const float* ln_g  = (const float*)d_in[2];
    const float* ln_b  = (const float*)d_in[3];
    const float* w_qkv = (const float*)d_in[4];
    const float* w_out = (const float*)d_in[5];
    const float* b_out = (const float*)d_in[6];
    const float* pk_w  = (const float*)d_in[7];
    const float* pk_b  = (const float*)d_in[8];
    const float* pv_w  = (const float*)d_in[9];
    const float* pv_b  = (const float*)d_in[10];
    float* out = (float*)d_out;

    __half *wqh, *wql, *woh, *wol;
    cudaGetSymbolAddress((void**)&wqh, g_wqh);
    cudaGetSymbolAddress((void**)&wql, g_wql);
    cudaGetSymbolAddress((void**)&woh, g_woh);
    cudaGetSymbolAddress((void**)&wol, g_wol);

    split_kernel<<<(DD * 3 * DD / 4 + 255) / 256, 256>>>(w_qkv, wqh, wql, DD * 3 * DD / 4);
    split_kernel<<<(DD * DD / 4 + 255) / 256, 256>>>(w_out, woh, wol, DD * DD / 4);
    ln_kernel<<<BB * NN, 128>>>(x, ln_g, ln_b);
    mma_gemm_kernel<<<dim3(1536 / 64, (BB * NN) / 128), 256>>>(wqh, wql, nullptr, nullptr, 1536, 0);
    copy_mem_kernel<<<(BB * MM * 512 / 4 + 255) / 256, 256>>>(mem);
    peg_kernel<<<BB * NK, 128>>>(pk_w, pk_b, 0);
    peg_kernel<<<BB * NK, 128>>>(pv_w, pv_b, 1);
    attn_mma_kernel<<<dim3(NN / 128, BB * HH), 256>>>();
    mma_gemm_kernel<<<dim3(512 / 64, (BB * NN) / 128), 256>>>(woh, wol, b_out, out, 512, 1);
}

// round 9
// speedup vs baseline: 18.5589x; 1.0196x over previous
#include <cuda_runtime.h>
#include <cuda_fp16.h>
#include <cstring>

#define BB 2
#define NN 4096
#define DD 512
#define HH 8
#define DH 64
#define MM 1024
#define NK 5120          // NN + MM
#define LSEQ 5119        // NK - 1

// ---------------- fp16 helpers -----------------------------------------------
__device__ __forceinline__ void splitpk(float x, float y, unsigned &hi, unsigned &lo) {
    __half2 h = __floats2half2_rn(x, y);
    float hx = __low2float(h), hy = __high2float(h);
    __half2 l = __floats2half2_rn(x - hx, y - hy);
    memcpy(&hi, &h, 4); memcpy(&lo, &l, 4);
}
__device__ __forceinline__ unsigned rnd2(float x, float y) {
    __half2 h = __floats2half2_rn(x, y);
    unsigned u; memcpy(&u, &h, 4); return u;
}
__device__ __forceinline__ void mma16816(float c[4], const unsigned a[4],
                                         unsigned b0, unsigned b1) {
    asm("mma.sync.aligned.m16n8k16.row.col.f32.f16.f16.f32 "
        "{%0,%1,%2,%3},{%4,%5,%6,%7},{%8,%9},{%0,%1,%2,%3};"
        : "+f"(c[0]), "+f"(c[1]), "+f"(c[2]), "+f"(c[3])
        : "r"(a[0]), "r"(a[1]), "r"(a[2]), "r"(a[3]), "r"(b0), "r"(b1));
}
__device__ __forceinline__ unsigned su(const void* p) {
    return (unsigned)__cvta_generic_to_shared(p);
}
__device__ __forceinline__ void ldsm4(unsigned* r, unsigned addr) {
    asm volatile("ldmatrix.sync.aligned.m8n8.x4.shared.b16 {%0,%1,%2,%3}, [%4];"
                 : "=r"(r[0]), "=r"(r[1]), "=r"(r[2]), "=r"(r[3]) : "r"(addr));
}
__device__ __forceinline__ void ldsm4t(unsigned* r, unsigned addr) {
    asm volatile("ldmatrix.sync.aligned.m8n8.x4.trans.shared.b16 {%0,%1,%2,%3}, [%4];"
                 : "=r"(r[0]), "=r"(r[1]), "=r"(r[2]), "=r"(r[3]) : "r"(addr));
}
__device__ __forceinline__ void cpa16(void* s, const void* g) {
    asm volatile("cp.async.cg.shared.global [%0], [%1], 16;" :: "r"(su(s)), "l"(g));
}
__device__ __forceinline__ void cp_commit() { asm volatile("cp.async.commit_group;"); }
__device__ __forceinline__ void cp_wait0()  { asm volatile("cp.async.wait_group 0;"); }

// ---------------- scratch ----------------------------------------------------
__device__ __half g_xh[BB * NN * DD];    // LN out hi
__device__ __half g_xl[BB * NN * DD];    // LN out lo
__device__ __half g_qf[BB * NN * DD];    // q, pre-scaled fp16
__device__ float  g_k [BB * NK * DD];    // k (first NN rows only; tail in mem)
__device__ float  g_v [BB * NK * DD];
__device__ __half g_kf[BB * NK * DD];    // post-PEG K fp16
__device__ __half g_vf[BB * NK * DD];    // post-PEG V fp16
__device__ __half g_ah[BB * NN * DD];    // attention out hi
__device__ __half g_al[BB * NN * DD];    // attention out lo
__device__ __half g_wq[DD * 3 * DD];     // w_qkv fp16
__device__ __half g_wo[DD * DD];         // w_out fp16

// ---------------- fp32 -> fp16 rounder (weights) -----------------------------
__global__ void round_kernel(const float* __restrict__ src,
                             __half* __restrict__ dst, int n4) {
    int i = blockIdx.x * 256 + threadIdx.x;
    if (i >= n4) return;
    float4 v = ((const float4*)src)[i];
    ((uint2*)dst)[i] = make_uint2(rnd2(v.x, v.y), rnd2(v.z, v.w));
}

// ---------------- LayerNorm (writes hi/lo fp16) ------------------------------
__global__ void ln_kernel(const float* __restrict__ x,
                          const float* __restrict__ g,
                          const float* __restrict__ bt) {
    int row = blockIdx.x;
    int t = threadIdx.x;
    const float4* xr = (const float4*)(x + (size_t)row * DD);
    float4 v = xr[t];
    float s  = v.x + v.y + v.z + v.w;
    float s2 = v.x*v.x + v.y*v.y + v.z*v.z + v.w*v.w;
    #pragma unroll
    for (int o = 16; o > 0; o >>= 1) {
        s  += __shfl_xor_sync(0xffffffffu, s,  o);
        s2 += __shfl_xor_sync(0xffffffffu, s2, o);
    }
    __shared__ float a1[4], a2[4];
    int w = t >> 5;
    if ((t & 31) == 0) { a1[w] = s; a2[w] = s2; }
    __syncthreads();
    s  = a1[0] + a1[1] + a1[2] + a1[3];
    s2 = a2[0] + a2[1] + a2[2] + a2[3];
    float mu  = s * (1.0f / 512.0f);
    float var = s2 * (1.0f / 512.0f) - mu * mu;
    float rs  = rsqrtf(var + 1e-5f);
    float4 gg = ((const float4*)g)[t];
    float4 bb = ((const float4*)bt)[t];
    float4 o4;
    o4.x = (v.x - mu) * rs * gg.x + bb.x;
    o4.y = (v.y - mu) * rs * gg.y + bb.y;
    o4.z = (v.z - mu) * rs * gg.z + bb.z;
    o4.w = (v.w - mu) * rs * gg.w + bb.w;
    unsigned h0, l0, h1, l1;
    splitpk(o4.x, o4.y, h0, l0);
    splitpk(o4.z, o4.w, h1, l1);
    ((uint2*)(g_xh + (size_t)row * DD))[t] = make_uint2(h0, h1);
    ((uint2*)(g_xl + (size_t)row * DD))[t] = make_uint2(l0, l1);
}

// ---------------- fp16 2-term mma GEMM, 2-stage cp.async --------------------
// C = (Ah + Al) @ Wfp16 ; block 128x64, 8 warps, k-step 16.
#define ASTR 24
#define WSTR 72
__global__ __launch_bounds__(256)
void mma_gemm_kernel(const __half* __restrict__ Wh,
                     const float* __restrict__ bias,
                     float* __restrict__ dout, int cn, int mode) {
    const __half* Ah = mode ? g_ah : g_xh;
    const __half* Al = mode ? g_al : g_xl;
    __shared__ __align__(16) __half sAh[2][128 * ASTR];
    __shared__ __align__(16) __half sAl[2][128 * ASTR];
    __shared__ __align__(16) __half sWh[2][16 * WSTR];
    int tid = threadIdx.x, w = tid >> 5, lane = tid & 31;
    int gq = lane >> 2, qq = lane & 3;
    int lt = lane >> 3, lr = lane & 7;
    int row0 = blockIdx.y * 128, col0 = blockIdx.x * 64;
    int wm = w >> 1, wn = w & 1;
    float acc[2][4][4];
    #pragma unroll
    for (int mf = 0; mf < 2; mf++)
        #pragma unroll
        for (int nf = 0; nf < 4; nf++)
            #pragma unroll
            for (int c = 0; c < 4; c++) acc[mf][nf][c] = 0.f;

    auto load_tile = [&](int t, int s) {
        int kt = t * 16;
        {
            int r = tid >> 1, e = tid & 1;
            cpa16(&sAh[s][r * ASTR + 8 * e], Ah + (size_t)(row0 + r) * 512 + kt + 8 * e);
            cpa16(&sAl[s][r * ASTR + 8 * e], Al + (size_t)(row0 + r) * 512 + kt + 8 * e);
        }
        if (tid < 128) {
            int r = tid >> 3, e = tid & 7;
            cpa16(&sWh[s][r * WSTR + 8 * e], Wh + (size_t)(kt + r) * cn + col0 + 8 * e);
        }
        cp_commit();
    };

    load_tile(0, 0);
    for (int t = 0; t < 32; t++) {
        int s = t & 1;
        cp_wait0();
        __syncthreads();
        if (t + 1 < 32) load_tile(t + 1, s ^ 1);
        unsigned ah[2][4], al[2][4];
        #pragma unroll
        for (int mf = 0; mf < 2; mf++) {
            int ar = wm * 32 + mf * 16 + (lt & 1) * 8 + lr;
            int ak = (lt >> 1) * 8;
            ldsm4(ah[mf], su(&sAh[s][ar * ASTR + ak]));
            ldsm4(al[mf], su(&sAl[s][ar * ASTR + ak]));
        }
        unsigned bh[2][4];
        #pragma unroll
        for (int nh = 0; nh < 2; nh++) {
            int br = (lt & 1) * 8 + lr;
            int bc = wn * 32 + nh * 16 + (lt >> 1) * 8;
            ldsm4t(bh[nh], su(&sWh[s][br * WSTR + bc]));
        }
        #pragma unroll
        for (int nf = 0; nf < 4; nf++) {
            unsigned bh0 = bh[nf >> 1][(nf & 1) * 2];
            unsigned bh1 = bh[nf >> 1][(nf & 1) * 2 + 1];
            #pragma unroll
            for (int mf = 0; mf < 2; mf++) {
                mma16816(acc[mf][nf], ah[mf], bh0, bh1);
                mma16816(acc[mf][nf], al[mf], bh0, bh1);
            }
        }
    }
    #pragma unroll
    for (int mf = 0; mf < 2; mf++) {
        int rlo = row0 + wm * 32 + mf * 16 + gq;
        #pragma unroll
        for (int nf = 0; nf < 4; nf++) {
            int cl = col0 + wn * 32 + nf * 8 + 2 * qq;
            float* c = acc[mf][nf];
            if (mode == 0) {
                #pragma unroll
                for (int half_ = 0; half_ < 2; half_++) {
                    int rr = rlo + half_ * 8;
                    int b = rr >> 12, n = rr & 4095;
                    #pragma unroll
                    for (int j = 0; j < 2; j++) {
                        int cc = cl + j;
                        int sel = cc >> 9, c5 = cc & 511;
                        float vv = c[2 * half_ + j];
                        if (sel == 0)
                            g_qf[((size_t)b * NN + n) * 512 + c5] = __float2half_rn(vv * 0.125f);
                        else if (sel == 1) g_k[((size_t)b * NK + n) * 512 + c5] = vv;
                        else               g_v[((size_t)b * NK + n) * 512 + c5] = vv;
                    }
                }
            } else {
                float2 bq = *(const float2*)(bias + cl);
                float2 o0; o0.x = c[0] + bq.x; o0.y = c[1] + bq.y;
                float2 o1; o1.x = c[2] + bq.x; o1.y = c[3] + bq.y;
                *(float2*)(dout + (size_t)rlo * 512 + cl)       = o0;
                *(float2*)(dout + (size_t)(rlo + 8) * 512 + cl) = o1;
            }
        }
    }
}

// ---------------- PEG1D depthwise conv (k & v fused, mem tail inline) --------
__global__ void peg_kernel(const float* __restrict__ mem,
                           const float* __restrict__ wk, const float* __restrict__ bk,
                           const float* __restrict__ wv, const float* __restrict__ bv) {
    int which = blockIdx.y;
    const float* w    = which ? wv : wk;
    const float* bias = which ? bv : bk;
    const float* src  = which ? g_v : g_k;
    __half* df        = which ? g_vf : g_kf;
    int gr = blockIdx.x;
    int b = gr / NK, r = gr - b * NK;
    int c = threadIdx.x << 2;
    const float* base = src + (size_t)b * NK * 512;
    const float* memb = mem + (size_t)b * MM * 512;
    auto rowp = [&](int row) -> const float* {
        return (row < NN) ? (base + (size_t)row * 512) : (memb + (size_t)(row - NN) * 512);
    };
    float4 xc = *(const float4*)(rowp(r) + c);
    size_t doff = ((size_t)b * NK + r) * 512 + c;
    float4 o4;
    if (r == 0) {
        o4 = xc;
    } else {
        int t = r - 1;
        float w0[4], w1[4], w2[4];
        #pragma unroll
        for (int j = 0; j < 4; j++) {
            w0[j] = __ldg(w + (c + j) * 3 + 0);
            w1[j] = __ldg(w + (c + j) * 3 + 1);
            w2[j] = __ldg(w + (c + j) * 3 + 2);
        }
        float4 bb = *(const float4*)(bias + c);
        const float4 z4 = make_float4(0.f, 0.f, 0.f, 0.f);
        int p = t & 31;
        float4 L1 = (p > 0)                 ? *(const float4*)(rowp(r - 1) + c) : z4;
        float4 R1 = (p < 31 && t + 1 < LSEQ)? *(const float4*)(rowp(r + 1) + c) : z4;
        int u   = (t + 16) % LSEQ;
        int p2p = u % 32;
        int jl  = (u + LSEQ - 17) % LSEQ;
        int jr  = (u + LSEQ - 15) % LSEQ;
        float4 L2 = (p2p > 0)                  ? *(const float4*)(rowp(1 + jl) + c) : z4;
        float4 R2 = (p2p < 31 && u + 1 < LSEQ) ? *(const float4*)(rowp(1 + jr) + c) : z4;
        o4.x = xc.x + (w0[0]*L1.x + w1[0]*xc.x + w2[0]*R1.x + bb.x)
                    + (w0[0]*L2.x + w1[0]*xc.x + w2[0]*R2.x + bb.x);
        o4.y = xc.y + (w0[1]*L1.y + w1[1]*xc.y + w2[1]*R1.y + bb.y)
                    + (w0[1]*L2.y + w1[1]*xc.y + w2[1]*R2.y + bb.y);
        o4.z = xc.z + (w0[2]*L1.z + w1[2]*xc.z + w2[2]*R1.z + bb.z)
                    + (w0[2]*L2.z + w1[2]*xc.z + w2[2]*R2.z + bb.z);
        o4.w = xc.w + (w0[3]*L1.w + w1[3]*xc.w + w2[3]*R1.w + bb.w)
                    + (w0[3]*L2.w + w1[3]*xc.w + w2[3]*R2.w + bb.w);
    }
    *(uint2*)(df + doff) = make_uint2(rnd2(o4.x, o4.y), rnd2(o4.z, o4.w));
}

// ---------------- flash attention, fp16 1-term mma + cp.async ---------------
#define KSTR 72
__global__ __launch_bounds__(256)
void attn_mma_kernel() {
    __shared__ __align__(16) __half Ks[2][64 * KSTR];
    __shared__ __align__(16) __half Vs[2][64 * KSTR];
    int tid = threadIdx.x;
    int w = tid >> 5, lane = tid & 31;
    int gq = lane >> 2, qq = lane & 3;
    int lt = lane >> 3, lr = lane & 7;
    int bh_ = blockIdx.y;
    int b = bh_ >> 3, h = bh_ & 7;
    int q0 = blockIdx.x * 128 + w * 16;

    const __half* kfb = g_kf + ((size_t)b * NK) * 512 + h * 64;
    const __half* vfb = g_vf + ((size_t)b * NK) * 512 + h * 64;

    auto load_tile = [&](int kt, int s) {
        #pragma unroll
        for (int i = 0; i < 2; i++) {
            int idx = tid + 256 * i;
            int row = idx >> 3, e = idx & 7;
            size_t goff = (size_t)(kt + row) * 512 + 8 * e;
            int soff = row * KSTR + 8 * e;
            cpa16(&Ks[s][soff], kfb + goff);
            cpa16(&Vs[s][soff], vfb + goff);
        }
        cp_commit();
    };

    unsigned qh[4][4];
    {
        const __half* qbase = g_qf + ((size_t)b * NN + q0) * 512 + h * 64;
        #pragma unroll
        for (int kk = 0; kk < 4; kk++)
            #pragma unroll
            for (int cc = 0; cc < 2; cc++)
                #pragma unroll
                for (int rr = 0; rr < 2; rr++) {
                    int row = gq + rr * 8;
                    int dim = kk * 16 + cc * 8 + qq * 2;
                    qh[kk][rr + 2 * cc] = *(const unsigned*)(qbase + (size_t)row * 512 + dim);
                }
    }

    float O[8][4];
    #pragma unroll
    for (int j = 0; j < 8; j++)
        #pragma unroll
        for (int c = 0; c < 4; c++) O[j][c] = 0.f;
    float rm0 = -1e30f, rm1 = -1e30f, rl0 = 0.f, rl1 = 0.f;

    load_tile(0, 0);
    const int NT = NK / 64;
    for (int t = 0; t < NT; t++) {
        int s = t & 1;
        cp_wait0();
        __syncthreads();
        if (t + 1 < NT) load_tile((t + 1) * 64, s ^ 1);

        float S[8][4];
        #pragma unroll
        for (int j = 0; j < 8; j++) {
            unsigned bf[8];
            int krow = (8 * j + lr) * KSTR;
            ldsm4(bf,     su(&Ks[s][krow + 8 * lt]));
            ldsm4(bf + 4, su(&Ks[s][krow + 32 + 8 * lt]));
            float c[4] = {0.f, 0.f, 0.f, 0.f};
            #pragma unroll
            for (int kk = 0; kk < 4; kk++)
                mma16816(c, qh[kk], bf[2 * kk], bf[2 * kk + 1]);
            S[j][0] = c[0]; S[j][1] = c[1]; S[j][2] = c[2]; S[j][3] = c[3];
        }

        float tm0 = -1e30f, tm1 = -1e30f;
        #pragma unroll
        for (int j = 0; j < 8; j++) {
            tm0 = fmaxf(tm0, fmaxf(S[j][0], S[j][1]));
            tm1 = fmaxf(tm1, fmaxf(S[j][2], S[j][3]));
        }
        tm0 = fmaxf(tm0, __shfl_xor_sync(0xffffffffu, tm0, 1));
        tm0 = fmaxf(tm0, __shfl_xor_sync(0xffffffffu, tm0, 2));
        tm1 = fmaxf(tm1, __shfl_xor_sync(0xffffffffu, tm1, 1));
        tm1 = fmaxf(tm1, __shfl_xor_sync(0xffffffffu, tm1, 2));
        float m0n = fmaxf(rm0, tm0), m1n = fmaxf(rm1, tm1);
        float cor0 = __expf(rm0 - m0n), cor1 = __expf(rm1 - m1n);
        rl0 *= cor0; rl1 *= cor1;
        #pragma unroll
        for (int j = 0; j < 8; j++) {
            O[j][0] *= cor0; O[j][1] *= cor0;
            O[j][2] *= cor1; O[j][3] *= cor1;
        }
        rm0 = m0n; rm1 = m1n;

        unsigned Ph[4][4];
        #pragma unroll
        for (int j = 0; j < 8; j++) {
            float p0 = __expf(S[j][0] - m0n);
            float p1 = __expf(S[j][1] - m0n);
            float p2 = __expf(S[j][2] - m1n);
            float p3 = __expf(S[j][3] - m1n);
            rl0 += p0 + p1; rl1 += p2 + p3;
            int kk2 = j >> 1, half_ = j & 1;
            Ph[kk2][2 * half_]     = rnd2(p0, p1);
            Ph[kk2][2 * half_ + 1] = rnd2(p2, p3);
        }

        #pragma unroll
        for (int jd = 0; jd < 8; jd++) {
            unsigned vf[8];
            ldsm4t(vf,     su(&Vs[s][(8 * lt + lr) * KSTR + 8 * jd]));
            ldsm4t(vf + 4, su(&Vs[s][(32 + 8 * lt + lr) * KSTR + 8 * jd]));
            #pragma unroll
            for (int kk2 = 0; kk2 < 4; kk2++)
                mma16816(O[jd], Ph[kk2], vf[2 * kk2], vf[2 * kk2 + 1]);
        }
    }

    float l0 = rl0, l1 = rl1;
    l0 += __shfl_xor_sync(0xffffffffu, l0, 1);
    l0 += __shfl_xor_sync(0xffffffffu, l0, 2);
    l1 += __shfl_xor_sync(0xffffffffu, l1, 1);
    l1 += __shfl_xor_sync(0xffffffffu, l1, 2);
    float inv0 = 1.0f / l0, inv1 = 1.0f / l1;
    size_t obase = ((size_t)b * NN + q0) * 512 + h * 64;
    #pragma unroll
    for (int jd = 0; jd < 8; jd++) {
        int dim = 8 * jd + qq * 2;
        unsigned h2, l2;
        splitpk(O[jd][0] * inv0, O[jd][1] * inv0, h2, l2);
        *(unsigned*)&g_ah[obase + (size_t)gq * 512 + dim] = h2;
        *(unsigned*)&g_al[obase + (size_t)gq * 512 + dim] = l2;
        splitpk(O[jd][2] * inv1, O[jd][3] * inv1, h2, l2);
        *(unsigned*)&g_ah[obase + (size_t)(gq + 8) * 512 + dim] = h2;
        *(unsigned*)&g_al[obase + (size_t)(gq + 8) * 512 + dim] = l2;
    }
}

// ---------------- launch ----------------------------------------------------
extern "C" void kernel_launch(void* const* d_in, const int* in_sizes, int n_in,
                              void* d_out, int out_size) {
    const float* x     = (const float*)d_in[0];
    const float* mem   = (const float*)d_in[1];
    const float* ln_g  = (const float*)d_in[2];
    const float* ln_b  = (const float*)d_in[3];
    const float* w_qkv = (const float*)d_in[4];
    const float* w_out = (const float*)d_in[5];
    const float* b_out = (const float*)d_in[6];
    const float* pk_w  = (const float*)d_in[7];
    const float* pk_b  = (const float*)d_in[8];
    const float* pv_w  = (const float*)d_in[9];
    const float* pv_b  = (const float*)d_in[10];
    float* out = (float*)d_out;

    __half *wq, *wo;
    cudaGetSymbolAddress((void**)&wq, g_wq);
    cudaGetSymbolAddress((void**)&wo, g_wo);

    round_kernel<<<(DD * 3 * DD / 4 + 255) / 256, 256>>>(w_qkv, wq, DD * 3 * DD / 4);
    round_kernel<<<(DD * DD / 4 + 255) / 256, 256>>>(w_out, wo, DD * DD / 4);
    ln_kernel<<<BB * NN, 128>>>(x, ln_g, ln_b);
    mma_gemm_kernel<<<dim3(1536 / 64, (BB * NN) / 128), 256>>>(wq, nullptr, nullptr, 1536, 0);
    peg_kernel<<<dim3(BB * NK, 2), 128>>>(mem, pk_w, pk_b, pv_w, pv_b);
    attn_mma_kernel<<<dim3(NN / 128, BB * HH), 256>>>();
    mma_gemm_kernel<<<dim3(512 / 64, (BB * NN) / 128), 256>>>(wo, b_out, out, 512, 1);
}